// round 1
// baseline (speedup 1.0000x reference)
#include <cuda_runtime.h>
#include <cstdint>
#include <math.h>

// ---------------- problem constants ----------------
#define BB 32
#define NN 4096
#define DF 768
#define DS 256
#define KSLOT 8
#define NROWS (BB*NN)        // 131072
#define SCALE_F 0.0625f      // 256^-0.5
#define EPS_ATTN 1e-8f

// ---------------- scratch (device globals; no allocations allowed) ----------------
static __device__ float g_mean[NROWS];
static __device__ float g_rstd[NROWS];
static __device__ float g_k[(size_t)NROWS*DS];     // 134 MB
static __device__ float g_v[(size_t)NROWS*DS];     // 134 MB
static __device__ float g_Wc[512*DF];              // [Wk';Wv'] with g_in folded in
static __device__ float g_csum[512];
static __device__ float g_cbias[512];
static __device__ float g_WqT[DS*DS];
static __device__ float g_WihT[DS*768];
static __device__ float g_WhhT[DS*768];
static __device__ float g_W1T[DS*DS];
static __device__ float g_W2T[DS*DS];
static __device__ float g_q[BB*KSLOT*DS];
static __device__ float g_slots[BB*KSLOT*DS];
static __device__ float g_U[BB*KSLOT*DS];
static __device__ float g_S[BB*KSLOT];
static __device__ float g_gi[BB*KSLOT*768];
static __device__ float g_gh[BB*KSLOT*768];

// ---------------- prep: combined, g-scaled projection weights ----------------
__global__ void __launch_bounds__(256) prep_wc(const float* __restrict__ Wk,
                                               const float* __restrict__ Wv,
                                               const float* __restrict__ gin,
                                               const float* __restrict__ bin) {
    int j = blockIdx.x;             // 0..511  (0..255 -> k, 256..511 -> v)
    const float* W = (j < 256) ? (Wk + (size_t)j*DF) : (Wv + (size_t)(j-256)*DF);
    int t = threadIdx.x;
    float s = 0.f, bsum = 0.f;
    for (int f = t; f < DF; f += 256) {
        float w  = W[f];
        float wc = w * gin[f];
        g_Wc[(size_t)j*DF + f] = wc;
        s += wc; bsum += w * bin[f];
    }
    __shared__ float r1[8], r2[8];
    for (int o = 16; o; o >>= 1) { s += __shfl_down_sync(0xffffffffu, s, o); bsum += __shfl_down_sync(0xffffffffu, bsum, o); }
    if ((t & 31) == 0) { r1[t>>5] = s; r2[t>>5] = bsum; }
    __syncthreads();
    if (t == 0) {
        float ts = 0.f, tb = 0.f;
        #pragma unroll
        for (int w = 0; w < 8; w++) { ts += r1[w]; tb += r2[w]; }
        g_csum[j] = ts; g_cbias[j] = tb;
    }
}

// ---------------- prep: transposed small weights + copy slots ----------------
__global__ void prep_transpose(const float* __restrict__ Wq,
                               const float* __restrict__ Wih,
                               const float* __restrict__ Whh,
                               const float* __restrict__ W1,
                               const float* __restrict__ W2,
                               const float* __restrict__ prev) {
    int i = blockIdx.x * blockDim.x + threadIdx.x;
    if (i < 768*256) {
        int g = i / 256, d = i % 256;
        g_WihT[d*768 + g] = Wih[i];
        g_WhhT[d*768 + g] = Whh[i];
    }
    if (i < 256*256) {
        int r = i / 256, c = i % 256;
        g_WqT[c*256 + r] = Wq[i];     // Wq[h][d] -> WqT[d][h]
        g_W1T[c*256 + r] = W1[i];     // W1[m][d] -> W1T[d][m]
        g_W2T[c*256 + r] = W2[i];     // W2[d][m] -> W2T[m][d]
    }
    if (i < BB*KSLOT*DS) g_slots[i] = prev[i];
}

// ---------------- per-row LN stats of features ----------------
__global__ void __launch_bounds__(256) row_stats(const float* __restrict__ F) {
    int row = blockIdx.x;
    const float* x = F + (size_t)row * DF;
    int t = threadIdx.x;
    float a0 = x[t], a1 = x[t+256], a2 = x[t+512];
    float s  = a0 + a1 + a2;
    float s2 = a0*a0 + a1*a1 + a2*a2;
    __shared__ float r1[8], r2[8];
    for (int o = 16; o; o >>= 1) { s += __shfl_down_sync(0xffffffffu, s, o); s2 += __shfl_down_sync(0xffffffffu, s2, o); }
    if ((t & 31) == 0) { r1[t>>5] = s; r2[t>>5] = s2; }
    __syncthreads();
    if (t == 0) {
        float ts = 0.f, ts2 = 0.f;
        #pragma unroll
        for (int w = 0; w < 8; w++) { ts += r1[w]; ts2 += r2[w]; }
        float m   = ts * (1.f/768.f);
        float var = ts2 * (1.f/768.f) - m*m;
        g_mean[row] = m;
        g_rstd[row] = rsqrtf(var + 1e-5f);
    }
}

// ---------------- big GEMM: C[131072 x 512] = F[131072 x 768] * Wc^T ----------------
#define GBM 128
#define GBN 128
#define GBK 16
#define SPAD 132

__device__ __forceinline__ void mm_compute(const float (*As)[SPAD], const float (*Bs)[SPAD],
                                           float acc[8][8], int ty, int tx) {
    #pragma unroll
    for (int k = 0; k < GBK; k++) {
        float ar[8], br[8];
        *(float4*)(ar)   = *(const float4*)&As[k][ty*8];
        *(float4*)(ar+4) = *(const float4*)&As[k][ty*8+4];
        *(float4*)(br)   = *(const float4*)&Bs[k][tx*8];
        *(float4*)(br+4) = *(const float4*)&Bs[k][tx*8+4];
        #pragma unroll
        for (int i = 0; i < 8; i++)
            #pragma unroll
            for (int j = 0; j < 8; j++)
                acc[i][j] += ar[i] * br[j];
    }
}

__global__ void __launch_bounds__(256, 2) gemm_kv(const float* __restrict__ F) {
    __shared__ float As[2][GBK][SPAD];
    __shared__ float Bs[2][GBK][SPAD];
    const int tid = threadIdx.x;
    const int bn = blockIdx.x * GBN;   // x over cols (4) so same-row blocks are L2-adjacent
    const int bm = blockIdx.y * GBM;   // y over rows (1024)
    const int tx = tid & 15, ty = tid >> 4;
    const int lr = tid >> 2;           // 0..63
    const int lk = (tid & 3) * 4;      // 0,4,8,12

    const float* Abase = F    + (size_t)(bm + lr) * DF + lk;
    const float* Bbase = g_Wc + (size_t)(bn + lr) * DF + lk;

    // preload tile 0
    {
        float4 a0 = *(const float4*)(Abase);
        float4 a1 = *(const float4*)(Abase + (size_t)64*DF);
        float4 c0 = *(const float4*)(Bbase);
        float4 c1 = *(const float4*)(Bbase + (size_t)64*DF);
        As[0][lk+0][lr]=a0.x; As[0][lk+1][lr]=a0.y; As[0][lk+2][lr]=a0.z; As[0][lk+3][lr]=a0.w;
        As[0][lk+0][lr+64]=a1.x; As[0][lk+1][lr+64]=a1.y; As[0][lk+2][lr+64]=a1.z; As[0][lk+3][lr+64]=a1.w;
        Bs[0][lk+0][lr]=c0.x; Bs[0][lk+1][lr]=c0.y; Bs[0][lk+2][lr]=c0.z; Bs[0][lk+3][lr]=c0.w;
        Bs[0][lk+0][lr+64]=c1.x; Bs[0][lk+1][lr+64]=c1.y; Bs[0][lk+2][lr+64]=c1.z; Bs[0][lk+3][lr+64]=c1.w;
    }
    __syncthreads();

    float acc[8][8];
    #pragma unroll
    for (int i = 0; i < 8; i++)
        #pragma unroll
        for (int j = 0; j < 8; j++) acc[i][j] = 0.f;

    int buf = 0;
    #pragma unroll 1
    for (int s = 0; s < (DF/GBK) - 1; s++) {
        const float* Ap = Abase + (s+1)*GBK;
        const float* Bp = Bbase + (s+1)*GBK;
        float4 a0 = *(const float4*)(Ap);
        float4 a1 = *(const float4*)(Ap + (size_t)64*DF);
        float4 c0 = *(const float4*)(Bp);
        float4 c1 = *(const float4*)(Bp + (size_t)64*DF);

        mm_compute(As[buf], Bs[buf], acc, ty, tx);

        int nb = buf ^ 1;
        As[nb][lk+0][lr]=a0.x; As[nb][lk+1][lr]=a0.y; As[nb][lk+2][lr]=a0.z; As[nb][lk+3][lr]=a0.w;
        As[nb][lk+0][lr+64]=a1.x; As[nb][lk+1][lr+64]=a1.y; As[nb][lk+2][lr+64]=a1.z; As[nb][lk+3][lr+64]=a1.w;
        Bs[nb][lk+0][lr]=c0.x; Bs[nb][lk+1][lr]=c0.y; Bs[nb][lk+2][lr]=c0.z; Bs[nb][lk+3][lr]=c0.w;
        Bs[nb][lk+0][lr+64]=c1.x; Bs[nb][lk+1][lr+64]=c1.y; Bs[nb][lk+2][lr+64]=c1.z; Bs[nb][lk+3][lr+64]=c1.w;
        __syncthreads();
        buf = nb;
    }
    mm_compute(As[buf], Bs[buf], acc, ty, tx);

    // epilogue: LN fold + split to k/v
    float rm[8], rs[8];
    #pragma unroll
    for (int i = 0; i < 8; i++) {
        int row = bm + ty*8 + i;
        rm[i] = g_mean[row]; rs[i] = g_rstd[row];
    }
    float cs[8], cb[8];
    #pragma unroll
    for (int j = 0; j < 8; j++) {
        int col = bn + tx*8 + j;
        cs[j] = g_csum[col]; cb[j] = g_cbias[col];
    }
    #pragma unroll
    for (int i = 0; i < 8; i++) {
        int row = bm + ty*8 + i;
        #pragma unroll
        for (int j = 0; j < 8; j++) {
            int col = bn + tx*8 + j;
            float outv = rs[i] * (acc[i][j] - rm[i]*cs[j]) + cb[j];
            if (col < 256) g_k[(size_t)row*DS + col]         = outv;
            else           g_v[(size_t)row*DS + (col - 256)] = outv;
        }
    }
}

// ---------------- per-slot q = LN(slots) @ Wq^T ----------------
__global__ void __launch_bounds__(256) slot_q(const float* __restrict__ gs, const float* __restrict__ bs) {
    int row = blockIdx.x;          // b*8+k
    int t = threadIdx.x;
    __shared__ float sn[256];
    __shared__ float r1[8], r2[8];
    __shared__ float smv[2];
    float x = g_slots[row*256 + t];
    float s = x, s2 = x*x;
    for (int o = 16; o; o >>= 1) { s += __shfl_down_sync(0xffffffffu, s, o); s2 += __shfl_down_sync(0xffffffffu, s2, o); }
    if ((t & 31) == 0) { r1[t>>5] = s; r2[t>>5] = s2; }
    __syncthreads();
    if (t == 0) {
        float ts = 0.f, ts2 = 0.f;
        #pragma unroll
        for (int w = 0; w < 8; w++) { ts += r1[w]; ts2 += r2[w]; }
        float m = ts * (1.f/256.f);
        float var = ts2 * (1.f/256.f) - m*m;
        smv[0] = m; smv[1] = rsqrtf(var + 1e-5f);
    }
    __syncthreads();
    sn[t] = (x - smv[0]) * smv[1] * gs[t] + bs[t];
    __syncthreads();
    float acc = 0.f;
    #pragma unroll 4
    for (int d = 0; d < 256; d++) acc += sn[d] * g_WqT[d*256 + t];
    g_q[row*256 + t] = acc;
}

// ---------------- zero U/S accumulators ----------------
__global__ void zero_US() {
    int i = blockIdx.x * blockDim.x + threadIdx.x;
    if (i < BB*KSLOT*DS) g_U[i] = 0.f;
    if (i < BB*KSLOT)    g_S[i] = 0.f;
}

// ---------------- fused attention sweep: logits -> softmax(8) -> [U accum | attn out] ----------------
#define ATILE 32
#define KPAD 260
#define CHUNKS 16
#define ATTN_SMEM_FLOATS (8*256 + 2*ATILE*KPAD + 2*8*36)

template <bool FINAL>
__global__ void __launch_bounds__(256) attn_pass(float* __restrict__ out_attn) {
    extern __shared__ float sm[];
    float* qs = sm;                        // 8*256, pre-scaled q
    float* kt = qs + 8*256;                // ATILE*KPAD
    float* vt = kt + ATILE*KPAD;           // ATILE*KPAD
    float* Ls = vt + ATILE*KPAD;           // 8*36
    float* ps = Ls + 8*36;                 // 8*36

    int b  = blockIdx.x;
    int ch = blockIdx.y;
    int t  = threadIdx.x;

    for (int i = t; i < 8*256; i += 256) qs[i] = g_q[b*2048 + i] * SCALE_F;

    const int n0 = ch * (NN / CHUNKS);     // 256 positions per chunk
    float regU[8], regS[8];
    #pragma unroll
    for (int h = 0; h < 8; h++) { regU[h] = 0.f; regS[h] = 0.f; }

    const int hq = t >> 5;  // slot index (warp id)
    const int nl = t & 31;  // local n

    #pragma unroll 1
    for (int tile = 0; tile < (NN/CHUNKS)/ATILE; tile++) {
        int nbase = n0 + tile * ATILE;
        __syncthreads();
        // cooperative tile load (float4, conflict-free pad 260)
        const float* kg = g_k + ((size_t)b*NN + nbase) * DS;
        const float* vg = g_v + ((size_t)b*NN + nbase) * DS;
        for (int i = t; i < ATILE*64; i += 256) {
            int n = i >> 6; int d4 = (i & 63) << 2;
            *(float4*)(kt + n*KPAD + d4) = *(const float4*)(kg + n*DS + d4);
            if (!FINAL)
                *(float4*)(vt + n*KPAD + d4) = *(const float4*)(vg + n*DS + d4);
        }
        __syncthreads();

        // logits: thread (slot=hq, n=nl)
        {
            float acc = 0.f;
            const float* qrow = qs + hq*256;
            const float* krow = kt + nl*KPAD;
            #pragma unroll 8
            for (int d = 0; d < 256; d += 4) {
                float4 qv = *(const float4*)(qrow + d);
                float4 kv = *(const float4*)(krow + d);
                acc += qv.x*kv.x + qv.y*kv.y + qv.z*kv.z + qv.w*kv.w;
            }
            Ls[hq*36 + nl] = acc;
        }
        __syncthreads();

        // softmax over 8 slots per n (threads 0..31)
        if (t < 32) {
            float l[8], m = -1e30f;
            #pragma unroll
            for (int h = 0; h < 8; h++) { l[h] = Ls[h*36 + t]; m = fmaxf(m, l[h]); }
            float ssum = 0.f;
            #pragma unroll
            for (int h = 0; h < 8; h++) { l[h] = expf(l[h] - m); ssum += l[h]; }
            float inv = 1.f / ssum;
            #pragma unroll
            for (int h = 0; h < 8; h++) {
                float p = l[h] * inv;
                ps[h*36 + t] = p;
                regS[h] += p;
                if (FINAL)
                    out_attn[((size_t)b*KSLOT + h)*NN + nbase + t] = p;
            }
        }
        __syncthreads();

        if (!FINAL) {
            // U[slot][d=t] += p[slot][n] * v[n][t]
            #pragma unroll 4
            for (int n = 0; n < ATILE; n++) {
                float vv = vt[n*KPAD + t];
                #pragma unroll
                for (int h = 0; h < 8; h++) regU[h] += ps[h*36 + n] * vv;
            }
        }
    }

    if (!FINAL) {
        #pragma unroll
        for (int h = 0; h < 8; h++)
            atomicAdd(&g_U[((size_t)b*KSLOT + h)*DS + t], regU[h]);
    }
    if (t < 32) {
        #pragma unroll
        for (int h = 0; h < 8; h++) {
            float v = regS[h];
            for (int o = 16; o; o >>= 1) v += __shfl_down_sync(0xffffffffu, v, o);
            if (t == 0) atomicAdd(&g_S[b*KSLOT + h], v);
        }
    }
}

// ---------------- GRU gate GEMMs: gi = upd@Wih^T + b_ih, gh = slots@Whh^T + b_hh ----------------
__global__ void __launch_bounds__(256) gru_gemm(const float* __restrict__ bih, const float* __restrict__ bhh) {
    int blk = blockIdx.x;
    int b = blk / 24, gc = blk % 24;      // 24 chunks of 32 gate outputs
    __shared__ float su[8*256], ss[8*256];
    int t = threadIdx.x;
    for (int i = t; i < 2048; i += 256) {
        int k = i >> 8;
        su[i] = g_U[b*2048 + i] / (g_S[b*8 + k] + EPS_ATTN);
        ss[i] = g_slots[b*2048 + i];
    }
    __syncthreads();
    int g = gc*32 + (t & 31);
    int k = t >> 5;
    float gi = bih[g], gh = bhh[g];
    const float* su_k = su + k*256;
    const float* ss_k = ss + k*256;
    #pragma unroll 4
    for (int d = 0; d < 256; d++) {
        gi += su_k[d] * g_WihT[d*768 + g];
        gh += ss_k[d] * g_WhhT[d*768 + g];
    }
    g_gi[((size_t)b*8 + k)*768 + g] = gi;
    g_gh[((size_t)b*8 + k)*768 + g] = gh;
}

// ---------------- GRU combine + LN + MLP, in-place slot update ----------------
__global__ void __launch_bounds__(256) gru_mlp(const float* __restrict__ gm, const float* __restrict__ bm,
                                               const float* __restrict__ b1, const float* __restrict__ b2) {
    int bk = blockIdx.x;
    int t = threadIdx.x;
    const float* gi = g_gi + (size_t)bk*768;
    const float* gh = g_gh + (size_t)bk*768;
    float sl = g_slots[bk*256 + t];
    float r  = 1.f / (1.f + expf(-(gi[t]       + gh[t])));
    float z  = 1.f / (1.f + expf(-(gi[256 + t] + gh[256 + t])));
    float nn = tanhf(gi[512 + t] + r * gh[512 + t]);
    float h  = (1.f - z) * nn + z * sl;

    __shared__ float hn[256], ms[256];
    __shared__ float r1[8], r2[8];
    __shared__ float smv[2];
    float s = h, s2 = h*h;
    for (int o = 16; o; o >>= 1) { s += __shfl_down_sync(0xffffffffu, s, o); s2 += __shfl_down_sync(0xffffffffu, s2, o); }
    if ((t & 31) == 0) { r1[t>>5] = s; r2[t>>5] = s2; }
    __syncthreads();
    if (t == 0) {
        float ts = 0.f, ts2 = 0.f;
        #pragma unroll
        for (int w = 0; w < 8; w++) { ts += r1[w]; ts2 += r2[w]; }
        float m = ts * (1.f/256.f);
        float var = ts2 * (1.f/256.f) - m*m;
        smv[0] = m; smv[1] = rsqrtf(var + 1e-5f);
    }
    __syncthreads();
    hn[t] = (h - smv[0]) * smv[1] * gm[t] + bm[t];
    __syncthreads();
    float acc = b1[t];
    #pragma unroll 4
    for (int d = 0; d < 256; d++) acc += hn[d] * g_W1T[d*256 + t];
    ms[t] = fmaxf(acc, 0.f);
    __syncthreads();
    float o = h + b2[t];
    #pragma unroll 4
    for (int j = 0; j < 256; j++) o += ms[j] * g_W2T[j*256 + t];
    g_slots[bk*256 + t] = o;
}

// ---------------- final confidence blend ----------------
__global__ void __launch_bounds__(256) finalize(const float* __restrict__ prev, float* __restrict__ out_slots) {
    int bk = blockIdx.x;
    int t = threadIdx.x;
    float mean = g_S[bk] * (1.f / 4096.f);
    float mask = 1.f / (1.f + expf(-mean));
    out_slots[bk*256 + t] = g_slots[bk*256 + t] * mask + prev[bk*256 + t] * (1.f - mask);
}

// ---------------- launch ----------------
extern "C" void kernel_launch(void* const* d_in, const int* in_sizes, int n_in,
                              void* d_out, int out_size) {
    const float* features = (const float*)d_in[0];
    const float* prev     = (const float*)d_in[1];
    const float* gin      = (const float*)d_in[2];
    const float* bin      = (const float*)d_in[3];
    const float* gs       = (const float*)d_in[4];
    const float* bs       = (const float*)d_in[5];
    const float* gm       = (const float*)d_in[6];
    const float* bm       = (const float*)d_in[7];
    const float* Wq       = (const float*)d_in[8];
    const float* Wk       = (const float*)d_in[9];
    const float* Wv       = (const float*)d_in[10];
    const float* Wih      = (const float*)d_in[11];
    const float* Whh      = (const float*)d_in[12];
    const float* bih      = (const float*)d_in[13];
    const float* bhh      = (const float*)d_in[14];
    const float* W1       = (const float*)d_in[15];
    const float* b1       = (const float*)d_in[16];
    const float* W2       = (const float*)d_in[17];
    const float* b2       = (const float*)d_in[18];

    float* out_slots = (float*)d_out;
    float* out_attn  = out_slots + BB*KSLOT*DS;

    const size_t attn_smem = (size_t)ATTN_SMEM_FLOATS * sizeof(float); // ~77 KB
    cudaFuncSetAttribute((const void*)attn_pass<false>, cudaFuncAttributeMaxDynamicSharedMemorySize, (int)attn_smem);
    cudaFuncSetAttribute((const void*)attn_pass<true>,  cudaFuncAttributeMaxDynamicSharedMemorySize, (int)attn_smem);

    // prep
    prep_wc<<<512, 256>>>(Wk, Wv, gin, bin);
    prep_transpose<<<(768*256 + 255)/256, 256>>>(Wq, Wih, Whh, W1, W2, prev);

    // phase A: LN stats + big projection GEMM
    row_stats<<<NROWS, 256>>>(features);
    gemm_kv<<<dim3(512/GBN, NROWS/GBM), 256>>>(features);

    // phase B: 3 slot-attention iterations
    for (int it = 0; it < 3; it++) {
        zero_US<<<(BB*KSLOT*DS + 255)/256, 256>>>();
        slot_q<<<BB*KSLOT, 256>>>(gs, bs);
        attn_pass<false><<<dim3(BB, CHUNKS), 256, attn_smem>>>(nullptr);
        gru_gemm<<<BB*24, 256>>>(bih, bhh);
        gru_mlp<<<BB*KSLOT, 256>>>(gm, bm, b1, b2);
    }

    // final attention + blend
    zero_US<<<(BB*KSLOT*DS + 255)/256, 256>>>();
    slot_q<<<BB*KSLOT, 256>>>(gs, bs);
    attn_pass<true><<<dim3(BB, CHUNKS), 256, attn_smem>>>(out_attn);
    finalize<<<BB*KSLOT, 256>>>(prev, out_slots);

    (void)in_sizes; (void)n_in; (void)out_size;
}

// round 3
// speedup vs baseline: 1.4089x; 1.4089x over previous
#include <cuda_runtime.h>
#include <cuda_bf16.h>
#include <cstdint>
#include <math.h>

// ---------------- problem constants ----------------
#define BB 32
#define NN 4096
#define DF 768
#define DS 256
#define KSLOT 8
#define NROWS (BB*NN)        // 131072
#define SCALE_F 0.0625f      // 256^-0.5
#define EPS_ATTN 1e-8f

// ---------------- scratch (device globals; no allocations allowed) ----------------
static __device__ float g_mean[NROWS];
static __device__ float g_rstd[NROWS];
static __device__ float g_k[(size_t)NROWS*DS];     // 134 MB
static __device__ float g_v[(size_t)NROWS*DS];     // 134 MB
static __device__ float g_Wc[512*DF];              // [Wk';Wv'] with g_in folded in
static __device__ __align__(16) __nv_bfloat16 g_WcHi[512*DF];
static __device__ __align__(16) __nv_bfloat16 g_WcLo[512*DF];
static __device__ float g_csum[512];
static __device__ float g_cbias[512];
static __device__ float g_WqT[DS*DS];
static __device__ float g_WihT[DS*768];
static __device__ float g_WhhT[DS*768];
static __device__ float g_W1T[DS*DS];
static __device__ float g_W2T[DS*DS];
static __device__ float g_q[BB*KSLOT*DS];
static __device__ float g_slots[BB*KSLOT*DS];
static __device__ float g_U[BB*KSLOT*DS];
static __device__ float g_S[BB*KSLOT];
static __device__ float g_gi[BB*KSLOT*768];
static __device__ float g_gh[BB*KSLOT*768];

// ---------------- prep: combined, g-scaled projection weights ----------------
__global__ void __launch_bounds__(256) prep_wc(const float* __restrict__ Wk,
                                               const float* __restrict__ Wv,
                                               const float* __restrict__ gin,
                                               const float* __restrict__ bin) {
    int j = blockIdx.x;             // 0..511  (0..255 -> k, 256..511 -> v)
    const float* W = (j < 256) ? (Wk + (size_t)j*DF) : (Wv + (size_t)(j-256)*DF);
    int t = threadIdx.x;
    float s = 0.f, bsum = 0.f;
    for (int f = t; f < DF; f += 256) {
        float w  = W[f];
        float wc = w * gin[f];
        g_Wc[(size_t)j*DF + f] = wc;
        s += wc; bsum += w * bin[f];
    }
    __shared__ float r1[8], r2[8];
    for (int o = 16; o; o >>= 1) { s += __shfl_down_sync(0xffffffffu, s, o); bsum += __shfl_down_sync(0xffffffffu, bsum, o); }
    if ((t & 31) == 0) { r1[t>>5] = s; r2[t>>5] = bsum; }
    __syncthreads();
    if (t == 0) {
        float ts = 0.f, tb = 0.f;
        #pragma unroll
        for (int w = 0; w < 8; w++) { ts += r1[w]; tb += r2[w]; }
        g_csum[j] = ts; g_cbias[j] = tb;
    }
}

// ---------------- prep: bf16 hi/lo split of Wc ----------------
__global__ void __launch_bounds__(256) prep_wc_bf(void) {
    int i = blockIdx.x * 256 + threadIdx.x;
    if (i < 512*DF) {
        float x = g_Wc[i];
        __nv_bfloat16 h = __float2bfloat16_rn(x);
        float lo = x - __bfloat162float(h);
        g_WcHi[i] = h;
        g_WcLo[i] = __float2bfloat16_rn(lo);
    }
}

// ---------------- prep: transposed small weights + copy slots ----------------
__global__ void prep_transpose(const float* __restrict__ Wq,
                               const float* __restrict__ Wih,
                               const float* __restrict__ Whh,
                               const float* __restrict__ W1,
                               const float* __restrict__ W2,
                               const float* __restrict__ prev) {
    int i = blockIdx.x * blockDim.x + threadIdx.x;
    if (i < 768*256) {
        int g = i / 256, d = i % 256;
        g_WihT[d*768 + g] = Wih[i];
        g_WhhT[d*768 + g] = Whh[i];
    }
    if (i < 256*256) {
        int r = i / 256, c = i % 256;
        g_WqT[c*256 + r] = Wq[i];
        g_W1T[c*256 + r] = W1[i];
        g_W2T[c*256 + r] = W2[i];
    }
    if (i < BB*KSLOT*DS) g_slots[i] = prev[i];
}

// ---------------- per-row LN stats of features ----------------
__global__ void __launch_bounds__(256) row_stats(const float* __restrict__ F) {
    int row = blockIdx.x;
    const float* x = F + (size_t)row * DF;
    int t = threadIdx.x;
    float a0 = x[t], a1 = x[t+256], a2 = x[t+512];
    float s  = a0 + a1 + a2;
    float s2 = a0*a0 + a1*a1 + a2*a2;
    __shared__ float r1[8], r2[8];
    for (int o = 16; o; o >>= 1) { s += __shfl_down_sync(0xffffffffu, s, o); s2 += __shfl_down_sync(0xffffffffu, s2, o); }
    if ((t & 31) == 0) { r1[t>>5] = s; r2[t>>5] = s2; }
    __syncthreads();
    if (t == 0) {
        float ts = 0.f, ts2 = 0.f;
        #pragma unroll
        for (int w = 0; w < 8; w++) { ts += r1[w]; ts2 += r2[w]; }
        float m   = ts * (1.f/768.f);
        float var = ts2 * (1.f/768.f) - m*m;
        g_mean[row] = m;
        g_rstd[row] = rsqrtf(var + 1e-5f);
    }
}

// ---------------- tensor-core GEMM via mma.sync with bf16 hi/lo compensation ----------------
// C[131072 x 512] = F[131072 x 768] @ Wc^T, fp32 accum.
// CTA 128x128, BK=32, 8 warps (warp tile 64x32), double-buffered SMEM.
#define PADH 40                   // bf16 per smem row (80 bytes): 80/16 odd -> conflict-free frags
#define TILE_BYTES (128*PADH*2)   // 10240
#define STAGE_BYTES (4*TILE_BYTES)// Ahi, Alo, Bhi, Blo = 40960
#define GEMM_SMEM (2*STAGE_BYTES) // 81920
#define NCHUNK (DF/32)            // 24

__device__ __forceinline__ uint32_t pack_bf2(float x, float y) {
    __nv_bfloat16 hx = __float2bfloat16_rn(x);
    __nv_bfloat16 hy = __float2bfloat16_rn(y);
    return (uint32_t)__bfloat16_as_ushort(hx) | ((uint32_t)__bfloat16_as_ushort(hy) << 16);
}

#define MMA16816(C, A, B) \
    asm volatile("mma.sync.aligned.m16n8k16.row.col.f32.bf16.bf16.f32 " \
        "{%0,%1,%2,%3}, {%4,%5,%6,%7}, {%8,%9}, {%0,%1,%2,%3};" \
        : "+f"((C)[0]), "+f"((C)[1]), "+f"((C)[2]), "+f"((C)[3]) \
        : "r"((A)[0]), "r"((A)[1]), "r"((A)[2]), "r"((A)[3]), "r"((B)[0]), "r"((B)[1]))

__global__ void __launch_bounds__(256) gemm_mma(const float* __restrict__ F) {
    extern __shared__ __align__(16) char smd[];
    __shared__ float s_cs[128], s_cb[128];

    const int tid = threadIdx.x;
    const int wid = tid >> 5, lane = tid & 31;
    const int wm = wid & 1, wn = wid >> 1;      // warp grid 2 x 4
    const int bn = blockIdx.x * 128;
    const int bm = blockIdx.y * 128;

    if (tid < 128) { s_cs[tid] = g_csum[bn + tid]; s_cb[tid] = g_cbias[bn + tid]; }

    // staging indices
    const int ar0 = tid >> 3;            // 0..31 (A row base)
    const int ac4 = tid & 7;             // float4 col within 32
    const int br  = tid >> 1;            // 0..127 (B row)
    const int bq  = (tid & 1) * 2;       // uint4 pair base

    const float* Abase = F + (size_t)(bm) * DF;

    float4 pa[4];
    uint4  pbh[2], pbl[2];

    // ---- load chunk 0 into regs ----
    {
        const int kb = 0;
        #pragma unroll
        for (int j = 0; j < 4; j++)
            pa[j] = *(const float4*)(Abase + (size_t)(ar0 + 32*j) * DF + kb + ac4 * 4);
        #pragma unroll
        for (int i = 0; i < 2; i++) {
            pbh[i] = *(const uint4*)(g_WcHi + (size_t)(bn + br) * DF + kb + (bq + i) * 8);
            pbl[i] = *(const uint4*)(g_WcLo + (size_t)(bn + br) * DF + kb + (bq + i) * 8);
        }
    }

    float acc[4][4][4];
    #pragma unroll
    for (int mi = 0; mi < 4; mi++)
        #pragma unroll
        for (int ni = 0; ni < 4; ni++)
            #pragma unroll
            for (int e = 0; e < 4; e++) acc[mi][ni][e] = 0.f;

    // ---- store chunk 0 to smem buf 0 ----
    {
        char* Ah = smd; char* Al = smd + TILE_BYTES;
        char* Bh = smd + 2*TILE_BYTES; char* Bl = smd + 3*TILE_BYTES;
        #pragma unroll
        for (int j = 0; j < 4; j++) {
            int row = ar0 + 32*j;
            uint32_t off = row * (PADH*2) + ac4 * 8;
            float4 x = pa[j];
            *(uint2*)(Ah + off) = make_uint2(pack_bf2(x.x, x.y), pack_bf2(x.z, x.w));
            __nv_bfloat16 hx = __float2bfloat16_rn(x.x), hy = __float2bfloat16_rn(x.y);
            __nv_bfloat16 hz = __float2bfloat16_rn(x.z), hw = __float2bfloat16_rn(x.w);
            *(uint2*)(Al + off) = make_uint2(
                pack_bf2(x.x - __bfloat162float(hx), x.y - __bfloat162float(hy)),
                pack_bf2(x.z - __bfloat162float(hz), x.w - __bfloat162float(hw)));
        }
        #pragma unroll
        for (int i = 0; i < 2; i++) {
            uint32_t off = br * (PADH*2) + (bq + i) * 16;
            *(uint4*)(Bh + off) = pbh[i];
            *(uint4*)(Bl + off) = pbl[i];
        }
    }
    __syncthreads();

    // fragment lane addressing
    const int fr = lane >> 2;            // 0..7
    const int fk = (lane & 3) * 4;       // byte offset of k-pair

    #pragma unroll 1
    for (int c = 0; c < NCHUNK; c++) {
        const int p = c & 1;
        const char* Ah = smd + p * STAGE_BYTES;
        const char* Al = Ah + TILE_BYTES;
        const char* Bh = Ah + 2*TILE_BYTES;
        const char* Bl = Ah + 3*TILE_BYTES;

        // prefetch next chunk into regs (latency overlapped with mma below)
        if (c + 1 < NCHUNK) {
            const int kb = (c + 1) * 32;
            #pragma unroll
            for (int j = 0; j < 4; j++)
                pa[j] = *(const float4*)(Abase + (size_t)(ar0 + 32*j) * DF + kb + ac4 * 4);
            #pragma unroll
            for (int i = 0; i < 2; i++) {
                pbh[i] = *(const uint4*)(g_WcHi + (size_t)(bn + br) * DF + kb + (bq + i) * 8);
                pbl[i] = *(const uint4*)(g_WcLo + (size_t)(bn + br) * DF + kb + (bq + i) * 8);
            }
        }

        // compute: 2 k16 steps x 3 compensation passes x 16 mma
        #pragma unroll
        for (int ks = 0; ks < 2; ks++) {
            uint32_t af[4][4], bfr[4][2];
            // A offsets: row (wm*64 + mi*16 + fr), k = ks*16 + lane pair
            #pragma unroll
            for (int mi = 0; mi < 4; mi++) {
                uint32_t o = (wm*64 + mi*16 + fr) * (PADH*2) + ks*32 + fk;
                af[mi][0] = *(const uint32_t*)(Ah + o);
                af[mi][1] = *(const uint32_t*)(Ah + o + 8*(PADH*2));
                af[mi][2] = *(const uint32_t*)(Ah + o + 16);
                af[mi][3] = *(const uint32_t*)(Ah + o + 8*(PADH*2) + 16);
            }
            #pragma unroll
            for (int ni = 0; ni < 4; ni++) {
                uint32_t o = (wn*32 + ni*8 + fr) * (PADH*2) + ks*32 + fk;
                bfr[ni][0] = *(const uint32_t*)(Bh + o);
                bfr[ni][1] = *(const uint32_t*)(Bh + o + 16);
            }
            #pragma unroll
            for (int mi = 0; mi < 4; mi++)
                #pragma unroll
                for (int ni = 0; ni < 4; ni++)
                    MMA16816(acc[mi][ni], af[mi], bfr[ni]);

            // Ahi x Blo
            #pragma unroll
            for (int ni = 0; ni < 4; ni++) {
                uint32_t o = (wn*32 + ni*8 + fr) * (PADH*2) + ks*32 + fk;
                bfr[ni][0] = *(const uint32_t*)(Bl + o);
                bfr[ni][1] = *(const uint32_t*)(Bl + o + 16);
            }
            #pragma unroll
            for (int mi = 0; mi < 4; mi++)
                #pragma unroll
                for (int ni = 0; ni < 4; ni++)
                    MMA16816(acc[mi][ni], af[mi], bfr[ni]);

            // Alo x Bhi
            #pragma unroll
            for (int mi = 0; mi < 4; mi++) {
                uint32_t o = (wm*64 + mi*16 + fr) * (PADH*2) + ks*32 + fk;
                af[mi][0] = *(const uint32_t*)(Al + o);
                af[mi][1] = *(const uint32_t*)(Al + o + 8*(PADH*2));
                af[mi][2] = *(const uint32_t*)(Al + o + 16);
                af[mi][3] = *(const uint32_t*)(Al + o + 8*(PADH*2) + 16);
            }
            #pragma unroll
            for (int ni = 0; ni < 4; ni++) {
                uint32_t o = (wn*32 + ni*8 + fr) * (PADH*2) + ks*32 + fk;
                bfr[ni][0] = *(const uint32_t*)(Bh + o);
                bfr[ni][1] = *(const uint32_t*)(Bh + o + 16);
            }
            #pragma unroll
            for (int mi = 0; mi < 4; mi++)
                #pragma unroll
                for (int ni = 0; ni < 4; ni++)
                    MMA16816(acc[mi][ni], af[mi], bfr[ni]);
        }

        __syncthreads();
        if (c + 1 < NCHUNK) {
            char* nAh = smd + (p ^ 1) * STAGE_BYTES;
            char* nAl = nAh + TILE_BYTES;
            char* nBh = nAh + 2*TILE_BYTES;
            char* nBl = nAh + 3*TILE_BYTES;
            #pragma unroll
            for (int j = 0; j < 4; j++) {
                int row = ar0 + 32*j;
                uint32_t off = row * (PADH*2) + ac4 * 8;
                float4 x = pa[j];
                *(uint2*)(nAh + off) = make_uint2(pack_bf2(x.x, x.y), pack_bf2(x.z, x.w));
                __nv_bfloat16 hx = __float2bfloat16_rn(x.x), hy = __float2bfloat16_rn(x.y);
                __nv_bfloat16 hz = __float2bfloat16_rn(x.z), hw = __float2bfloat16_rn(x.w);
                *(uint2*)(nAl + off) = make_uint2(
                    pack_bf2(x.x - __bfloat162float(hx), x.y - __bfloat162float(hy)),
                    pack_bf2(x.z - __bfloat162float(hz), x.w - __bfloat162float(hw)));
            }
            #pragma unroll
            for (int i = 0; i < 2; i++) {
                uint32_t off = br * (PADH*2) + (bq + i) * 16;
                *(uint4*)(nBh + off) = pbh[i];
                *(uint4*)(nBl + off) = pbl[i];
            }
            __syncthreads();
        }
    }

    // ---- epilogue: LN fold + split to k/v ----
    #pragma unroll
    for (int mi = 0; mi < 4; mi++) {
        int r1 = bm + wm*64 + mi*16 + fr;
        int r2 = r1 + 8;
        float rm1 = g_mean[r1], rs1 = g_rstd[r1];
        float rm2 = g_mean[r2], rs2 = g_rstd[r2];
        #pragma unroll
        for (int ni = 0; ni < 4; ni++) {
            int cl = wn*32 + ni*8 + (lane & 3)*2;   // local col in [0,128)
            int colg = bn + cl;
            float cs0 = s_cs[cl], cs1 = s_cs[cl+1];
            float cb0 = s_cb[cl], cb1 = s_cb[cl+1];
            float* d1;
            float* d2;
            if (colg < 256) {
                d1 = g_k + (size_t)r1*DS + colg;
                d2 = g_k + (size_t)r2*DS + colg;
            } else {
                d1 = g_v + (size_t)r1*DS + (colg - 256);
                d2 = g_v + (size_t)r2*DS + (colg - 256);
            }
            float2 o1, o2;
            o1.x = rs1*(acc[mi][ni][0] - rm1*cs0) + cb0;
            o1.y = rs1*(acc[mi][ni][1] - rm1*cs1) + cb1;
            o2.x = rs2*(acc[mi][ni][2] - rm2*cs0) + cb0;
            o2.y = rs2*(acc[mi][ni][3] - rm2*cs1) + cb1;
            *(float2*)d1 = o1;
            *(float2*)d2 = o2;
        }
    }
}

// ---------------- per-slot q = LN(slots) @ Wq^T ----------------
__global__ void __launch_bounds__(256) slot_q(const float* __restrict__ gs, const float* __restrict__ bs) {
    int row = blockIdx.x;
    int t = threadIdx.x;
    __shared__ float sn[256];
    __shared__ float r1[8], r2[8];
    __shared__ float smv[2];
    float x = g_slots[row*256 + t];
    float s = x, s2 = x*x;
    for (int o = 16; o; o >>= 1) { s += __shfl_down_sync(0xffffffffu, s, o); s2 += __shfl_down_sync(0xffffffffu, s2, o); }
    if ((t & 31) == 0) { r1[t>>5] = s; r2[t>>5] = s2; }
    __syncthreads();
    if (t == 0) {
        float ts = 0.f, ts2 = 0.f;
        #pragma unroll
        for (int w = 0; w < 8; w++) { ts += r1[w]; ts2 += r2[w]; }
        float m = ts * (1.f/256.f);
        float var = ts2 * (1.f/256.f) - m*m;
        smv[0] = m; smv[1] = rsqrtf(var + 1e-5f);
    }
    __syncthreads();
    sn[t] = (x - smv[0]) * smv[1] * gs[t] + bs[t];
    __syncthreads();
    float acc = 0.f;
    #pragma unroll 4
    for (int d = 0; d < 256; d++) acc += sn[d] * g_WqT[d*256 + t];
    g_q[row*256 + t] = acc;
}

// ---------------- zero U/S accumulators ----------------
__global__ void zero_US() {
    int i = blockIdx.x * blockDim.x + threadIdx.x;
    if (i < BB*KSLOT*DS) g_U[i] = 0.f;
    if (i < BB*KSLOT)    g_S[i] = 0.f;
}

// ---------------- fused attention sweep ----------------
#define ATILE 32
#define KPAD 260
#define CHUNKS 16
#define ATTN_SMEM_FLOATS (8*256 + 2*ATILE*KPAD + 2*8*36)

template <bool FINAL>
__global__ void __launch_bounds__(256) attn_pass(float* __restrict__ out_attn) {
    extern __shared__ float sm[];
    float* qs = sm;
    float* kt = qs + 8*256;
    float* vt = kt + ATILE*KPAD;
    float* Ls = vt + ATILE*KPAD;
    float* ps = Ls + 8*36;

    int b  = blockIdx.x;
    int ch = blockIdx.y;
    int t  = threadIdx.x;

    for (int i = t; i < 8*256; i += 256) qs[i] = g_q[b*2048 + i] * SCALE_F;

    const int n0 = ch * (NN / CHUNKS);
    float regU[8], regS[8];
    #pragma unroll
    for (int h = 0; h < 8; h++) { regU[h] = 0.f; regS[h] = 0.f; }

    const int hq = t >> 5;
    const int nl = t & 31;

    #pragma unroll 1
    for (int tile = 0; tile < (NN/CHUNKS)/ATILE; tile++) {
        int nbase = n0 + tile * ATILE;
        __syncthreads();
        const float* kg = g_k + ((size_t)b*NN + nbase) * DS;
        const float* vg = g_v + ((size_t)b*NN + nbase) * DS;
        for (int i = t; i < ATILE*64; i += 256) {
            int n = i >> 6; int d4 = (i & 63) << 2;
            *(float4*)(kt + n*KPAD + d4) = *(const float4*)(kg + n*DS + d4);
            if (!FINAL)
                *(float4*)(vt + n*KPAD + d4) = *(const float4*)(vg + n*DS + d4);
        }
        __syncthreads();

        {
            float acc = 0.f;
            const float* qrow = qs + hq*256;
            const float* krow = kt + nl*KPAD;
            #pragma unroll 8
            for (int d = 0; d < 256; d += 4) {
                float4 qv = *(const float4*)(qrow + d);
                float4 kv = *(const float4*)(krow + d);
                acc += qv.x*kv.x + qv.y*kv.y + qv.z*kv.z + qv.w*kv.w;
            }
            Ls[hq*36 + nl] = acc;
        }
        __syncthreads();

        if (t < 32) {
            float l[8], m = -1e30f;
            #pragma unroll
            for (int h = 0; h < 8; h++) { l[h] = Ls[h*36 + t]; m = fmaxf(m, l[h]); }
            float ssum = 0.f;
            #pragma unroll
            for (int h = 0; h < 8; h++) { l[h] = expf(l[h] - m); ssum += l[h]; }
            float inv = 1.f / ssum;
            #pragma unroll
            for (int h = 0; h < 8; h++) {
                float p = l[h] * inv;
                ps[h*36 + t] = p;
                regS[h] += p;
                if (FINAL)
                    out_attn[((size_t)b*KSLOT + h)*NN + nbase + t] = p;
            }
        }
        __syncthreads();

        if (!FINAL) {
            #pragma unroll 4
            for (int n = 0; n < ATILE; n++) {
                float vv = vt[n*KPAD + t];
                #pragma unroll
                for (int h = 0; h < 8; h++) regU[h] += ps[h*36 + n] * vv;
            }
        }
    }

    if (!FINAL) {
        #pragma unroll
        for (int h = 0; h < 8; h++)
            atomicAdd(&g_U[((size_t)b*KSLOT + h)*DS + t], regU[h]);
    }
    if (t < 32) {
        #pragma unroll
        for (int h = 0; h < 8; h++) {
            float v = regS[h];
            for (int o = 16; o; o >>= 1) v += __shfl_down_sync(0xffffffffu, v, o);
            if (t == 0) atomicAdd(&g_S[b*KSLOT + h], v);
        }
    }
}

// ---------------- GRU gate GEMMs ----------------
__global__ void __launch_bounds__(256) gru_gemm(const float* __restrict__ bih, const float* __restrict__ bhh) {
    int blk = blockIdx.x;
    int b = blk / 24, gc = blk % 24;
    __shared__ float su[8*256], ss[8*256];
    int t = threadIdx.x;
    for (int i = t; i < 2048; i += 256) {
        int k = i >> 8;
        su[i] = g_U[b*2048 + i] / (g_S[b*8 + k] + EPS_ATTN);
        ss[i] = g_slots[b*2048 + i];
    }
    __syncthreads();
    int g = gc*32 + (t & 31);
    int k = t >> 5;
    float gi = bih[g], gh = bhh[g];
    const float* su_k = su + k*256;
    const float* ss_k = ss + k*256;
    #pragma unroll 4
    for (int d = 0; d < 256; d++) {
        gi += su_k[d] * g_WihT[d*768 + g];
        gh += ss_k[d] * g_WhhT[d*768 + g];
    }
    g_gi[((size_t)b*8 + k)*768 + g] = gi;
    g_gh[((size_t)b*8 + k)*768 + g] = gh;
}

// ---------------- GRU combine + LN + MLP ----------------
__global__ void __launch_bounds__(256) gru_mlp(const float* __restrict__ gm, const float* __restrict__ bm,
                                               const float* __restrict__ b1, const float* __restrict__ b2) {
    int bk = blockIdx.x;
    int t = threadIdx.x;
    const float* gi = g_gi + (size_t)bk*768;
    const float* gh = g_gh + (size_t)bk*768;
    float sl = g_slots[bk*256 + t];
    float r  = 1.f / (1.f + expf(-(gi[t]       + gh[t])));
    float z  = 1.f / (1.f + expf(-(gi[256 + t] + gh[256 + t])));
    float nn = tanhf(gi[512 + t] + r * gh[512 + t]);
    float h  = (1.f - z) * nn + z * sl;

    __shared__ float hn[256], ms[256];
    __shared__ float r1[8], r2[8];
    __shared__ float smv[2];
    float s = h, s2 = h*h;
    for (int o = 16; o; o >>= 1) { s += __shfl_down_sync(0xffffffffu, s, o); s2 += __shfl_down_sync(0xffffffffu, s2, o); }
    if ((t & 31) == 0) { r1[t>>5] = s; r2[t>>5] = s2; }
    __syncthreads();
    if (t == 0) {
        float ts = 0.f, ts2 = 0.f;
        #pragma unroll
        for (int w = 0; w < 8; w++) { ts += r1[w]; ts2 += r2[w]; }
        float m = ts * (1.f/256.f);
        float var = ts2 * (1.f/256.f) - m*m;
        smv[0] = m; smv[1] = rsqrtf(var + 1e-5f);
    }
    __syncthreads();
    hn[t] = (h - smv[0]) * smv[1] * gm[t] + bm[t];
    __syncthreads();
    float acc = b1[t];
    #pragma unroll 4
    for (int d = 0; d < 256; d++) acc += hn[d] * g_W1T[d*256 + t];
    ms[t] = fmaxf(acc, 0.f);
    __syncthreads();
    float o = h + b2[t];
    #pragma unroll 4
    for (int j = 0; j < 256; j++) o += ms[j] * g_W2T[j*256 + t];
    g_slots[bk*256 + t] = o;
}

// ---------------- final confidence blend ----------------
__global__ void __launch_bounds__(256) finalize(const float* __restrict__ prev, float* __restrict__ out_slots) {
    int bk = blockIdx.x;
    int t = threadIdx.x;
    float mean = g_S[bk] * (1.f / 4096.f);
    float mask = 1.f / (1.f + expf(-mean));
    out_slots[bk*256 + t] = g_slots[bk*256 + t] * mask + prev[bk*256 + t] * (1.f - mask);
}

// ---------------- launch ----------------
extern "C" void kernel_launch(void* const* d_in, const int* in_sizes, int n_in,
                              void* d_out, int out_size) {
    const float* features = (const float*)d_in[0];
    const float* prev     = (const float*)d_in[1];
    const float* gin      = (const float*)d_in[2];
    const float* bin      = (const float*)d_in[3];
    const float* gs       = (const float*)d_in[4];
    const float* bs       = (const float*)d_in[5];
    const float* gm       = (const float*)d_in[6];
    const float* bm       = (const float*)d_in[7];
    const float* Wq       = (const float*)d_in[8];
    const float* Wk       = (const float*)d_in[9];
    const float* Wv       = (const float*)d_in[10];
    const float* Wih      = (const float*)d_in[11];
    const float* Whh      = (const float*)d_in[12];
    const float* bih      = (const float*)d_in[13];
    const float* bhh      = (const float*)d_in[14];
    const float* W1       = (const float*)d_in[15];
    const float* b1       = (const float*)d_in[16];
    const float* W2       = (const float*)d_in[17];
    const float* b2       = (const float*)d_in[18];

    float* out_slots = (float*)d_out;
    float* out_attn  = out_slots + BB*KSLOT*DS;

    const size_t attn_smem = (size_t)ATTN_SMEM_FLOATS * sizeof(float);
    cudaFuncSetAttribute((const void*)attn_pass<false>, cudaFuncAttributeMaxDynamicSharedMemorySize, (int)attn_smem);
    cudaFuncSetAttribute((const void*)attn_pass<true>,  cudaFuncAttributeMaxDynamicSharedMemorySize, (int)attn_smem);
    cudaFuncSetAttribute((const void*)gemm_mma, cudaFuncAttributeMaxDynamicSharedMemorySize, GEMM_SMEM);

    // prep
    prep_wc<<<512, 256>>>(Wk, Wv, gin, bin);
    prep_wc_bf<<<(512*DF + 255)/256, 256>>>();
    prep_transpose<<<(768*256 + 255)/256, 256>>>(Wq, Wih, Whh, W1, W2, prev);

    // phase A: LN stats + tensor-core projection GEMM
    row_stats<<<NROWS, 256>>>(features);
    gemm_mma<<<dim3(512/128, NROWS/128), 256, GEMM_SMEM>>>(features);

    // phase B: 3 slot-attention iterations
    for (int it = 0; it < 3; it++) {
        zero_US<<<(BB*KSLOT*DS + 255)/256, 256>>>();
        slot_q<<<BB*KSLOT, 256>>>(gs, bs);
        attn_pass<false><<<dim3(BB, CHUNKS), 256, attn_smem>>>(nullptr);
        gru_gemm<<<BB*24, 256>>>(bih, bhh);
        gru_mlp<<<BB*KSLOT, 256>>>(gm, bm, b1, b2);
    }

    // final attention + blend
    zero_US<<<(BB*KSLOT*DS + 255)/256, 256>>>();
    slot_q<<<BB*KSLOT, 256>>>(gs, bs);
    attn_pass<true><<<dim3(BB, CHUNKS), 256, attn_smem>>>(out_attn);
    finalize<<<BB*KSLOT, 256>>>(prev, out_slots);

    (void)in_sizes; (void)n_in; (void)out_size;
}

// round 4
// speedup vs baseline: 1.6112x; 1.1436x over previous
#include <cuda_runtime.h>
#include <cuda_bf16.h>
#include <cstdint>
#include <math.h>

// ---------------- problem constants ----------------
#define BB 32
#define NN 4096
#define DF 768
#define DS 256
#define KSLOT 8
#define NROWS (BB*NN)        // 131072
#define SCALE_F 0.0625f      // 256^-0.5
#define EPS_ATTN 1e-8f

// ---------------- scratch (device globals; no allocations allowed) ----------------
static __device__ float g_mean[NROWS];
static __device__ float g_rstd[NROWS];
static __device__ float g_k[(size_t)NROWS*DS];     // 134 MB
static __device__ float g_v[(size_t)NROWS*DS];     // 134 MB
static __device__ float g_Wc[512*DF];              // [Wk';Wv'] with g_in folded in
static __device__ __align__(16) __nv_bfloat16 g_WcHi[512*DF];
static __device__ __align__(16) __nv_bfloat16 g_WcLo[512*DF];
static __device__ float g_csum[512];
static __device__ float g_cbias[512];
static __device__ float g_WqT[DS*DS];
static __device__ float g_WihT[DS*768];
static __device__ float g_WhhT[DS*768];
static __device__ float g_W1T[DS*DS];
static __device__ float g_W2T[DS*DS];
static __device__ float g_q[BB*KSLOT*DS];
static __device__ float g_slots[BB*KSLOT*DS];
static __device__ float g_U[BB*KSLOT*DS];
static __device__ float g_S[BB*KSLOT];
static __device__ float g_gi[BB*KSLOT*768];
static __device__ float g_gh[BB*KSLOT*768];

// ---------------- prep: combined, g-scaled projection weights ----------------
__global__ void __launch_bounds__(256) prep_wc(const float* __restrict__ Wk,
                                               const float* __restrict__ Wv,
                                               const float* __restrict__ gin,
                                               const float* __restrict__ bin) {
    int j = blockIdx.x;             // 0..511  (0..255 -> k, 256..511 -> v)
    const float* W = (j < 256) ? (Wk + (size_t)j*DF) : (Wv + (size_t)(j-256)*DF);
    int t = threadIdx.x;
    float s = 0.f, bsum = 0.f;
    for (int f = t; f < DF; f += 256) {
        float w  = W[f];
        float wc = w * gin[f];
        g_Wc[(size_t)j*DF + f] = wc;
        s += wc; bsum += w * bin[f];
    }
    __shared__ float r1[8], r2[8];
    for (int o = 16; o; o >>= 1) { s += __shfl_down_sync(0xffffffffu, s, o); bsum += __shfl_down_sync(0xffffffffu, bsum, o); }
    if ((t & 31) == 0) { r1[t>>5] = s; r2[t>>5] = bsum; }
    __syncthreads();
    if (t == 0) {
        float ts = 0.f, tb = 0.f;
        #pragma unroll
        for (int w = 0; w < 8; w++) { ts += r1[w]; tb += r2[w]; }
        g_csum[j] = ts; g_cbias[j] = tb;
    }
}

// ---------------- prep: bf16 hi/lo split of Wc ----------------
__global__ void __launch_bounds__(256) prep_wc_bf(void) {
    int i = blockIdx.x * 256 + threadIdx.x;
    if (i < 512*DF) {
        float x = g_Wc[i];
        __nv_bfloat16 h = __float2bfloat16_rn(x);
        float lo = x - __bfloat162float(h);
        g_WcHi[i] = h;
        g_WcLo[i] = __float2bfloat16_rn(lo);
    }
}

// ---------------- prep: transposed small weights + copy slots ----------------
__global__ void prep_transpose(const float* __restrict__ Wq,
                               const float* __restrict__ Wih,
                               const float* __restrict__ Whh,
                               const float* __restrict__ W1,
                               const float* __restrict__ W2,
                               const float* __restrict__ prev) {
    int i = blockIdx.x * blockDim.x + threadIdx.x;
    if (i < 768*256) {
        int g = i / 256, d = i % 256;
        g_WihT[d*768 + g] = Wih[i];
        g_WhhT[d*768 + g] = Whh[i];
    }
    if (i < 256*256) {
        int r = i / 256, c = i % 256;
        g_WqT[c*256 + r] = Wq[i];
        g_W1T[c*256 + r] = W1[i];
        g_W2T[c*256 + r] = W2[i];
    }
    if (i < BB*KSLOT*DS) g_slots[i] = prev[i];
}

// ---------------- per-row LN stats: warp per row, float4 ----------------
__global__ void __launch_bounds__(256) row_stats(const float* __restrict__ F) {
    int w = threadIdx.x >> 5, l = threadIdx.x & 31;
    int row = blockIdx.x * 8 + w;
    const float4* x = (const float4*)(F + (size_t)row * DF);
    float s = 0.f, s2 = 0.f;
    #pragma unroll
    for (int j = 0; j < 6; j++) {
        float4 a = x[l + 32*j];
        s  += a.x + a.y + a.z + a.w;
        s2 += a.x*a.x + a.y*a.y + a.z*a.z + a.w*a.w;
    }
    for (int o = 16; o; o >>= 1) {
        s  += __shfl_down_sync(0xffffffffu, s, o);
        s2 += __shfl_down_sync(0xffffffffu, s2, o);
    }
    if (l == 0) {
        float m   = s * (1.f/768.f);
        float var = s2 * (1.f/768.f) - m*m;
        g_mean[row] = m;
        g_rstd[row] = rsqrtf(var + 1e-5f);
    }
}

// ---------------- tensor-core GEMM via mma.sync with bf16 hi/lo compensation ----------------
// C[131072 x 512] = F[131072 x 768] @ Wc^T, fp32 accum.
// CTA 128x256, BK=32, 8 warps (2x4 grid, warp tile 64x64), double-buffered SMEM.
#define PADH 40                      // bf16 per smem row (80 bytes): 80/16 odd -> conflict-free frags
#define TILE_A (128*PADH*2)          // 10240
#define TILE_Bb (256*PADH*2)         // 20480
#define STAGE_BYTES (2*TILE_A + 2*TILE_Bb)  // 61440: Ah, Al, Bh, Bl
#define GEMM_SMEM (2*STAGE_BYTES)    // 122880
#define NCHUNK (DF/32)               // 24

__device__ __forceinline__ uint32_t pack_bf2(float x, float y) {
    __nv_bfloat16 hx = __float2bfloat16_rn(x);
    __nv_bfloat16 hy = __float2bfloat16_rn(y);
    return (uint32_t)__bfloat16_as_ushort(hx) | ((uint32_t)__bfloat16_as_ushort(hy) << 16);
}

#define MMA16816(C, A, B) \
    asm volatile("mma.sync.aligned.m16n8k16.row.col.f32.bf16.bf16.f32 " \
        "{%0,%1,%2,%3}, {%4,%5,%6,%7}, {%8,%9}, {%0,%1,%2,%3};" \
        : "+f"((C)[0]), "+f"((C)[1]), "+f"((C)[2]), "+f"((C)[3]) \
        : "r"((A)[0]), "r"((A)[1]), "r"((A)[2]), "r"((A)[3]), "r"((B)[0]), "r"((B)[1]))

__global__ void __launch_bounds__(256) gemm_mma(const float* __restrict__ F) {
    extern __shared__ __align__(16) char smd[];
    __shared__ float s_cs[256], s_cb[256];

    const int tid = threadIdx.x;
    const int wid = tid >> 5, lane = tid & 31;
    const int wm = wid & 1, wn = wid >> 1;      // warp grid 2 x 4, tile 64x64
    const int bn = blockIdx.x * 256;
    const int bm = blockIdx.y * 128;

    s_cs[tid] = g_csum[bn + tid];
    s_cb[tid] = g_cbias[bn + tid];

    // staging indices
    const int ar0 = tid >> 3;            // 0..31 (A row base; 4 rows stepping 32)
    const int ac4 = tid & 7;             // float4 col within 32
    const int br0 = tid >> 2;            // 0..63 (B row base; 4 rows stepping 64)
    const int bq4 = tid & 3;             // uint4 within row (4 per 32-bf16 row)

    const float* Abase = F + (size_t)bm * DF;

    float4 pa[4];
    uint4  pbh[4], pbl[4];

    // ---- load chunk 0 into regs ----
    {
        #pragma unroll
        for (int j = 0; j < 4; j++)
            pa[j] = *(const float4*)(Abase + (size_t)(ar0 + 32*j) * DF + ac4 * 4);
        #pragma unroll
        for (int j = 0; j < 4; j++) {
            pbh[j] = *(const uint4*)(g_WcHi + (size_t)(bn + br0 + 64*j) * DF + bq4 * 8);
            pbl[j] = *(const uint4*)(g_WcLo + (size_t)(bn + br0 + 64*j) * DF + bq4 * 8);
        }
    }

    float acc[4][8][4];
    #pragma unroll
    for (int mi = 0; mi < 4; mi++)
        #pragma unroll
        for (int ni = 0; ni < 8; ni++)
            #pragma unroll
            for (int e = 0; e < 4; e++) acc[mi][ni][e] = 0.f;

    // ---- store chunk 0 to smem buf 0 ----
    {
        char* Ah = smd;                 char* Al = smd + TILE_A;
        char* Bh = smd + 2*TILE_A;      char* Bl = Bh + TILE_Bb;
        #pragma unroll
        for (int j = 0; j < 4; j++) {
            uint32_t off = (ar0 + 32*j) * (PADH*2) + ac4 * 8;
            float4 x = pa[j];
            *(uint2*)(Ah + off) = make_uint2(pack_bf2(x.x, x.y), pack_bf2(x.z, x.w));
            __nv_bfloat16 hx = __float2bfloat16_rn(x.x), hy = __float2bfloat16_rn(x.y);
            __nv_bfloat16 hz = __float2bfloat16_rn(x.z), hw = __float2bfloat16_rn(x.w);
            *(uint2*)(Al + off) = make_uint2(
                pack_bf2(x.x - __bfloat162float(hx), x.y - __bfloat162float(hy)),
                pack_bf2(x.z - __bfloat162float(hz), x.w - __bfloat162float(hw)));
        }
        #pragma unroll
        for (int j = 0; j < 4; j++) {
            uint32_t off = (br0 + 64*j) * (PADH*2) + bq4 * 16;
            *(uint4*)(Bh + off) = pbh[j];
            *(uint4*)(Bl + off) = pbl[j];
        }
    }
    __syncthreads();

    // fragment lane addressing
    const int fr = lane >> 2;            // 0..7
    const int fk = (lane & 3) * 4;       // byte offset of k-pair

    #pragma unroll 1
    for (int c = 0; c < NCHUNK; c++) {
        const int p = c & 1;
        const char* Ah = smd + p * STAGE_BYTES;
        const char* Al = Ah + TILE_A;
        const char* Bh = Ah + 2*TILE_A;
        const char* Bl = Bh + TILE_Bb;

        // prefetch next chunk into regs (latency overlapped with mma below)
        if (c + 1 < NCHUNK) {
            const int kb = (c + 1) * 32;
            #pragma unroll
            for (int j = 0; j < 4; j++)
                pa[j] = *(const float4*)(Abase + (size_t)(ar0 + 32*j) * DF + kb + ac4 * 4);
            #pragma unroll
            for (int j = 0; j < 4; j++) {
                pbh[j] = *(const uint4*)(g_WcHi + (size_t)(bn + br0 + 64*j) * DF + kb + bq4 * 8);
                pbl[j] = *(const uint4*)(g_WcLo + (size_t)(bn + br0 + 64*j) * DF + kb + bq4 * 8);
            }
        }

        // compute: 2 k16 steps x 3 compensation passes x 32 mma
        #pragma unroll
        for (int ks = 0; ks < 2; ks++) {
            uint32_t af[4][4], bfr[8][2];
            // Ahi frags
            #pragma unroll
            for (int mi = 0; mi < 4; mi++) {
                uint32_t o = (wm*64 + mi*16 + fr) * (PADH*2) + ks*32 + fk;
                af[mi][0] = *(const uint32_t*)(Ah + o);
                af[mi][1] = *(const uint32_t*)(Ah + o + 8*(PADH*2));
                af[mi][2] = *(const uint32_t*)(Ah + o + 16);
                af[mi][3] = *(const uint32_t*)(Ah + o + 8*(PADH*2) + 16);
            }
            // Bhi frags
            #pragma unroll
            for (int ni = 0; ni < 8; ni++) {
                uint32_t o = (wn*64 + ni*8 + fr) * (PADH*2) + ks*32 + fk;
                bfr[ni][0] = *(const uint32_t*)(Bh + o);
                bfr[ni][1] = *(const uint32_t*)(Bh + o + 16);
            }
            #pragma unroll
            for (int mi = 0; mi < 4; mi++)
                #pragma unroll
                for (int ni = 0; ni < 8; ni++)
                    MMA16816(acc[mi][ni], af[mi], bfr[ni]);

            // Ahi x Blo
            #pragma unroll
            for (int ni = 0; ni < 8; ni++) {
                uint32_t o = (wn*64 + ni*8 + fr) * (PADH*2) + ks*32 + fk;
                bfr[ni][0] = *(const uint32_t*)(Bl + o);
                bfr[ni][1] = *(const uint32_t*)(Bl + o + 16);
            }
            #pragma unroll
            for (int mi = 0; mi < 4; mi++)
                #pragma unroll
                for (int ni = 0; ni < 8; ni++)
                    MMA16816(acc[mi][ni], af[mi], bfr[ni]);

            // Alo x Bhi
            #pragma unroll
            for (int mi = 0; mi < 4; mi++) {
                uint32_t o = (wm*64 + mi*16 + fr) * (PADH*2) + ks*32 + fk;
                af[mi][0] = *(const uint32_t*)(Al + o);
                af[mi][1] = *(const uint32_t*)(Al + o + 8*(PADH*2));
                af[mi][2] = *(const uint32_t*)(Al + o + 16);
                af[mi][3] = *(const uint32_t*)(Al + o + 8*(PADH*2) + 16);
            }
            #pragma unroll
            for (int ni = 0; ni < 8; ni++) {
                uint32_t o = (wn*64 + ni*8 + fr) * (PADH*2) + ks*32 + fk;
                bfr[ni][0] = *(const uint32_t*)(Bh + o);
                bfr[ni][1] = *(const uint32_t*)(Bh + o + 16);
            }
            #pragma unroll
            for (int mi = 0; mi < 4; mi++)
                #pragma unroll
                for (int ni = 0; ni < 8; ni++)
                    MMA16816(acc[mi][ni], af[mi], bfr[ni]);
        }

        __syncthreads();
        if (c + 1 < NCHUNK) {
            char* nAh = smd + (p ^ 1) * STAGE_BYTES;
            char* nAl = nAh + TILE_A;
            char* nBh = nAh + 2*TILE_A;
            char* nBl = nBh + TILE_Bb;
            #pragma unroll
            for (int j = 0; j < 4; j++) {
                uint32_t off = (ar0 + 32*j) * (PADH*2) + ac4 * 8;
                float4 x = pa[j];
                *(uint2*)(nAh + off) = make_uint2(pack_bf2(x.x, x.y), pack_bf2(x.z, x.w));
                __nv_bfloat16 hx = __float2bfloat16_rn(x.x), hy = __float2bfloat16_rn(x.y);
                __nv_bfloat16 hz = __float2bfloat16_rn(x.z), hw = __float2bfloat16_rn(x.w);
                *(uint2*)(nAl + off) = make_uint2(
                    pack_bf2(x.x - __bfloat162float(hx), x.y - __bfloat162float(hy)),
                    pack_bf2(x.z - __bfloat162float(hz), x.w - __bfloat162float(hw)));
            }
            #pragma unroll
            for (int j = 0; j < 4; j++) {
                uint32_t off = (br0 + 64*j) * (PADH*2) + bq4 * 16;
                *(uint4*)(nBh + off) = pbh[j];
                *(uint4*)(nBl + off) = pbl[j];
            }
            __syncthreads();
        }
    }

    // ---- epilogue: LN fold + split to k/v ----
    #pragma unroll
    for (int mi = 0; mi < 4; mi++) {
        int r1 = bm + wm*64 + mi*16 + fr;
        int r2 = r1 + 8;
        float rm1 = g_mean[r1], rs1 = g_rstd[r1];
        float rm2 = g_mean[r2], rs2 = g_rstd[r2];
        #pragma unroll
        for (int ni = 0; ni < 8; ni++) {
            int cl = wn*64 + ni*8 + (lane & 3)*2;   // local col in [0,256)
            int colg = bn + cl;
            float cs0 = s_cs[cl], cs1 = s_cs[cl+1];
            float cb0 = s_cb[cl], cb1 = s_cb[cl+1];
            float* d1;
            float* d2;
            if (colg < 256) {
                d1 = g_k + (size_t)r1*DS + colg;
                d2 = g_k + (size_t)r2*DS + colg;
            } else {
                d1 = g_v + (size_t)r1*DS + (colg - 256);
                d2 = g_v + (size_t)r2*DS + (colg - 256);
            }
            float2 o1, o2;
            o1.x = rs1*(acc[mi][ni][0] - rm1*cs0) + cb0;
            o1.y = rs1*(acc[mi][ni][1] - rm1*cs1) + cb1;
            o2.x = rs2*(acc[mi][ni][2] - rm2*cs0) + cb0;
            o2.y = rs2*(acc[mi][ni][3] - rm2*cs1) + cb1;
            *(float2*)d1 = o1;
            *(float2*)d2 = o2;
        }
    }
}

// ---------------- per-slot q = LN(slots) @ Wq^T (also zeroes U/S accumulators) ----------------
__global__ void __launch_bounds__(256) slot_q(const float* __restrict__ gs, const float* __restrict__ bs) {
    int row = blockIdx.x;
    int t = threadIdx.x;
    __shared__ float sn[256];
    __shared__ float r1[8], r2[8];
    __shared__ float smv[2];
    // fold zero_US here: runs strictly before attn_pass accumulation
    g_U[row*256 + t] = 0.f;
    if (t == 0) g_S[row] = 0.f;
    float x = g_slots[row*256 + t];
    float s = x, s2 = x*x;
    for (int o = 16; o; o >>= 1) { s += __shfl_down_sync(0xffffffffu, s, o); s2 += __shfl_down_sync(0xffffffffu, s2, o); }
    if ((t & 31) == 0) { r1[t>>5] = s; r2[t>>5] = s2; }
    __syncthreads();
    if (t == 0) {
        float ts = 0.f, ts2 = 0.f;
        #pragma unroll
        for (int w = 0; w < 8; w++) { ts += r1[w]; ts2 += r2[w]; }
        float m = ts * (1.f/256.f);
        float var = ts2 * (1.f/256.f) - m*m;
        smv[0] = m; smv[1] = rsqrtf(var + 1e-5f);
    }
    __syncthreads();
    sn[t] = (x - smv[0]) * smv[1] * gs[t] + bs[t];
    __syncthreads();
    float acc = 0.f;
    #pragma unroll 4
    for (int d = 0; d < 256; d++) acc += sn[d] * g_WqT[d*256 + t];
    g_q[row*256 + t] = acc;
}

// ---------------- fused attention sweep ----------------
#define ATILE 32
#define KPAD 260
#define CHUNKS 16
#define ATTN_SMEM_FLOATS (8*256 + 2*ATILE*KPAD + 2*8*36)

template <bool FINAL>
__global__ void __launch_bounds__(256) attn_pass(float* __restrict__ out_attn) {
    extern __shared__ float sm[];
    float* qs = sm;
    float* kt = qs + 8*256;
    float* vt = kt + ATILE*KPAD;
    float* Ls = vt + ATILE*KPAD;
    float* ps = Ls + 8*36;

    int b  = blockIdx.x;
    int ch = blockIdx.y;
    int t  = threadIdx.x;

    for (int i = t; i < 8*256; i += 256) qs[i] = g_q[b*2048 + i] * SCALE_F;

    const int n0 = ch * (NN / CHUNKS);
    float regU[8], regS[8];
    #pragma unroll
    for (int h = 0; h < 8; h++) { regU[h] = 0.f; regS[h] = 0.f; }

    const int hq = t >> 5;
    const int nl = t & 31;

    #pragma unroll 1
    for (int tile = 0; tile < (NN/CHUNKS)/ATILE; tile++) {
        int nbase = n0 + tile * ATILE;
        __syncthreads();
        const float* kg = g_k + ((size_t)b*NN + nbase) * DS;
        const float* vg = g_v + ((size_t)b*NN + nbase) * DS;
        for (int i = t; i < ATILE*64; i += 256) {
            int n = i >> 6; int d4 = (i & 63) << 2;
            *(float4*)(kt + n*KPAD + d4) = *(const float4*)(kg + n*DS + d4);
            if (!FINAL)
                *(float4*)(vt + n*KPAD + d4) = *(const float4*)(vg + n*DS + d4);
        }
        __syncthreads();

        {
            float acc = 0.f;
            const float* qrow = qs + hq*256;
            const float* krow = kt + nl*KPAD;
            #pragma unroll 8
            for (int d = 0; d < 256; d += 4) {
                float4 qv = *(const float4*)(qrow + d);
                float4 kv = *(const float4*)(krow + d);
                acc += qv.x*kv.x + qv.y*kv.y + qv.z*kv.z + qv.w*kv.w;
            }
            Ls[hq*36 + nl] = acc;
        }
        __syncthreads();

        if (t < 32) {
            float l[8], m = -1e30f;
            #pragma unroll
            for (int h = 0; h < 8; h++) { l[h] = Ls[h*36 + t]; m = fmaxf(m, l[h]); }
            float ssum = 0.f;
            #pragma unroll
            for (int h = 0; h < 8; h++) { l[h] = expf(l[h] - m); ssum += l[h]; }
            float inv = 1.f / ssum;
            #pragma unroll
            for (int h = 0; h < 8; h++) {
                float p = l[h] * inv;
                ps[h*36 + t] = p;
                regS[h] += p;
                if (FINAL)
                    out_attn[((size_t)b*KSLOT + h)*NN + nbase + t] = p;
            }
        }
        __syncthreads();

        if (!FINAL) {
            #pragma unroll 4
            for (int n = 0; n < ATILE; n++) {
                float vv = vt[n*KPAD + t];
                #pragma unroll
                for (int h = 0; h < 8; h++) regU[h] += ps[h*36 + n] * vv;
            }
        }
    }

    if (!FINAL) {
        #pragma unroll
        for (int h = 0; h < 8; h++)
            atomicAdd(&g_U[((size_t)b*KSLOT + h)*DS + t], regU[h]);
    }
    if (t < 32) {
        #pragma unroll
        for (int h = 0; h < 8; h++) {
            float v = regS[h];
            for (int o = 16; o; o >>= 1) v += __shfl_down_sync(0xffffffffu, v, o);
            if (t == 0) atomicAdd(&g_S[b*KSLOT + h], v);
        }
    }
}

// ---------------- GRU gate GEMMs ----------------
__global__ void __launch_bounds__(256) gru_gemm(const float* __restrict__ bih, const float* __restrict__ bhh) {
    int blk = blockIdx.x;
    int b = blk / 24, gc = blk % 24;
    __shared__ float su[8*256], ss[8*256];
    int t = threadIdx.x;
    for (int i = t; i < 2048; i += 256) {
        int k = i >> 8;
        su[i] = g_U[b*2048 + i] / (g_S[b*8 + k] + EPS_ATTN);
        ss[i] = g_slots[b*2048 + i];
    }
    __syncthreads();
    int g = gc*32 + (t & 31);
    int k = t >> 5;
    float gi = bih[g], gh = bhh[g];
    const float* su_k = su + k*256;
    const float* ss_k = ss + k*256;
    #pragma unroll 4
    for (int d = 0; d < 256; d++) {
        gi += su_k[d] * g_WihT[d*768 + g];
        gh += ss_k[d] * g_WhhT[d*768 + g];
    }
    g_gi[((size_t)b*8 + k)*768 + g] = gi;
    g_gh[((size_t)b*8 + k)*768 + g] = gh;
}

// ---------------- GRU combine + LN + MLP ----------------
__global__ void __launch_bounds__(256) gru_mlp(const float* __restrict__ gm, const float* __restrict__ bm,
                                               const float* __restrict__ b1, const float* __restrict__ b2) {
    int bk = blockIdx.x;
    int t = threadIdx.x;
    const float* gi = g_gi + (size_t)bk*768;
    const float* gh = g_gh + (size_t)bk*768;
    float sl = g_slots[bk*256 + t];
    float r  = 1.f / (1.f + expf(-(gi[t]       + gh[t])));
    float z  = 1.f / (1.f + expf(-(gi[256 + t] + gh[256 + t])));
    float nn = tanhf(gi[512 + t] + r * gh[512 + t]);
    float h  = (1.f - z) * nn + z * sl;

    __shared__ float hn[256], ms[256];
    __shared__ float r1[8], r2[8];
    __shared__ float smv[2];
    float s = h, s2 = h*h;
    for (int o = 16; o; o >>= 1) { s += __shfl_down_sync(0xffffffffu, s, o); s2 += __shfl_down_sync(0xffffffffu, s2, o); }
    if ((t & 31) == 0) { r1[t>>5] = s; r2[t>>5] = s2; }
    __syncthreads();
    if (t == 0) {
        float ts = 0.f, ts2 = 0.f;
        #pragma unroll
        for (int w = 0; w < 8; w++) { ts += r1[w]; ts2 += r2[w]; }
        float m = ts * (1.f/256.f);
        float var = ts2 * (1.f/256.f) - m*m;
        smv[0] = m; smv[1] = rsqrtf(var + 1e-5f);
    }
    __syncthreads();
    hn[t] = (h - smv[0]) * smv[1] * gm[t] + bm[t];
    __syncthreads();
    float acc = b1[t];
    #pragma unroll 4
    for (int d = 0; d < 256; d++) acc += hn[d] * g_W1T[d*256 + t];
    ms[t] = fmaxf(acc, 0.f);
    __syncthreads();
    float o = h + b2[t];
    #pragma unroll 4
    for (int j = 0; j < 256; j++) o += ms[j] * g_W2T[j*256 + t];
    g_slots[bk*256 + t] = o;
}

// ---------------- final confidence blend ----------------
__global__ void __launch_bounds__(256) finalize(const float* __restrict__ prev, float* __restrict__ out_slots) {
    int bk = blockIdx.x;
    int t = threadIdx.x;
    float mean = g_S[bk] * (1.f / 4096.f);
    float mask = 1.f / (1.f + expf(-mean));
    out_slots[bk*256 + t] = g_slots[bk*256 + t] * mask + prev[bk*256 + t] * (1.f - mask);
}

// ---------------- launch ----------------
extern "C" void kernel_launch(void* const* d_in, const int* in_sizes, int n_in,
                              void* d_out, int out_size) {
    const float* features = (const float*)d_in[0];
    const float* prev     = (const float*)d_in[1];
    const float* gin      = (const float*)d_in[2];
    const float* bin      = (const float*)d_in[3];
    const float* gs       = (const float*)d_in[4];
    const float* bs       = (const float*)d_in[5];
    const float* gm       = (const float*)d_in[6];
    const float* bm       = (const float*)d_in[7];
    const float* Wq       = (const float*)d_in[8];
    const float* Wk       = (const float*)d_in[9];
    const float* Wv       = (const float*)d_in[10];
    const float* Wih      = (const float*)d_in[11];
    const float* Whh      = (const float*)d_in[12];
    const float* bih      = (const float*)d_in[13];
    const float* bhh      = (const float*)d_in[14];
    const float* W1       = (const float*)d_in[15];
    const float* b1       = (const float*)d_in[16];
    const float* W2       = (const float*)d_in[17];
    const float* b2       = (const float*)d_in[18];

    float* out_slots = (float*)d_out;
    float* out_attn  = out_slots + BB*KSLOT*DS;

    const size_t attn_smem = (size_t)ATTN_SMEM_FLOATS * sizeof(float);
    cudaFuncSetAttribute((const void*)attn_pass<false>, cudaFuncAttributeMaxDynamicSharedMemorySize, (int)attn_smem);
    cudaFuncSetAttribute((const void*)attn_pass<true>,  cudaFuncAttributeMaxDynamicSharedMemorySize, (int)attn_smem);
    cudaFuncSetAttribute((const void*)gemm_mma, cudaFuncAttributeMaxDynamicSharedMemorySize, GEMM_SMEM);

    // prep
    prep_wc<<<512, 256>>>(Wk, Wv, gin, bin);
    prep_wc_bf<<<(512*DF + 255)/256, 256>>>();
    prep_transpose<<<(768*256 + 255)/256, 256>>>(Wq, Wih, Whh, W1, W2, prev);

    // phase A: LN stats + tensor-core projection GEMM
    row_stats<<<NROWS/8, 256>>>(features);
    gemm_mma<<<dim3(512/256, NROWS/128), 256, GEMM_SMEM>>>(features);

    // phase B: 3 slot-attention iterations
    for (int it = 0; it < 3; it++) {
        slot_q<<<BB*KSLOT, 256>>>(gs, bs);
        attn_pass<false><<<dim3(BB, CHUNKS), 256, attn_smem>>>(nullptr);
        gru_gemm<<<BB*24, 256>>>(bih, bhh);
        gru_mlp<<<BB*KSLOT, 256>>>(gm, bm, b1, b2);
    }

    // final attention + blend
    slot_q<<<BB*KSLOT, 256>>>(gs, bs);
    attn_pass<true><<<dim3(BB, CHUNKS), 256, attn_smem>>>(out_attn);
    finalize<<<BB*KSLOT, 256>>>(prev, out_slots);

    (void)in_sizes; (void)n_in; (void)out_size;
}

// round 5
// speedup vs baseline: 1.6157x; 1.0028x over previous
#include <cuda_runtime.h>
#include <cuda_bf16.h>
#include <cstdint>
#include <math.h>

// ---------------- problem constants ----------------
#define BB 32
#define NN 4096
#define DF 768
#define DS 256
#define KSLOT 8
#define NROWS (BB*NN)        // 131072
#define SCALE_F 0.0625f      // 256^-0.5
#define EPS_ATTN 1e-8f

// ---------------- scratch (device globals; no allocations allowed) ----------------
static __device__ float g_mean[NROWS];
static __device__ float g_rstd[NROWS];
static __device__ __align__(16) __nv_bfloat16 g_Fhi[(size_t)NROWS*DF];  // 201 MB
static __device__ __align__(16) __nv_bfloat16 g_Flo[(size_t)NROWS*DF];  // 201 MB
static __device__ float g_k[(size_t)NROWS*DS];     // 134 MB
static __device__ float g_v[(size_t)NROWS*DS];     // 134 MB
static __device__ float g_Wc[512*DF];              // [Wk';Wv'] with g_in folded in
static __device__ __align__(16) __nv_bfloat16 g_WcHi[512*DF];
static __device__ __align__(16) __nv_bfloat16 g_WcLo[512*DF];
static __device__ float g_csum[512];
static __device__ float g_cbias[512];
static __device__ float g_WqT[DS*DS];
static __device__ float g_WihT[DS*768];
static __device__ float g_WhhT[DS*768];
static __device__ float g_W1T[DS*DS];
static __device__ float g_W2T[DS*DS];
static __device__ float g_q[BB*KSLOT*DS];
static __device__ float g_slots[BB*KSLOT*DS];
static __device__ float g_U[BB*KSLOT*DS];
static __device__ float g_S[BB*KSLOT];
static __device__ float g_gi[BB*KSLOT*768];
static __device__ float g_gh[BB*KSLOT*768];

// ---------------- helpers ----------------
__device__ __forceinline__ uint32_t s2u(const void* p) {
    uint32_t r;
    asm("{ .reg .u64 t; cvta.to.shared.u64 t, %1; cvt.u32.u64 %0, t; }" : "=r"(r) : "l"(p));
    return r;
}
__device__ __forceinline__ uint32_t pack_bf2(float x, float y) {
    __nv_bfloat16 hx = __float2bfloat16_rn(x);
    __nv_bfloat16 hy = __float2bfloat16_rn(y);
    return (uint32_t)__bfloat16_as_ushort(hx) | ((uint32_t)__bfloat16_as_ushort(hy) << 16);
}
__device__ __forceinline__ void cpa16(uint32_t dst, const void* src) {
    asm volatile("cp.async.cg.shared.global [%0], [%1], 16;" :: "r"(dst), "l"(src));
}
#define CP_COMMIT() asm volatile("cp.async.commit_group;" ::: "memory")
#define CP_WAIT1()  asm volatile("cp.async.wait_group 1;" ::: "memory")
#define CP_WAIT0()  asm volatile("cp.async.wait_group 0;" ::: "memory")

#define MMA16816(C, A, B) \
    asm volatile("mma.sync.aligned.m16n8k16.row.col.f32.bf16.bf16.f32 " \
        "{%0,%1,%2,%3}, {%4,%5,%6,%7}, {%8,%9}, {%0,%1,%2,%3};" \
        : "+f"((C)[0]), "+f"((C)[1]), "+f"((C)[2]), "+f"((C)[3]) \
        : "r"((A)[0]), "r"((A)[1]), "r"((A)[2]), "r"((A)[3]), "r"((B)[0]), "r"((B)[1]))

// ---------------- prep: combined, g-scaled projection weights ----------------
__global__ void __launch_bounds__(256) prep_wc(const float* __restrict__ Wk,
                                               const float* __restrict__ Wv,
                                               const float* __restrict__ gin,
                                               const float* __restrict__ bin) {
    int j = blockIdx.x;             // 0..511  (0..255 -> k, 256..511 -> v)
    const float* W = (j < 256) ? (Wk + (size_t)j*DF) : (Wv + (size_t)(j-256)*DF);
    int t = threadIdx.x;
    float s = 0.f, bsum = 0.f;
    for (int f = t; f < DF; f += 256) {
        float w  = W[f];
        float wc = w * gin[f];
        g_Wc[(size_t)j*DF + f] = wc;
        s += wc; bsum += w * bin[f];
    }
    __shared__ float r1[8], r2[8];
    for (int o = 16; o; o >>= 1) { s += __shfl_down_sync(0xffffffffu, s, o); bsum += __shfl_down_sync(0xffffffffu, bsum, o); }
    if ((t & 31) == 0) { r1[t>>5] = s; r2[t>>5] = bsum; }
    __syncthreads();
    if (t == 0) {
        float ts = 0.f, tb = 0.f;
        #pragma unroll
        for (int w = 0; w < 8; w++) { ts += r1[w]; tb += r2[w]; }
        g_csum[j] = ts; g_cbias[j] = tb;
    }
}

// ---------------- prep: bf16 hi/lo split of Wc ----------------
__global__ void __launch_bounds__(256) prep_wc_bf(void) {
    int i = blockIdx.x * 256 + threadIdx.x;
    if (i < 512*DF) {
        float x = g_Wc[i];
        __nv_bfloat16 h = __float2bfloat16_rn(x);
        float lo = x - __bfloat162float(h);
        g_WcHi[i] = h;
        g_WcLo[i] = __float2bfloat16_rn(lo);
    }
}

// ---------------- prep: transposed small weights + copy slots ----------------
__global__ void prep_transpose(const float* __restrict__ Wq,
                               const float* __restrict__ Wih,
                               const float* __restrict__ Whh,
                               const float* __restrict__ W1,
                               const float* __restrict__ W2,
                               const float* __restrict__ prev) {
    int i = blockIdx.x * blockDim.x + threadIdx.x;
    if (i < 768*256) {
        int g = i / 256, d = i % 256;
        g_WihT[d*768 + g] = Wih[i];
        g_WhhT[d*768 + g] = Whh[i];
    }
    if (i < 256*256) {
        int r = i / 256, c = i % 256;
        g_WqT[c*256 + r] = Wq[i];
        g_W1T[c*256 + r] = W1[i];
        g_W2T[c*256 + r] = W2[i];
    }
    if (i < BB*KSLOT*DS) g_slots[i] = prev[i];
}

// ---------------- LN stats + bf16 hi/lo split of F (one streaming pass) ----------------
__global__ void __launch_bounds__(256) row_stats_split(const float* __restrict__ F) {
    int w = threadIdx.x >> 5, l = threadIdx.x & 31;
    int row = blockIdx.x * 8 + w;
    const float4* x = (const float4*)(F + (size_t)row * DF);
    float4 a[6];
    float s = 0.f, s2 = 0.f;
    #pragma unroll
    for (int j = 0; j < 6; j++) {
        a[j] = x[l + 32*j];
        s  += a[j].x + a[j].y + a[j].z + a[j].w;
        s2 += a[j].x*a[j].x + a[j].y*a[j].y + a[j].z*a[j].z + a[j].w*a[j].w;
    }
    // write hi/lo split while stats reduce
    uint2* hdst = (uint2*)(g_Fhi + (size_t)row * DF);
    uint2* ldst = (uint2*)(g_Flo + (size_t)row * DF);
    #pragma unroll
    for (int j = 0; j < 6; j++) {
        float4 v = a[j];
        uint2 h = make_uint2(pack_bf2(v.x, v.y), pack_bf2(v.z, v.w));
        __nv_bfloat16 hx = __float2bfloat16_rn(v.x), hy = __float2bfloat16_rn(v.y);
        __nv_bfloat16 hz = __float2bfloat16_rn(v.z), hw = __float2bfloat16_rn(v.w);
        uint2 lo = make_uint2(
            pack_bf2(v.x - __bfloat162float(hx), v.y - __bfloat162float(hy)),
            pack_bf2(v.z - __bfloat162float(hz), v.w - __bfloat162float(hw)));
        hdst[l + 32*j] = h;
        ldst[l + 32*j] = lo;
    }
    for (int o = 16; o; o >>= 1) {
        s  += __shfl_down_sync(0xffffffffu, s, o);
        s2 += __shfl_down_sync(0xffffffffu, s2, o);
    }
    if (l == 0) {
        float m   = s * (1.f/768.f);
        float var = s2 * (1.f/768.f) - m*m;
        g_mean[row] = m;
        g_rstd[row] = rsqrtf(var + 1e-5f);
    }
}

// ---------------- tensor-core GEMM (pure bf16, cp.async staged, hi/lo compensated) ----------------
// C[131072 x 512] = F[131072 x 768] @ Wc^T, fp32 accum.
// CTA 128x256, BK=32, 8 warps (2x4 grid, warp tile 64x64), 2-stage cp.async pipeline.
#define PADB 80                      // bytes per smem row (40 bf16): odd 16B multiple -> conflict-free
#define TILE_A (128*PADB)            // 10240
#define TILE_Bb (256*PADB)           // 20480
#define STAGE_BYTES (2*TILE_A + 2*TILE_Bb)  // 61440: Ah, Al, Bh, Bl
#define GEMM_SMEM (2*STAGE_BYTES)    // 122880
#define NCHUNK (DF/32)               // 24

__global__ void __launch_bounds__(256) gemm_mma(void) {
    extern __shared__ __align__(16) char smd[];
    __shared__ float s_cs[256], s_cb[256];

    const int tid = threadIdx.x;
    const int wid = tid >> 5, lane = tid & 31;
    const int wm = wid & 1, wn = wid >> 1;      // warp grid 2 x 4, tile 64x64
    const int bn = blockIdx.x * 256;
    const int bm = blockIdx.y * 128;

    s_cs[tid] = g_csum[bn + tid];
    s_cb[tid] = g_cbias[bn + tid];

    const uint32_t smem_u = s2u(smd);
    const int arow = tid >> 2;           // 0..63 (A rows, step 64) / also B rows step 64
    const int aq   = tid & 3;            // 16B quarter within 64B row-chunk

    // stage a chunk via cp.async (A: 128 rows, B: 256 rows; 64B per row per array)
    auto stage = [&](int buf, int c) {
        const int kb = c * 32;
        uint32_t sb = smem_u + buf * STAGE_BYTES;
        const __nv_bfloat16* fh = g_Fhi + (size_t)(bm + arow) * DF + kb + aq * 8;
        const __nv_bfloat16* fl = g_Flo + (size_t)(bm + arow) * DF + kb + aq * 8;
        uint32_t da = sb + arow * PADB + aq * 16;
        cpa16(da,          fh);
        cpa16(da + TILE_A, fl);
        cpa16(da + (size_t)64*DF*0 + 64*PADB,          fh + (size_t)64*DF);   // rows 64..127
        cpa16(da + TILE_A + 64*PADB,                   fl + (size_t)64*DF);
        const __nv_bfloat16* bh = g_WcHi + (size_t)(bn + arow) * DF + kb + aq * 8;
        const __nv_bfloat16* bl = g_WcLo + (size_t)(bn + arow) * DF + kb + aq * 8;
        uint32_t db = sb + 2*TILE_A + arow * PADB + aq * 16;
        #pragma unroll
        for (int j = 0; j < 4; j++) {
            cpa16(db + j*64*PADB,           bh + (size_t)j*64*DF);
            cpa16(db + TILE_Bb + j*64*PADB, bl + (size_t)j*64*DF);
        }
    };

    float acc[4][8][4];
    #pragma unroll
    for (int mi = 0; mi < 4; mi++)
        #pragma unroll
        for (int ni = 0; ni < 8; ni++)
            #pragma unroll
            for (int e = 0; e < 4; e++) acc[mi][ni][e] = 0.f;

    stage(0, 0); CP_COMMIT();
    stage(1, 1); CP_COMMIT();

    // fragment lane addressing
    const int fr = lane >> 2;            // 0..7
    const int fk = (lane & 3) * 4;       // byte offset of k-pair

    #pragma unroll 1
    for (int c = 0; c < NCHUNK; c++) {
        const int p = c & 1;
        if (c == NCHUNK - 1) CP_WAIT0(); else CP_WAIT1();
        __syncthreads();

        const char* Ah = smd + p * STAGE_BYTES;
        const char* Al = Ah + TILE_A;
        const char* Bh = Ah + 2*TILE_A;
        const char* Bl = Bh + TILE_Bb;

        #pragma unroll
        for (int ks = 0; ks < 2; ks++) {
            uint32_t af[4][4], bfr[8][2];
            // Ahi frags
            #pragma unroll
            for (int mi = 0; mi < 4; mi++) {
                uint32_t o = (wm*64 + mi*16 + fr) * PADB + ks*32 + fk;
                af[mi][0] = *(const uint32_t*)(Ah + o);
                af[mi][1] = *(const uint32_t*)(Ah + o + 8*PADB);
                af[mi][2] = *(const uint32_t*)(Ah + o + 16);
                af[mi][3] = *(const uint32_t*)(Ah + o + 8*PADB + 16);
            }
            // Bhi frags
            #pragma unroll
            for (int ni = 0; ni < 8; ni++) {
                uint32_t o = (wn*64 + ni*8 + fr) * PADB + ks*32 + fk;
                bfr[ni][0] = *(const uint32_t*)(Bh + o);
                bfr[ni][1] = *(const uint32_t*)(Bh + o + 16);
            }
            #pragma unroll
            for (int mi = 0; mi < 4; mi++)
                #pragma unroll
                for (int ni = 0; ni < 8; ni++)
                    MMA16816(acc[mi][ni], af[mi], bfr[ni]);

            // Ahi x Blo
            #pragma unroll
            for (int ni = 0; ni < 8; ni++) {
                uint32_t o = (wn*64 + ni*8 + fr) * PADB + ks*32 + fk;
                bfr[ni][0] = *(const uint32_t*)(Bl + o);
                bfr[ni][1] = *(const uint32_t*)(Bl + o + 16);
            }
            #pragma unroll
            for (int mi = 0; mi < 4; mi++)
                #pragma unroll
                for (int ni = 0; ni < 8; ni++)
                    MMA16816(acc[mi][ni], af[mi], bfr[ni]);

            // Alo x Bhi
            #pragma unroll
            for (int mi = 0; mi < 4; mi++) {
                uint32_t o = (wm*64 + mi*16 + fr) * PADB + ks*32 + fk;
                af[mi][0] = *(const uint32_t*)(Al + o);
                af[mi][1] = *(const uint32_t*)(Al + o + 8*PADB);
                af[mi][2] = *(const uint32_t*)(Al + o + 16);
                af[mi][3] = *(const uint32_t*)(Al + o + 8*PADB + 16);
            }
            #pragma unroll
            for (int ni = 0; ni < 8; ni++) {
                uint32_t o = (wn*64 + ni*8 + fr) * PADB + ks*32 + fk;
                bfr[ni][0] = *(const uint32_t*)(Bh + o);
                bfr[ni][1] = *(const uint32_t*)(Bh + o + 16);
            }
            #pragma unroll
            for (int mi = 0; mi < 4; mi++)
                #pragma unroll
                for (int ni = 0; ni < 8; ni++)
                    MMA16816(acc[mi][ni], af[mi], bfr[ni]);
        }

        __syncthreads();
        if (c + 2 < NCHUNK) stage(p, c + 2);
        CP_COMMIT();
    }

    // ---- epilogue: LN fold + split to k/v ----
    #pragma unroll
    for (int mi = 0; mi < 4; mi++) {
        int r1 = bm + wm*64 + mi*16 + fr;
        int r2 = r1 + 8;
        float rm1 = g_mean[r1], rs1 = g_rstd[r1];
        float rm2 = g_mean[r2], rs2 = g_rstd[r2];
        #pragma unroll
        for (int ni = 0; ni < 8; ni++) {
            int cl = wn*64 + ni*8 + (lane & 3)*2;   // local col in [0,256)
            int colg = bn + cl;
            float cs0 = s_cs[cl], cs1 = s_cs[cl+1];
            float cb0 = s_cb[cl], cb1 = s_cb[cl+1];
            float* d1;
            float* d2;
            if (colg < 256) {
                d1 = g_k + (size_t)r1*DS + colg;
                d2 = g_k + (size_t)r2*DS + colg;
            } else {
                d1 = g_v + (size_t)r1*DS + (colg - 256);
                d2 = g_v + (size_t)r2*DS + (colg - 256);
            }
            float2 o1, o2;
            o1.x = rs1*(acc[mi][ni][0] - rm1*cs0) + cb0;
            o1.y = rs1*(acc[mi][ni][1] - rm1*cs1) + cb1;
            o2.x = rs2*(acc[mi][ni][2] - rm2*cs0) + cb0;
            o2.y = rs2*(acc[mi][ni][3] - rm2*cs1) + cb1;
            *(float2*)d1 = o1;
            *(float2*)d2 = o2;
        }
    }
}

// ---------------- per-slot q = LN(slots) @ Wq^T (also zeroes U/S accumulators) ----------------
__global__ void __launch_bounds__(256) slot_q(const float* __restrict__ gs, const float* __restrict__ bs) {
    int row = blockIdx.x;
    int t = threadIdx.x;
    __shared__ float sn[256];
    __shared__ float r1[8], r2[8];
    __shared__ float smv[2];
    g_U[row*256 + t] = 0.f;
    if (t == 0) g_S[row] = 0.f;
    float x = g_slots[row*256 + t];
    float s = x, s2 = x*x;
    for (int o = 16; o; o >>= 1) { s += __shfl_down_sync(0xffffffffu, s, o); s2 += __shfl_down_sync(0xffffffffu, s2, o); }
    if ((t & 31) == 0) { r1[t>>5] = s; r2[t>>5] = s2; }
    __syncthreads();
    if (t == 0) {
        float ts = 0.f, ts2 = 0.f;
        #pragma unroll
        for (int w = 0; w < 8; w++) { ts += r1[w]; ts2 += r2[w]; }
        float m = ts * (1.f/256.f);
        float var = ts2 * (1.f/256.f) - m*m;
        smv[0] = m; smv[1] = rsqrtf(var + 1e-5f);
    }
    __syncthreads();
    sn[t] = (x - smv[0]) * smv[1] * gs[t] + bs[t];
    __syncthreads();
    float acc = 0.f;
    #pragma unroll 4
    for (int d = 0; d < 256; d++) acc += sn[d] * g_WqT[d*256 + t];
    g_q[row*256 + t] = acc;
}

// ---------------- fused attention sweep ----------------
#define ATILE 32
#define KPAD 260
#define CHUNKS 32
#define ATTN_SMEM_FLOATS (8*256 + 2*ATILE*KPAD + 2*8*36)

template <bool FINAL>
__global__ void __launch_bounds__(256) attn_pass(float* __restrict__ out_attn) {
    extern __shared__ float sm[];
    float* qs = sm;
    float* kt = qs + 8*256;
    float* vt = kt + ATILE*KPAD;
    float* Ls = vt + ATILE*KPAD;
    float* ps = Ls + 8*36;

    int b  = blockIdx.x;
    int ch = blockIdx.y;
    int t  = threadIdx.x;

    for (int i = t; i < 8*256; i += 256) qs[i] = g_q[b*2048 + i] * SCALE_F;

    const int n0 = ch * (NN / CHUNKS);
    float regU[8], regS[8];
    #pragma unroll
    for (int h = 0; h < 8; h++) { regU[h] = 0.f; regS[h] = 0.f; }

    const int hq = t >> 5;
    const int nl = t & 31;

    #pragma unroll 1
    for (int tile = 0; tile < (NN/CHUNKS)/ATILE; tile++) {
        int nbase = n0 + tile * ATILE;
        __syncthreads();
        const float* kg = g_k + ((size_t)b*NN + nbase) * DS;
        const float* vg = g_v + ((size_t)b*NN + nbase) * DS;
        for (int i = t; i < ATILE*64; i += 256) {
            int n = i >> 6; int d4 = (i & 63) << 2;
            *(float4*)(kt + n*KPAD + d4) = *(const float4*)(kg + n*DS + d4);
            if (!FINAL)
                *(float4*)(vt + n*KPAD + d4) = *(const float4*)(vg + n*DS + d4);
        }
        __syncthreads();

        {
            float acc = 0.f;
            const float* qrow = qs + hq*256;
            const float* krow = kt + nl*KPAD;
            #pragma unroll 8
            for (int d = 0; d < 256; d += 4) {
                float4 qv = *(const float4*)(qrow + d);
                float4 kv = *(const float4*)(krow + d);
                acc += qv.x*kv.x + qv.y*kv.y + qv.z*kv.z + qv.w*kv.w;
            }
            Ls[hq*36 + nl] = acc;
        }
        __syncthreads();

        if (t < 32) {
            float l[8], m = -1e30f;
            #pragma unroll
            for (int h = 0; h < 8; h++) { l[h] = Ls[h*36 + t]; m = fmaxf(m, l[h]); }
            float ssum = 0.f;
            #pragma unroll
            for (int h = 0; h < 8; h++) { l[h] = expf(l[h] - m); ssum += l[h]; }
            float inv = 1.f / ssum;
            #pragma unroll
            for (int h = 0; h < 8; h++) {
                float p = l[h] * inv;
                ps[h*36 + t] = p;
                regS[h] += p;
                if (FINAL)
                    out_attn[((size_t)b*KSLOT + h)*NN + nbase + t] = p;
            }
        }
        __syncthreads();

        if (!FINAL) {
            #pragma unroll 4
            for (int n = 0; n < ATILE; n++) {
                float vv = vt[n*KPAD + t];
                #pragma unroll
                for (int h = 0; h < 8; h++) regU[h] += ps[h*36 + n] * vv;
            }
        }
    }

    if (!FINAL) {
        #pragma unroll
        for (int h = 0; h < 8; h++)
            atomicAdd(&g_U[((size_t)b*KSLOT + h)*DS + t], regU[h]);
    }
    if (t < 32) {
        #pragma unroll
        for (int h = 0; h < 8; h++) {
            float v = regS[h];
            for (int o = 16; o; o >>= 1) v += __shfl_down_sync(0xffffffffu, v, o);
            if (t == 0) atomicAdd(&g_S[b*KSLOT + h], v);
        }
    }
}

// ---------------- GRU gate GEMMs ----------------
__global__ void __launch_bounds__(256) gru_gemm(const float* __restrict__ bih, const float* __restrict__ bhh) {
    int blk = blockIdx.x;
    int b = blk / 24, gc = blk % 24;
    __shared__ float su[8*256], ss[8*256];
    int t = threadIdx.x;
    for (int i = t; i < 2048; i += 256) {
        int k = i >> 8;
        su[i] = g_U[b*2048 + i] / (g_S[b*8 + k] + EPS_ATTN);
        ss[i] = g_slots[b*2048 + i];
    }
    __syncthreads();
    int g = gc*32 + (t & 31);
    int k = t >> 5;
    float gi = bih[g], gh = bhh[g];
    const float* su_k = su + k*256;
    const float* ss_k = ss + k*256;
    #pragma unroll 4
    for (int d = 0; d < 256; d++) {
        gi += su_k[d] * g_WihT[d*768 + g];
        gh += ss_k[d] * g_WhhT[d*768 + g];
    }
    g_gi[((size_t)b*8 + k)*768 + g] = gi;
    g_gh[((size_t)b*8 + k)*768 + g] = gh;
}

// ---------------- GRU combine + LN + MLP ----------------
__global__ void __launch_bounds__(256) gru_mlp(const float* __restrict__ gm, const float* __restrict__ bm,
                                               const float* __restrict__ b1, const float* __restrict__ b2) {
    int bk = blockIdx.x;
    int t = threadIdx.x;
    const float* gi = g_gi + (size_t)bk*768;
    const float* gh = g_gh + (size_t)bk*768;
    float sl = g_slots[bk*256 + t];
    float r  = 1.f / (1.f + expf(-(gi[t]       + gh[t])));
    float z  = 1.f / (1.f + expf(-(gi[256 + t] + gh[256 + t])));
    float nn = tanhf(gi[512 + t] + r * gh[512 + t]);
    float h  = (1.f - z) * nn + z * sl;

    __shared__ float hn[256], ms[256];
    __shared__ float r1[8], r2[8];
    __shared__ float smv[2];
    float s = h, s2 = h*h;
    for (int o = 16; o; o >>= 1) { s += __shfl_down_sync(0xffffffffu, s, o); s2 += __shfl_down_sync(0xffffffffu, s2, o); }
    if ((t & 31) == 0) { r1[t>>5] = s; r2[t>>5] = s2; }
    __syncthreads();
    if (t == 0) {
        float ts = 0.f, ts2 = 0.f;
        #pragma unroll
        for (int w = 0; w < 8; w++) { ts += r1[w]; ts2 += r2[w]; }
        float m = ts * (1.f/256.f);
        float var = ts2 * (1.f/256.f) - m*m;
        smv[0] = m; smv[1] = rsqrtf(var + 1e-5f);
    }
    __syncthreads();
    hn[t] = (h - smv[0]) * smv[1] * gm[t] + bm[t];
    __syncthreads();
    float acc = b1[t];
    #pragma unroll 4
    for (int d = 0; d < 256; d++) acc += hn[d] * g_W1T[d*256 + t];
    ms[t] = fmaxf(acc, 0.f);
    __syncthreads();
    float o = h + b2[t];
    #pragma unroll 4
    for (int j = 0; j < 256; j++) o += ms[j] * g_W2T[j*256 + t];
    g_slots[bk*256 + t] = o;
}

// ---------------- final confidence blend ----------------
__global__ void __launch_bounds__(256) finalize(const float* __restrict__ prev, float* __restrict__ out_slots) {
    int bk = blockIdx.x;
    int t = threadIdx.x;
    float mean = g_S[bk] * (1.f / 4096.f);
    float mask = 1.f / (1.f + expf(-mean));
    out_slots[bk*256 + t] = g_slots[bk*256 + t] * mask + prev[bk*256 + t] * (1.f - mask);
}

// ---------------- launch ----------------
extern "C" void kernel_launch(void* const* d_in, const int* in_sizes, int n_in,
                              void* d_out, int out_size) {
    const float* features = (const float*)d_in[0];
    const float* prev     = (const float*)d_in[1];
    const float* gin      = (const float*)d_in[2];
    const float* bin      = (const float*)d_in[3];
    const float* gs       = (const float*)d_in[4];
    const float* bs       = (const float*)d_in[5];
    const float* gm       = (const float*)d_in[6];
    const float* bm       = (const float*)d_in[7];
    const float* Wq       = (const float*)d_in[8];
    const float* Wk       = (const float*)d_in[9];
    const float* Wv       = (const float*)d_in[10];
    const float* Wih      = (const float*)d_in[11];
    const float* Whh      = (const float*)d_in[12];
    const float* bih      = (const float*)d_in[13];
    const float* bhh      = (const float*)d_in[14];
    const float* W1       = (const float*)d_in[15];
    const float* b1       = (const float*)d_in[16];
    const float* W2       = (const float*)d_in[17];
    const float* b2       = (const float*)d_in[18];

    float* out_slots = (float*)d_out;
    float* out_attn  = out_slots + BB*KSLOT*DS;

    const size_t attn_smem = (size_t)ATTN_SMEM_FLOATS * sizeof(float);
    cudaFuncSetAttribute((const void*)attn_pass<false>, cudaFuncAttributeMaxDynamicSharedMemorySize, (int)attn_smem);
    cudaFuncSetAttribute((const void*)attn_pass<true>,  cudaFuncAttributeMaxDynamicSharedMemorySize, (int)attn_smem);
    cudaFuncSetAttribute((const void*)gemm_mma, cudaFuncAttributeMaxDynamicSharedMemorySize, GEMM_SMEM);

    // prep
    prep_wc<<<512, 256>>>(Wk, Wv, gin, bin);
    prep_wc_bf<<<(512*DF + 255)/256, 256>>>();
    prep_transpose<<<(768*256 + 255)/256, 256>>>(Wq, Wih, Whh, W1, W2, prev);

    // phase A: fused LN stats + hi/lo split, then pure-bf16 tensor GEMM
    row_stats_split<<<NROWS/8, 256>>>(features);
    gemm_mma<<<dim3(512/256, NROWS/128), 256, GEMM_SMEM>>>();

    // phase B: 3 slot-attention iterations
    for (int it = 0; it < 3; it++) {
        slot_q<<<BB*KSLOT, 256>>>(gs, bs);
        attn_pass<false><<<dim3(BB, CHUNKS), 256, attn_smem>>>(nullptr);
        gru_gemm<<<BB*24, 256>>>(bih, bhh);
        gru_mlp<<<BB*KSLOT, 256>>>(gm, bm, b1, b2);
    }

    // final attention + blend
    slot_q<<<BB*KSLOT, 256>>>(gs, bs);
    attn_pass<true><<<dim3(BB, CHUNKS), 256, attn_smem>>>(out_attn);
    finalize<<<BB*KSLOT, 256>>>(prev, out_slots);

    (void)in_sizes; (void)n_in; (void)out_size;
}

// round 6
// speedup vs baseline: 2.0232x; 1.2522x over previous
#include <cuda_runtime.h>
#include <cuda_fp16.h>
#include <cstdint>
#include <math.h>

// ---------------- problem constants ----------------
#define BB 32
#define NN 4096
#define DF 768
#define DS 256
#define KSLOT 8
#define NROWS (BB*NN)        // 131072
#define SCALE_F 0.0625f      // 256^-0.5
#define EPS_ATTN 1e-8f
#define INV64 0.015625f

// ---------------- scratch (device globals; no allocations allowed) ----------------
static __device__ float g_mean[NROWS];
static __device__ float g_rstd[NROWS];
static __device__ __align__(16) __half g_Fh[(size_t)NROWS*DF];          // 201 MB
static __device__ __align__(16) __half g_k[(size_t)NROWS*DS];           // 67 MB
static __device__ __align__(16) __half g_v[(size_t)NROWS*DS];           // 67 MB
static __device__ float g_Wc[512*DF];              // [Wk';Wv'] with g_in folded in
static __device__ __align__(16) __half g_WcHi[512*DF];                  // 64*Wc hi
static __device__ __align__(16) __half g_WcLo[512*DF];                  // 64*Wc lo
static __device__ float g_csum[512];
static __device__ float g_cbias[512];
static __device__ float g_WqT[DS*DS];
static __device__ float g_WihT[DS*768];
static __device__ float g_WhhT[DS*768];
static __device__ float g_W1T[DS*DS];
static __device__ float g_W2T[DS*DS];
static __device__ float g_q[BB*KSLOT*DS];
static __device__ float g_slots[BB*KSLOT*DS];
static __device__ float g_U[BB*KSLOT*DS];
static __device__ float g_S[BB*KSLOT];
static __device__ float g_gi[BB*KSLOT*768];
static __device__ float g_gh[BB*KSLOT*768];

// ---------------- helpers ----------------
__device__ __forceinline__ uint32_t s2u(const void* p) {
    uint32_t r;
    asm("{ .reg .u64 t; cvta.to.shared.u64 t, %1; cvt.u32.u64 %0, t; }" : "=r"(r) : "l"(p));
    return r;
}
__device__ __forceinline__ void cpa16(uint32_t dst, const void* src) {
    asm volatile("cp.async.cg.shared.global [%0], [%1], 16;" :: "r"(dst), "l"(src));
}
#define CP_COMMIT() asm volatile("cp.async.commit_group;" ::: "memory")
#define CP_WAIT1()  asm volatile("cp.async.wait_group 1;" ::: "memory")
#define CP_WAIT0()  asm volatile("cp.async.wait_group 0;" ::: "memory")

#define MMA16816(C, A, B) \
    asm volatile("mma.sync.aligned.m16n8k16.row.col.f32.f16.f16.f32 " \
        "{%0,%1,%2,%3}, {%4,%5,%6,%7}, {%8,%9}, {%0,%1,%2,%3};" \
        : "+f"((C)[0]), "+f"((C)[1]), "+f"((C)[2]), "+f"((C)[3]) \
        : "r"((A)[0]), "r"((A)[1]), "r"((A)[2]), "r"((A)[3]), "r"((B)[0]), "r"((B)[1]))

// ---------------- prep: combined, g-scaled projection weights ----------------
__global__ void __launch_bounds__(256) prep_wc(const float* __restrict__ Wk,
                                               const float* __restrict__ Wv,
                                               const float* __restrict__ gin,
                                               const float* __restrict__ bin) {
    int j = blockIdx.x;             // 0..511  (0..255 -> k, 256..511 -> v)
    const float* W = (j < 256) ? (Wk + (size_t)j*DF) : (Wv + (size_t)(j-256)*DF);
    int t = threadIdx.x;
    float s = 0.f, bsum = 0.f;
    for (int f = t; f < DF; f += 256) {
        float w  = W[f];
        float wc = w * gin[f];
        g_Wc[(size_t)j*DF + f] = wc;
        s += wc; bsum += w * bin[f];
    }
    __shared__ float r1[8], r2[8];
    for (int o = 16; o; o >>= 1) { s += __shfl_down_sync(0xffffffffu, s, o); bsum += __shfl_down_sync(0xffffffffu, bsum, o); }
    if ((t & 31) == 0) { r1[t>>5] = s; r2[t>>5] = bsum; }
    __syncthreads();
    if (t == 0) {
        float ts = 0.f, tb = 0.f;
        #pragma unroll
        for (int w = 0; w < 8; w++) { ts += r1[w]; tb += r2[w]; }
        g_csum[j] = ts; g_cbias[j] = tb;
    }
}

// ---------------- prep: fp16 hi/lo split of 64*Wc ----------------
__global__ void __launch_bounds__(256) prep_wc_split(void) {
    int i = blockIdx.x * 256 + threadIdx.x;
    if (i < 512*DF) {
        float x = g_Wc[i] * 64.f;
        __half h = __float2half_rn(x);
        g_WcHi[i] = h;
        g_WcLo[i] = __float2half_rn(x - __half2float(h));
    }
}

// ---------------- prep: transposed small weights + copy slots ----------------
__global__ void prep_transpose(const float* __restrict__ Wq,
                               const float* __restrict__ Wih,
                               const float* __restrict__ Whh,
                               const float* __restrict__ W1,
                               const float* __restrict__ W2,
                               const float* __restrict__ prev) {
    int i = blockIdx.x * blockDim.x + threadIdx.x;
    if (i < 768*256) {
        int g = i / 256, d = i % 256;
        g_WihT[d*768 + g] = Wih[i];
        g_WhhT[d*768 + g] = Whh[i];
    }
    if (i < 256*256) {
        int r = i / 256, c = i % 256;
        g_WqT[c*256 + r] = Wq[i];
        g_W1T[c*256 + r] = W1[i];
        g_W2T[c*256 + r] = W2[i];
    }
    if (i < BB*KSLOT*DS) g_slots[i] = prev[i];
}

// ---------------- LN stats + fp16 cast of F (one streaming pass) ----------------
__global__ void __launch_bounds__(256) row_stats_split(const float* __restrict__ F) {
    int w = threadIdx.x >> 5, l = threadIdx.x & 31;
    int row = blockIdx.x * 8 + w;
    const float4* x = (const float4*)(F + (size_t)row * DF);
    float4 a[6];
    float s = 0.f, s2 = 0.f;
    #pragma unroll
    for (int j = 0; j < 6; j++) {
        a[j] = x[l + 32*j];
        s  += a[j].x + a[j].y + a[j].z + a[j].w;
        s2 += a[j].x*a[j].x + a[j].y*a[j].y + a[j].z*a[j].z + a[j].w*a[j].w;
    }
    uint2* hdst = (uint2*)(g_Fh + (size_t)row * DF);
    #pragma unroll
    for (int j = 0; j < 6; j++) {
        float4 v = a[j];
        __half2 h0 = __floats2half2_rn(v.x, v.y);
        __half2 h1 = __floats2half2_rn(v.z, v.w);
        hdst[l + 32*j] = make_uint2(*(uint32_t*)&h0, *(uint32_t*)&h1);
    }
    for (int o = 16; o; o >>= 1) {
        s  += __shfl_down_sync(0xffffffffu, s, o);
        s2 += __shfl_down_sync(0xffffffffu, s2, o);
    }
    if (l == 0) {
        float m   = s * (1.f/768.f);
        float var = s2 * (1.f/768.f) - m*m;
        g_mean[row] = m;
        g_rstd[row] = rsqrtf(var + 1e-5f);
    }
}

// ---------------- tensor-core GEMM (fp16, cp.async staged) ----------------
// C[131072 x 512] = F @ Wc^T, fp32 accum. A single fp16; B = fp16 hi/lo of 64*Wc.
// blockIdx.x==0 -> k cols (2-pass: A*Bhi + A*Blo); ==1 -> v cols (1-pass A*Bhi).
// CTA 128x256, BK=32, 8 warps (2x4 grid, warp tile 64x64), 2-stage cp.async pipeline.
#define PADB 80                      // bytes per smem row (32 halfs data + pad); odd 16B mult
#define TILE_A (128*PADB)            // 10240
#define TILE_Bb (256*PADB)           // 20480
#define STAGE_BYTES (TILE_A + 2*TILE_Bb)    // 51200: A, Bh, Bl
#define GEMM_SMEM (2*STAGE_BYTES)    // 102400
#define NCHUNK (DF/32)               // 24

__global__ void __launch_bounds__(256) gemm_mma(void) {
    extern __shared__ __align__(16) char smd[];
    __shared__ float s_cs[256], s_cb[256];

    const int tid = threadIdx.x;
    const int wid = tid >> 5, lane = tid & 31;
    const int wm = wid & 1, wn = wid >> 1;      // warp grid 2 x 4, tile 64x64
    const int bn = blockIdx.x * 256;
    const int bm = blockIdx.y * 128;
    const bool isK = (blockIdx.x == 0);

    s_cs[tid] = g_csum[bn + tid];
    s_cb[tid] = g_cbias[bn + tid];

    const uint32_t smem_u = s2u(smd);
    const int arow = tid >> 2;           // 0..63
    const int aq   = tid & 3;            // 16B quarter within 64B row-chunk

    auto stage = [&](int buf, int c) {
        const int kb = c * 32;
        uint32_t sb = smem_u + buf * STAGE_BYTES;
        const __half* fa = g_Fh + (size_t)(bm + arow) * DF + kb + aq * 8;
        uint32_t da = sb + arow * PADB + aq * 16;
        cpa16(da,            fa);
        cpa16(da + 64*PADB,  fa + (size_t)64*DF);
        const __half* bh = g_WcHi + (size_t)(bn + arow) * DF + kb + aq * 8;
        uint32_t db = sb + TILE_A + arow * PADB + aq * 16;
        #pragma unroll
        for (int j = 0; j < 4; j++)
            cpa16(db + j*64*PADB, bh + (size_t)j*64*DF);
        if (isK) {
            const __half* bl = g_WcLo + (size_t)(bn + arow) * DF + kb + aq * 8;
            uint32_t dl = db + TILE_Bb;
            #pragma unroll
            for (int j = 0; j < 4; j++)
                cpa16(dl + j*64*PADB, bl + (size_t)j*64*DF);
        }
    };

    float acc[4][8][4];
    #pragma unroll
    for (int mi = 0; mi < 4; mi++)
        #pragma unroll
        for (int ni = 0; ni < 8; ni++)
            #pragma unroll
            for (int e = 0; e < 4; e++) acc[mi][ni][e] = 0.f;

    stage(0, 0); CP_COMMIT();
    stage(1, 1); CP_COMMIT();

    const int fr = lane >> 2;            // 0..7
    const int fk = (lane & 3) * 4;       // byte offset of k-pair

    #pragma unroll 1
    for (int c = 0; c < NCHUNK; c++) {
        const int p = c & 1;
        if (c == NCHUNK - 1) CP_WAIT0(); else CP_WAIT1();
        __syncthreads();

        const char* Aa = smd + p * STAGE_BYTES;
        const char* Bh = Aa + TILE_A;
        const char* Bl = Bh + TILE_Bb;

        #pragma unroll
        for (int ks = 0; ks < 2; ks++) {
            uint32_t af[4][4], bfr[8][2];
            #pragma unroll
            for (int mi = 0; mi < 4; mi++) {
                uint32_t o = (wm*64 + mi*16 + fr) * PADB + ks*32 + fk;
                af[mi][0] = *(const uint32_t*)(Aa + o);
                af[mi][1] = *(const uint32_t*)(Aa + o + 8*PADB);
                af[mi][2] = *(const uint32_t*)(Aa + o + 16);
                af[mi][3] = *(const uint32_t*)(Aa + o + 8*PADB + 16);
            }
            #pragma unroll
            for (int ni = 0; ni < 8; ni++) {
                uint32_t o = (wn*64 + ni*8 + fr) * PADB + ks*32 + fk;
                bfr[ni][0] = *(const uint32_t*)(Bh + o);
                bfr[ni][1] = *(const uint32_t*)(Bh + o + 16);
            }
            #pragma unroll
            for (int mi = 0; mi < 4; mi++)
                #pragma unroll
                for (int ni = 0; ni < 8; ni++)
                    MMA16816(acc[mi][ni], af[mi], bfr[ni]);

            if (isK) {
                #pragma unroll
                for (int ni = 0; ni < 8; ni++) {
                    uint32_t o = (wn*64 + ni*8 + fr) * PADB + ks*32 + fk;
                    bfr[ni][0] = *(const uint32_t*)(Bl + o);
                    bfr[ni][1] = *(const uint32_t*)(Bl + o + 16);
                }
                #pragma unroll
                for (int mi = 0; mi < 4; mi++)
                    #pragma unroll
                    for (int ni = 0; ni < 8; ni++)
                        MMA16816(acc[mi][ni], af[mi], bfr[ni]);
            }
        }

        __syncthreads();
        if (c + 2 < NCHUNK) stage(p, c + 2);
        CP_COMMIT();
    }

    // ---- epilogue: unscale (1/64) + LN fold + fp16 store to k/v ----
    __half* base = isK ? g_k : g_v;
    #pragma unroll
    for (int mi = 0; mi < 4; mi++) {
        int r1 = bm + wm*64 + mi*16 + fr;
        int r2 = r1 + 8;
        float rm1 = g_mean[r1], rs1 = g_rstd[r1];
        float rm2 = g_mean[r2], rs2 = g_rstd[r2];
        #pragma unroll
        for (int ni = 0; ni < 8; ni++) {
            int cl = wn*64 + ni*8 + (lane & 3)*2;   // local col in [0,256)
            float cs0 = s_cs[cl], cs1 = s_cs[cl+1];
            float cb0 = s_cb[cl], cb1 = s_cb[cl+1];
            __half2* d1 = (__half2*)(base + (size_t)r1*DS + cl);
            __half2* d2 = (__half2*)(base + (size_t)r2*DS + cl);
            *d1 = __floats2half2_rn(
                rs1*(acc[mi][ni][0]*INV64 - rm1*cs0) + cb0,
                rs1*(acc[mi][ni][1]*INV64 - rm1*cs1) + cb1);
            *d2 = __floats2half2_rn(
                rs2*(acc[mi][ni][2]*INV64 - rm2*cs0) + cb0,
                rs2*(acc[mi][ni][3]*INV64 - rm2*cs1) + cb1);
        }
    }
}

// ---------------- per-slot q = LN(slots) @ Wq^T (also zeroes U/S accumulators) ----------------
__global__ void __launch_bounds__(256) slot_q(const float* __restrict__ gs, const float* __restrict__ bs) {
    int row = blockIdx.x;
    int t = threadIdx.x;
    __shared__ float sn[256];
    __shared__ float r1[8], r2[8];
    __shared__ float smv[2];
    g_U[row*256 + t] = 0.f;
    if (t == 0) g_S[row] = 0.f;
    float x = g_slots[row*256 + t];
    float s = x, s2 = x*x;
    for (int o = 16; o; o >>= 1) { s += __shfl_down_sync(0xffffffffu, s, o); s2 += __shfl_down_sync(0xffffffffu, s2, o); }
    if ((t & 31) == 0) { r1[t>>5] = s; r2[t>>5] = s2; }
    __syncthreads();
    if (t == 0) {
        float ts = 0.f, ts2 = 0.f;
        #pragma unroll
        for (int w = 0; w < 8; w++) { ts += r1[w]; ts2 += r2[w]; }
        float m = ts * (1.f/256.f);
        float var = ts2 * (1.f/256.f) - m*m;
        smv[0] = m; smv[1] = rsqrtf(var + 1e-5f);
    }
    __syncthreads();
    sn[t] = (x - smv[0]) * smv[1] * gs[t] + bs[t];
    __syncthreads();
    float acc = 0.f;
    #pragma unroll 4
    for (int d = 0; d < 256; d++) acc += sn[d] * g_WqT[d*256 + t];
    g_q[row*256 + t] = acc;
}

// ---------------- fused attention sweep (k/v fp16 in GMEM, fp32 in smem) ----------------
#define ATILE 32
#define KPAD 260
#define CHUNKS 32
#define ATTN_SMEM_FLOATS (8*256 + 2*ATILE*KPAD + 2*8*36)

template <bool FINAL>
__global__ void __launch_bounds__(256) attn_pass(float* __restrict__ out_attn) {
    extern __shared__ float sm[];
    float* qs = sm;
    float* kt = qs + 8*256;
    float* vt = kt + ATILE*KPAD;
    float* Ls = vt + ATILE*KPAD;
    float* ps = Ls + 8*36;

    int b  = blockIdx.x;
    int ch = blockIdx.y;
    int t  = threadIdx.x;

    for (int i = t; i < 8*256; i += 256) qs[i] = g_q[b*2048 + i] * SCALE_F;

    const int n0 = ch * (NN / CHUNKS);
    float regU[8], regS[8];
    #pragma unroll
    for (int h = 0; h < 8; h++) { regU[h] = 0.f; regS[h] = 0.f; }

    const int hq = t >> 5;
    const int nl = t & 31;

    #pragma unroll 1
    for (int tile = 0; tile < (NN/CHUNKS)/ATILE; tile++) {
        int nbase = n0 + tile * ATILE;
        __syncthreads();
        const __half* kg = g_k + ((size_t)b*NN + nbase) * DS;
        const __half* vg = g_v + ((size_t)b*NN + nbase) * DS;
        for (int i = t; i < ATILE*32; i += 256) {
            int n = i >> 5; int d8 = (i & 31) << 3;
            uint4 raw = *(const uint4*)(kg + n*DS + d8);
            __half2* hp = (__half2*)&raw;
            float2 f0 = __half22float2(hp[0]), f1 = __half22float2(hp[1]);
            float2 f2 = __half22float2(hp[2]), f3 = __half22float2(hp[3]);
            *(float4*)(kt + n*KPAD + d8)     = make_float4(f0.x, f0.y, f1.x, f1.y);
            *(float4*)(kt + n*KPAD + d8 + 4) = make_float4(f2.x, f2.y, f3.x, f3.y);
            if (!FINAL) {
                uint4 rv = *(const uint4*)(vg + n*DS + d8);
                __half2* vp = (__half2*)&rv;
                float2 g0 = __half22float2(vp[0]), g1 = __half22float2(vp[1]);
                float2 g2 = __half22float2(vp[2]), g3 = __half22float2(vp[3]);
                *(float4*)(vt + n*KPAD + d8)     = make_float4(g0.x, g0.y, g1.x, g1.y);
                *(float4*)(vt + n*KPAD + d8 + 4) = make_float4(g2.x, g2.y, g3.x, g3.y);
            }
        }
        __syncthreads();

        {
            float acc = 0.f;
            const float* qrow = qs + hq*256;
            const float* krow = kt + nl*KPAD;
            #pragma unroll 8
            for (int d = 0; d < 256; d += 4) {
                float4 qv = *(const float4*)(qrow + d);
                float4 kv = *(const float4*)(krow + d);
                acc += qv.x*kv.x + qv.y*kv.y + qv.z*kv.z + qv.w*kv.w;
            }
            Ls[hq*36 + nl] = acc;
        }
        __syncthreads();

        if (t < 32) {
            float l[8], m = -1e30f;
            #pragma unroll
            for (int h = 0; h < 8; h++) { l[h] = Ls[h*36 + t]; m = fmaxf(m, l[h]); }
            float ssum = 0.f;
            #pragma unroll
            for (int h = 0; h < 8; h++) { l[h] = expf(l[h] - m); ssum += l[h]; }
            float inv = 1.f / ssum;
            #pragma unroll
            for (int h = 0; h < 8; h++) {
                float p = l[h] * inv;
                ps[h*36 + t] = p;
                regS[h] += p;
                if (FINAL)
                    out_attn[((size_t)b*KSLOT + h)*NN + nbase + t] = p;
            }
        }
        __syncthreads();

        if (!FINAL) {
            #pragma unroll 4
            for (int n = 0; n < ATILE; n++) {
                float vv = vt[n*KPAD + t];
                #pragma unroll
                for (int h = 0; h < 8; h++) regU[h] += ps[h*36 + n] * vv;
            }
        }
    }

    if (!FINAL) {
        #pragma unroll
        for (int h = 0; h < 8; h++)
            atomicAdd(&g_U[((size_t)b*KSLOT + h)*DS + t], regU[h]);
    }
    if (t < 32) {
        #pragma unroll
        for (int h = 0; h < 8; h++) {
            float v = regS[h];
            for (int o = 16; o; o >>= 1) v += __shfl_down_sync(0xffffffffu, v, o);
            if (t == 0) atomicAdd(&g_S[b*KSLOT + h], v);
        }
    }
}

// ---------------- GRU gate GEMMs ----------------
__global__ void __launch_bounds__(256) gru_gemm(const float* __restrict__ bih, const float* __restrict__ bhh) {
    int blk = blockIdx.x;
    int b = blk / 24, gc = blk % 24;
    __shared__ float su[8*256], ss[8*256];
    int t = threadIdx.x;
    for (int i = t; i < 2048; i += 256) {
        int k = i >> 8;
        su[i] = g_U[b*2048 + i] / (g_S[b*8 + k] + EPS_ATTN);
        ss[i] = g_slots[b*2048 + i];
    }
    __syncthreads();
    int g = gc*32 + (t & 31);
    int k = t >> 5;
    float gi = bih[g], gh = bhh[g];
    const float* su_k = su + k*256;
    const float* ss_k = ss + k*256;
    #pragma unroll 4
    for (int d = 0; d < 256; d++) {
        gi += su_k[d] * g_WihT[d*768 + g];
        gh += ss_k[d] * g_WhhT[d*768 + g];
    }
    g_gi[((size_t)b*8 + k)*768 + g] = gi;
    g_gh[((size_t)b*8 + k)*768 + g] = gh;
}

// ---------------- GRU combine + LN + MLP ----------------
__global__ void __launch_bounds__(256) gru_mlp(const float* __restrict__ gm, const float* __restrict__ bm,
                                               const float* __restrict__ b1, const float* __restrict__ b2) {
    int bk = blockIdx.x;
    int t = threadIdx.x;
    const float* gi = g_gi + (size_t)bk*768;
    const float* gh = g_gh + (size_t)bk*768;
    float sl = g_slots[bk*256 + t];
    float r  = 1.f / (1.f + expf(-(gi[t]       + gh[t])));
    float z  = 1.f / (1.f + expf(-(gi[256 + t] + gh[256 + t])));
    float nn = tanhf(gi[512 + t] + r * gh[512 + t]);
    float h  = (1.f - z) * nn + z * sl;

    __shared__ float hn[256], ms[256];
    __shared__ float r1[8], r2[8];
    __shared__ float smv[2];
    float s = h, s2 = h*h;
    for (int o = 16; o; o >>= 1) { s += __shfl_down_sync(0xffffffffu, s, o); s2 += __shfl_down_sync(0xffffffffu, s2, o); }
    if ((t & 31) == 0) { r1[t>>5] = s; r2[t>>5] = s2; }
    __syncthreads();
    if (t == 0) {
        float ts = 0.f, ts2 = 0.f;
        #pragma unroll
        for (int w = 0; w < 8; w++) { ts += r1[w]; ts2 += r2[w]; }
        float m = ts * (1.f/256.f);
        float var = ts2 * (1.f/256.f) - m*m;
        smv[0] = m; smv[1] = rsqrtf(var + 1e-5f);
    }
    __syncthreads();
    hn[t] = (h - smv[0]) * smv[1] * gm[t] + bm[t];
    __syncthreads();
    float acc = b1[t];
    #pragma unroll 4
    for (int d = 0; d < 256; d++) acc += hn[d] * g_W1T[d*256 + t];
    ms[t] = fmaxf(acc, 0.f);
    __syncthreads();
    float o = h + b2[t];
    #pragma unroll 4
    for (int j = 0; j < 256; j++) o += ms[j] * g_W2T[j*256 + t];
    g_slots[bk*256 + t] = o;
}

// ---------------- final confidence blend ----------------
__global__ void __launch_bounds__(256) finalize(const float* __restrict__ prev, float* __restrict__ out_slots) {
    int bk = blockIdx.x;
    int t = threadIdx.x;
    float mean = g_S[bk] * (1.f / 4096.f);
    float mask = 1.f / (1.f + expf(-mean));
    out_slots[bk*256 + t] = g_slots[bk*256 + t] * mask + prev[bk*256 + t] * (1.f - mask);
}

// ---------------- launch ----------------
extern "C" void kernel_launch(void* const* d_in, const int* in_sizes, int n_in,
                              void* d_out, int out_size) {
    const float* features = (const float*)d_in[0];
    const float* prev     = (const float*)d_in[1];
    const float* gin      = (const float*)d_in[2];
    const float* bin      = (const float*)d_in[3];
    const float* gs       = (const float*)d_in[4];
    const float* bs       = (const float*)d_in[5];
    const float* gm       = (const float*)d_in[6];
    const float* bm       = (const float*)d_in[7];
    const float* Wq       = (const float*)d_in[8];
    const float* Wk       = (const float*)d_in[9];
    const float* Wv       = (const float*)d_in[10];
    const float* Wih      = (const float*)d_in[11];
    const float* Whh      = (const float*)d_in[12];
    const float* bih      = (const float*)d_in[13];
    const float* bhh      = (const float*)d_in[14];
    const float* W1       = (const float*)d_in[15];
    const float* b1       = (const float*)d_in[16];
    const float* W2       = (const float*)d_in[17];
    const float* b2       = (const float*)d_in[18];

    float* out_slots = (float*)d_out;
    float* out_attn  = out_slots + BB*KSLOT*DS;

    const size_t attn_smem = (size_t)ATTN_SMEM_FLOATS * sizeof(float);
    cudaFuncSetAttribute((const void*)attn_pass<false>, cudaFuncAttributeMaxDynamicSharedMemorySize, (int)attn_smem);
    cudaFuncSetAttribute((const void*)attn_pass<true>,  cudaFuncAttributeMaxDynamicSharedMemorySize, (int)attn_smem);
    cudaFuncSetAttribute((const void*)gemm_mma, cudaFuncAttributeMaxDynamicSharedMemorySize, GEMM_SMEM);

    // prep
    prep_wc<<<512, 256>>>(Wk, Wv, gin, bin);
    prep_wc_split<<<(512*DF + 255)/256, 256>>>();
    prep_transpose<<<(768*256 + 255)/256, 256>>>(Wq, Wih, Whh, W1, W2, prev);

    // phase A: fused LN stats + fp16 cast, then fp16 tensor GEMM
    row_stats_split<<<NROWS/8, 256>>>(features);
    gemm_mma<<<dim3(2, NROWS/128), 256, GEMM_SMEM>>>();

    // phase B: 3 slot-attention iterations
    for (int it = 0; it < 3; it++) {
        slot_q<<<BB*KSLOT, 256>>>(gs, bs);
        attn_pass<false><<<dim3(BB, CHUNKS), 256, attn_smem>>>(nullptr);
        gru_gemm<<<BB*24, 256>>>(bih, bhh);
        gru_mlp<<<BB*KSLOT, 256>>>(gm, bm, b1, b2);
    }

    // final attention + blend
    slot_q<<<BB*KSLOT, 256>>>(gs, bs);
    attn_pass<true><<<dim3(BB, CHUNKS), 256, attn_smem>>>(out_attn);
    finalize<<<BB*KSLOT, 256>>>(prev, out_slots);

    (void)in_sizes; (void)n_in; (void)out_size;
}

// round 7
// speedup vs baseline: 2.2119x; 1.0933x over previous
#include <cuda_runtime.h>
#include <cuda_fp16.h>
#include <cstdint>
#include <math.h>

// ---------------- problem constants ----------------
#define BB 32
#define NN 4096
#define DF 768
#define DS 256
#define KSLOT 8
#define NROWS (BB*NN)        // 131072
#define SCALE_F 0.0625f      // 256^-0.5
#define EPS_ATTN 1e-8f

// ---------------- scratch (device globals; no allocations allowed) ----------------
static __device__ float g_mean[NROWS];
static __device__ float g_rstd[NROWS];
static __device__ __align__(16) __half g_Fh[(size_t)NROWS*DF];          // 201 MB
static __device__ __align__(16) __half g_k[(size_t)NROWS*DS];           // 67 MB
static __device__ __align__(16) __half g_v[(size_t)NROWS*DS];           // 67 MB
static __device__ float g_Wc[512*DF];              // [Wk';Wv'] with g_in folded in
static __device__ __align__(16) __half g_WcH[512*DF];                   // fp16(Wc)
static __device__ float g_csum[512];
static __device__ float g_cbias[512];
static __device__ float g_WqT[DS*DS];
static __device__ float g_WihT[DS*768];
static __device__ float g_WhhT[DS*768];
static __device__ float g_W1T[DS*DS];
static __device__ float g_W2T[DS*DS];
static __device__ float g_q[BB*KSLOT*DS];
static __device__ float g_slots[BB*KSLOT*DS];
static __device__ float g_U[BB*KSLOT*DS];
static __device__ float g_S[BB*KSLOT];
static __device__ float g_gi[BB*KSLOT*768];
static __device__ float g_gh[BB*KSLOT*768];

// ---------------- helpers ----------------
__device__ __forceinline__ uint32_t s2u(const void* p) {
    uint32_t r;
    asm("{ .reg .u64 t; cvta.to.shared.u64 t, %1; cvt.u32.u64 %0, t; }" : "=r"(r) : "l"(p));
    return r;
}
__device__ __forceinline__ void cpa16(uint32_t dst, const void* src) {
    asm volatile("cp.async.cg.shared.global [%0], [%1], 16;" :: "r"(dst), "l"(src));
}
#define CP_COMMIT() asm volatile("cp.async.commit_group;" ::: "memory")
#define CP_WAIT1()  asm volatile("cp.async.wait_group 1;" ::: "memory")
#define CP_WAIT0()  asm volatile("cp.async.wait_group 0;" ::: "memory")

#define MMA16816(C, A, B) \
    asm volatile("mma.sync.aligned.m16n8k16.row.col.f32.f16.f16.f32 " \
        "{%0,%1,%2,%3}, {%4,%5,%6,%7}, {%8,%9}, {%0,%1,%2,%3};" \
        : "+f"((C)[0]), "+f"((C)[1]), "+f"((C)[2]), "+f"((C)[3]) \
        : "r"((A)[0]), "r"((A)[1]), "r"((A)[2]), "r"((A)[3]), "r"((B)[0]), "r"((B)[1]))

// ---------------- prep: combined, g-scaled projection weights ----------------
__global__ void __launch_bounds__(256) prep_wc(const float* __restrict__ Wk,
                                               const float* __restrict__ Wv,
                                               const float* __restrict__ gin,
                                               const float* __restrict__ bin) {
    int j = blockIdx.x;             // 0..511  (0..255 -> k, 256..511 -> v)
    const float* W = (j < 256) ? (Wk + (size_t)j*DF) : (Wv + (size_t)(j-256)*DF);
    int t = threadIdx.x;
    float s = 0.f, bsum = 0.f;
    for (int f = t; f < DF; f += 256) {
        float w  = W[f];
        float wc = w * gin[f];
        g_Wc[(size_t)j*DF + f] = wc;
        s += wc; bsum += w * bin[f];
    }
    __shared__ float r1[8], r2[8];
    for (int o = 16; o; o >>= 1) { s += __shfl_down_sync(0xffffffffu, s, o); bsum += __shfl_down_sync(0xffffffffu, bsum, o); }
    if ((t & 31) == 0) { r1[t>>5] = s; r2[t>>5] = bsum; }
    __syncthreads();
    if (t == 0) {
        float ts = 0.f, tb = 0.f;
        #pragma unroll
        for (int w = 0; w < 8; w++) { ts += r1[w]; tb += r2[w]; }
        g_csum[j] = ts; g_cbias[j] = tb;
    }
}

// ---------------- prep: fp16 cast of Wc ----------------
__global__ void __launch_bounds__(256) prep_wc_split(void) {
    int i = blockIdx.x * 256 + threadIdx.x;
    if (i < 512*DF) g_WcH[i] = __float2half_rn(g_Wc[i]);
}

// ---------------- prep: transposed small weights + copy slots ----------------
__global__ void prep_transpose(const float* __restrict__ Wq,
                               const float* __restrict__ Wih,
                               const float* __restrict__ Whh,
                               const float* __restrict__ W1,
                               const float* __restrict__ W2,
                               const float* __restrict__ prev) {
    int i = blockIdx.x * blockDim.x + threadIdx.x;
    if (i < 768*256) {
        int g = i / 256, d = i % 256;
        g_WihT[d*768 + g] = Wih[i];
        g_WhhT[d*768 + g] = Whh[i];
    }
    if (i < 256*256) {
        int r = i / 256, c = i % 256;
        g_WqT[c*256 + r] = Wq[i];
        g_W1T[c*256 + r] = W1[i];
        g_W2T[c*256 + r] = W2[i];
    }
    if (i < BB*KSLOT*DS) g_slots[i] = prev[i];
}

// ---------------- LN stats + fp16 cast of F (one streaming pass) ----------------
__global__ void __launch_bounds__(256) row_stats_split(const float* __restrict__ F) {
    int w = threadIdx.x >> 5, l = threadIdx.x & 31;
    int row = blockIdx.x * 8 + w;
    const float4* x = (const float4*)(F + (size_t)row * DF);
    float4 a[6];
    float s = 0.f, s2 = 0.f;
    #pragma unroll
    for (int j = 0; j < 6; j++) {
        a[j] = x[l + 32*j];
        s  += a[j].x + a[j].y + a[j].z + a[j].w;
        s2 += a[j].x*a[j].x + a[j].y*a[j].y + a[j].z*a[j].z + a[j].w*a[j].w;
    }
    uint2* hdst = (uint2*)(g_Fh + (size_t)row * DF);
    #pragma unroll
    for (int j = 0; j < 6; j++) {
        float4 v = a[j];
        __half2 h0 = __floats2half2_rn(v.x, v.y);
        __half2 h1 = __floats2half2_rn(v.z, v.w);
        hdst[l + 32*j] = make_uint2(*(uint32_t*)&h0, *(uint32_t*)&h1);
    }
    for (int o = 16; o; o >>= 1) {
        s  += __shfl_down_sync(0xffffffffu, s, o);
        s2 += __shfl_down_sync(0xffffffffu, s2, o);
    }
    if (l == 0) {
        float m   = s * (1.f/768.f);
        float var = s2 * (1.f/768.f) - m*m;
        g_mean[row] = m;
        g_rstd[row] = rsqrtf(var + 1e-5f);
    }
}

// ---------------- tensor-core GEMM (fp16 single-pass, cp.async staged) ----------------
// C[131072 x 512] = F @ Wc^T, fp32 accum. A = fp16(F), B = fp16(Wc).
// CTA 128x256, BK=32, 8 warps (2x4 grid, warp tile 64x64), 2-stage cp.async pipeline.
#define PADB 80                      // bytes per smem row (32 halfs data + pad); odd 16B mult
#define TILE_A (128*PADB)            // 10240
#define TILE_Bb (256*PADB)           // 20480
#define STAGE_BYTES (TILE_A + TILE_Bb)      // 30720: A, B
#define GEMM_SMEM (2*STAGE_BYTES)    // 61440
#define NCHUNK (DF/32)               // 24

__global__ void __launch_bounds__(256) gemm_mma(void) {
    extern __shared__ __align__(16) char smd[];
    __shared__ float s_cs[256], s_cb[256];

    const int tid = threadIdx.x;
    const int wid = tid >> 5, lane = tid & 31;
    const int wm = wid & 1, wn = wid >> 1;      // warp grid 2 x 4, tile 64x64
    const int bn = blockIdx.x * 256;
    const int bm = blockIdx.y * 128;

    s_cs[tid] = g_csum[bn + tid];
    s_cb[tid] = g_cbias[bn + tid];

    const uint32_t smem_u = s2u(smd);
    const int arow = tid >> 2;           // 0..63
    const int aq   = tid & 3;            // 16B quarter within 64B row-chunk

    auto stage = [&](int buf, int c) {
        const int kb = c * 32;
        uint32_t sb = smem_u + buf * STAGE_BYTES;
        const __half* fa = g_Fh + (size_t)(bm + arow) * DF + kb + aq * 8;
        uint32_t da = sb + arow * PADB + aq * 16;
        cpa16(da,            fa);
        cpa16(da + 64*PADB,  fa + (size_t)64*DF);
        const __half* bh = g_WcH + (size_t)(bn + arow) * DF + kb + aq * 8;
        uint32_t db = sb + TILE_A + arow * PADB + aq * 16;
        #pragma unroll
        for (int j = 0; j < 4; j++)
            cpa16(db + j*64*PADB, bh + (size_t)j*64*DF);
    };

    float acc[4][8][4];
    #pragma unroll
    for (int mi = 0; mi < 4; mi++)
        #pragma unroll
        for (int ni = 0; ni < 8; ni++)
            #pragma unroll
            for (int e = 0; e < 4; e++) acc[mi][ni][e] = 0.f;

    stage(0, 0); CP_COMMIT();
    stage(1, 1); CP_COMMIT();

    const int fr = lane >> 2;            // 0..7
    const int fk = (lane & 3) * 4;       // byte offset of k-pair

    #pragma unroll 1
    for (int c = 0; c < NCHUNK; c++) {
        const int p = c & 1;
        if (c == NCHUNK - 1) CP_WAIT0(); else CP_WAIT1();
        __syncthreads();

        const char* Aa = smd + p * STAGE_BYTES;
        const char* Bh = Aa + TILE_A;

        #pragma unroll
        for (int ks = 0; ks < 2; ks++) {
            uint32_t af[4][4], bfr[8][2];
            #pragma unroll
            for (int mi = 0; mi < 4; mi++) {
                uint32_t o = (wm*64 + mi*16 + fr) * PADB + ks*32 + fk;
                af[mi][0] = *(const uint32_t*)(Aa + o);
                af[mi][1] = *(const uint32_t*)(Aa + o + 8*PADB);
                af[mi][2] = *(const uint32_t*)(Aa + o + 16);
                af[mi][3] = *(const uint32_t*)(Aa + o + 8*PADB + 16);
            }
            #pragma unroll
            for (int ni = 0; ni < 8; ni++) {
                uint32_t o = (wn*64 + ni*8 + fr) * PADB + ks*32 + fk;
                bfr[ni][0] = *(const uint32_t*)(Bh + o);
                bfr[ni][1] = *(const uint32_t*)(Bh + o + 16);
            }
            #pragma unroll
            for (int mi = 0; mi < 4; mi++)
                #pragma unroll
                for (int ni = 0; ni < 8; ni++)
                    MMA16816(acc[mi][ni], af[mi], bfr[ni]);
        }

        __syncthreads();
        if (c + 2 < NCHUNK) stage(p, c + 2);
        CP_COMMIT();
    }

    // ---- epilogue: LN fold + fp16 store to k/v ----
    __half* base = (blockIdx.x == 0) ? g_k : g_v;
    #pragma unroll
    for (int mi = 0; mi < 4; mi++) {
        int r1 = bm + wm*64 + mi*16 + fr;
        int r2 = r1 + 8;
        float rm1 = g_mean[r1], rs1 = g_rstd[r1];
        float rm2 = g_mean[r2], rs2 = g_rstd[r2];
        #pragma unroll
        for (int ni = 0; ni < 8; ni++) {
            int cl = wn*64 + ni*8 + (lane & 3)*2;   // local col in [0,256)
            float cs0 = s_cs[cl], cs1 = s_cs[cl+1];
            float cb0 = s_cb[cl], cb1 = s_cb[cl+1];
            __half2* d1 = (__half2*)(base + (size_t)r1*DS + cl);
            __half2* d2 = (__half2*)(base + (size_t)r2*DS + cl);
            *d1 = __floats2half2_rn(
                rs1*(acc[mi][ni][0] - rm1*cs0) + cb0,
                rs1*(acc[mi][ni][1] - rm1*cs1) + cb1);
            *d2 = __floats2half2_rn(
                rs2*(acc[mi][ni][2] - rm2*cs0) + cb0,
                rs2*(acc[mi][ni][3] - rm2*cs1) + cb1);
        }
    }
}

// ---------------- per-slot q = LN(slots) @ Wq^T (also zeroes U/S accumulators) ----------------
__global__ void __launch_bounds__(256) slot_q(const float* __restrict__ gs, const float* __restrict__ bs) {
    int row = blockIdx.x;
    int t = threadIdx.x;
    __shared__ float sn[256];
    __shared__ float r1[8], r2[8];
    __shared__ float smv[2];
    g_U[row*256 + t] = 0.f;
    if (t == 0) g_S[row] = 0.f;
    float x = g_slots[row*256 + t];
    float s = x, s2 = x*x;
    for (int o = 16; o; o >>= 1) { s += __shfl_down_sync(0xffffffffu, s, o); s2 += __shfl_down_sync(0xffffffffu, s2, o); }
    if ((t & 31) == 0) { r1[t>>5] = s; r2[t>>5] = s2; }
    __syncthreads();
    if (t == 0) {
        float ts = 0.f, ts2 = 0.f;
        #pragma unroll
        for (int w = 0; w < 8; w++) { ts += r1[w]; ts2 += r2[w]; }
        float m = ts * (1.f/256.f);
        float var = ts2 * (1.f/256.f) - m*m;
        smv[0] = m; smv[1] = rsqrtf(var + 1e-5f);
    }
    __syncthreads();
    sn[t] = (x - smv[0]) * smv[1] * gs[t] + bs[t];
    __syncthreads();
    float acc = 0.f;
    #pragma unroll 4
    for (int d = 0; d < 256; d++) acc += sn[d] * g_WqT[d*256 + t];
    g_q[row*256 + t] = acc;
}

// ---------------- fused attention sweep (k/v fp16 in GMEM, fp32 in smem) ----------------
#define ATILE 32
#define KPAD 260
#define CHUNKS 32
#define ATTN_SMEM_FLOATS (8*256 + 2*ATILE*KPAD + 2*8*36)

template <bool FINAL>
__global__ void __launch_bounds__(256) attn_pass(float* __restrict__ out_attn) {
    extern __shared__ float sm[];
    float* qs = sm;
    float* kt = qs + 8*256;
    float* vt = kt + ATILE*KPAD;
    float* Ls = vt + ATILE*KPAD;
    float* ps = Ls + 8*36;

    int b  = blockIdx.x;
    int ch = blockIdx.y;
    int t  = threadIdx.x;

    for (int i = t; i < 8*256; i += 256) qs[i] = g_q[b*2048 + i] * SCALE_F;

    const int n0 = ch * (NN / CHUNKS);
    float regU[8], regS[8];
    #pragma unroll
    for (int h = 0; h < 8; h++) { regU[h] = 0.f; regS[h] = 0.f; }

    const int hq = t >> 5;
    const int nl = t & 31;

    #pragma unroll 1
    for (int tile = 0; tile < (NN/CHUNKS)/ATILE; tile++) {
        int nbase = n0 + tile * ATILE;
        __syncthreads();
        const __half* kg = g_k + ((size_t)b*NN + nbase) * DS;
        const __half* vg = g_v + ((size_t)b*NN + nbase) * DS;
        for (int i = t; i < ATILE*32; i += 256) {
            int n = i >> 5; int d8 = (i & 31) << 3;
            uint4 raw = *(const uint4*)(kg + n*DS + d8);
            __half2* hp = (__half2*)&raw;
            float2 f0 = __half22float2(hp[0]), f1 = __half22float2(hp[1]);
            float2 f2 = __half22float2(hp[2]), f3 = __half22float2(hp[3]);
            *(float4*)(kt + n*KPAD + d8)     = make_float4(f0.x, f0.y, f1.x, f1.y);
            *(float4*)(kt + n*KPAD + d8 + 4) = make_float4(f2.x, f2.y, f3.x, f3.y);
            if (!FINAL) {
                uint4 rv = *(const uint4*)(vg + n*DS + d8);
                __half2* vp = (__half2*)&rv;
                float2 g0 = __half22float2(vp[0]), g1 = __half22float2(vp[1]);
                float2 g2 = __half22float2(vp[2]), g3 = __half22float2(vp[3]);
                *(float4*)(vt + n*KPAD + d8)     = make_float4(g0.x, g0.y, g1.x, g1.y);
                *(float4*)(vt + n*KPAD + d8 + 4) = make_float4(g2.x, g2.y, g3.x, g3.y);
            }
        }
        __syncthreads();

        {
            float acc = 0.f;
            const float* qrow = qs + hq*256;
            const float* krow = kt + nl*KPAD;
            #pragma unroll 8
            for (int d = 0; d < 256; d += 4) {
                float4 qv = *(const float4*)(qrow + d);
                float4 kv = *(const float4*)(krow + d);
                acc += qv.x*kv.x + qv.y*kv.y + qv.z*kv.z + qv.w*kv.w;
            }
            Ls[hq*36 + nl] = acc;
        }
        __syncthreads();

        if (t < 32) {
            float l[8], m = -1e30f;
            #pragma unroll
            for (int h = 0; h < 8; h++) { l[h] = Ls[h*36 + t]; m = fmaxf(m, l[h]); }
            float ssum = 0.f;
            #pragma unroll
            for (int h = 0; h < 8; h++) { l[h] = expf(l[h] - m); ssum += l[h]; }
            float inv = 1.f / ssum;
            #pragma unroll
            for (int h = 0; h < 8; h++) {
                float p = l[h] * inv;
                ps[h*36 + t] = p;
                regS[h] += p;
                if (FINAL)
                    out_attn[((size_t)b*KSLOT + h)*NN + nbase + t] = p;
            }
        }
        __syncthreads();

        if (!FINAL) {
            #pragma unroll 4
            for (int n = 0; n < ATILE; n++) {
                float vv = vt[n*KPAD + t];
                #pragma unroll
                for (int h = 0; h < 8; h++) regU[h] += ps[h*36 + n] * vv;
            }
        }
    }

    if (!FINAL) {
        #pragma unroll
        for (int h = 0; h < 8; h++)
            atomicAdd(&g_U[((size_t)b*KSLOT + h)*DS + t], regU[h]);
    }
    if (t < 32) {
        #pragma unroll
        for (int h = 0; h < 8; h++) {
            float v = regS[h];
            for (int o = 16; o; o >>= 1) v += __shfl_down_sync(0xffffffffu, v, o);
            if (t == 0) atomicAdd(&g_S[b*KSLOT + h], v);
        }
    }
}

// ---------------- GRU gate GEMMs ----------------
__global__ void __launch_bounds__(256) gru_gemm(const float* __restrict__ bih, const float* __restrict__ bhh) {
    int blk = blockIdx.x;
    int b = blk / 24, gc = blk % 24;
    __shared__ float su[8*256], ss[8*256];
    int t = threadIdx.x;
    for (int i = t; i < 2048; i += 256) {
        int k = i >> 8;
        su[i] = g_U[b*2048 + i] / (g_S[b*8 + k] + EPS_ATTN);
        ss[i] = g_slots[b*2048 + i];
    }
    __syncthreads();
    int g = gc*32 + (t & 31);
    int k = t >> 5;
    float gi = bih[g], gh = bhh[g];
    const float* su_k = su + k*256;
    const float* ss_k = ss + k*256;
    #pragma unroll 4
    for (int d = 0; d < 256; d++) {
        gi += su_k[d] * g_WihT[d*768 + g];
        gh += ss_k[d] * g_WhhT[d*768 + g];
    }
    g_gi[((size_t)b*8 + k)*768 + g] = gi;
    g_gh[((size_t)b*8 + k)*768 + g] = gh;
}

// ---------------- GRU combine + LN + MLP ----------------
__global__ void __launch_bounds__(256) gru_mlp(const float* __restrict__ gm, const float* __restrict__ bm,
                                               const float* __restrict__ b1, const float* __restrict__ b2) {
    int bk = blockIdx.x;
    int t = threadIdx.x;
    const float* gi = g_gi + (size_t)bk*768;
    const float* gh = g_gh + (size_t)bk*768;
    float sl = g_slots[bk*256 + t];
    float r  = 1.f / (1.f + expf(-(gi[t]       + gh[t])));
    float z  = 1.f / (1.f + expf(-(gi[256 + t] + gh[256 + t])));
    float nn = tanhf(gi[512 + t] + r * gh[512 + t]);
    float h  = (1.f - z) * nn + z * sl;

    __shared__ float hn[256], ms[256];
    __shared__ float r1[8], r2[8];
    __shared__ float smv[2];
    float s = h, s2 = h*h;
    for (int o = 16; o; o >>= 1) { s += __shfl_down_sync(0xffffffffu, s, o); s2 += __shfl_down_sync(0xffffffffu, s2, o); }
    if ((t & 31) == 0) { r1[t>>5] = s; r2[t>>5] = s2; }
    __syncthreads();
    if (t == 0) {
        float ts = 0.f, ts2 = 0.f;
        #pragma unroll
        for (int w = 0; w < 8; w++) { ts += r1[w]; ts2 += r2[w]; }
        float m = ts * (1.f/256.f);
        float var = ts2 * (1.f/256.f) - m*m;
        smv[0] = m; smv[1] = rsqrtf(var + 1e-5f);
    }
    __syncthreads();
    hn[t] = (h - smv[0]) * smv[1] * gm[t] + bm[t];
    __syncthreads();
    float acc = b1[t];
    #pragma unroll 4
    for (int d = 0; d < 256; d++) acc += hn[d] * g_W1T[d*256 + t];
    ms[t] = fmaxf(acc, 0.f);
    __syncthreads();
    float o = h + b2[t];
    #pragma unroll 4
    for (int j = 0; j < 256; j++) o += ms[j] * g_W2T[j*256 + t];
    g_slots[bk*256 + t] = o;
}

// ---------------- final confidence blend ----------------
__global__ void __launch_bounds__(256) finalize(const float* __restrict__ prev, float* __restrict__ out_slots) {
    int bk = blockIdx.x;
    int t = threadIdx.x;
    float mean = g_S[bk] * (1.f / 4096.f);
    float mask = 1.f / (1.f + expf(-mean));
    out_slots[bk*256 + t] = g_slots[bk*256 + t] * mask + prev[bk*256 + t] * (1.f - mask);
}

// ---------------- launch ----------------
extern "C" void kernel_launch(void* const* d_in, const int* in_sizes, int n_in,
                              void* d_out, int out_size) {
    const float* features = (const float*)d_in[0];
    const float* prev     = (const float*)d_in[1];
    const float* gin      = (const float*)d_in[2];
    const float* bin      = (const float*)d_in[3];
    const float* gs       = (const float*)d_in[4];
    const float* bs       = (const float*)d_in[5];
    const float* gm       = (const float*)d_in[6];
    const float* bm       = (const float*)d_in[7];
    const float* Wq       = (const float*)d_in[8];
    const float* Wk       = (const float*)d_in[9];
    const float* Wv       = (const float*)d_in[10];
    const float* Wih      = (const float*)d_in[11];
    const float* Whh      = (const float*)d_in[12];
    const float* bih      = (const float*)d_in[13];
    const float* bhh      = (const float*)d_in[14];
    const float* W1       = (const float*)d_in[15];
    const float* b1       = (const float*)d_in[16];
    const float* W2       = (const float*)d_in[17];
    const float* b2       = (const float*)d_in[18];

    float* out_slots = (float*)d_out;
    float* out_attn  = out_slots + BB*KSLOT*DS;

    const size_t attn_smem = (size_t)ATTN_SMEM_FLOATS * sizeof(float);
    cudaFuncSetAttribute((const void*)attn_pass<false>, cudaFuncAttributeMaxDynamicSharedMemorySize, (int)attn_smem);
    cudaFuncSetAttribute((const void*)attn_pass<true>,  cudaFuncAttributeMaxDynamicSharedMemorySize, (int)attn_smem);
    cudaFuncSetAttribute((const void*)gemm_mma, cudaFuncAttributeMaxDynamicSharedMemorySize, GEMM_SMEM);

    // prep
    prep_wc<<<512, 256>>>(Wk, Wv, gin, bin);
    prep_wc_split<<<(512*DF + 255)/256, 256>>>();
    prep_transpose<<<(768*256 + 255)/256, 256>>>(Wq, Wih, Whh, W1, W2, prev);

    // phase A: fused LN stats + fp16 cast, then fp16 tensor GEMM
    row_stats_split<<<NROWS/8, 256>>>(features);
    gemm_mma<<<dim3(2, NROWS/128), 256, GEMM_SMEM>>>();

    // phase B: 3 slot-attention iterations
    for (int it = 0; it < 3; it++) {
        slot_q<<<BB*KSLOT, 256>>>(gs, bs);
        attn_pass<false><<<dim3(BB, CHUNKS), 256, attn_smem>>>(nullptr);
        gru_gemm<<<BB*24, 256>>>(bih, bhh);
        gru_mlp<<<BB*KSLOT, 256>>>(gm, bm, b1, b2);
    }

    // final attention + blend
    slot_q<<<BB*KSLOT, 256>>>(gs, bs);
    attn_pass<true><<<dim3(BB, CHUNKS), 256, attn_smem>>>(out_attn);
    finalize<<<BB*KSLOT, 256>>>(prev, out_slots);

    (void)in_sizes; (void)n_in; (void)out_size;
}

// round 9
// speedup vs baseline: 2.2497x; 1.0171x over previous
#include <cuda_runtime.h>
#include <cuda_fp16.h>
#include <cstdint>
#include <math.h>

// ---------------- problem constants ----------------
#define BB 32
#define NN 4096
#define DF 768
#define DS 256
#define KSLOT 8
#define NROWS (BB*NN)        // 131072
#define SCALE_F 0.0625f      // 256^-0.5
#define EPS_ATTN 1e-8f

// ---------------- scratch (device globals; no allocations allowed) ----------------
static __device__ float g_mean[NROWS];
static __device__ float g_rstd[NROWS];
static __device__ __align__(16) __half g_Fh[(size_t)NROWS*DF];          // 201 MB
static __device__ __align__(16) __half g_k[(size_t)NROWS*DS];           // 67 MB
static __device__ __align__(16) __half g_v[(size_t)NROWS*DS];           // 67 MB
static __device__ __align__(16) __half g_WcH[512*DF];                   // fp16(Wc)
static __device__ float g_csum[512];
static __device__ float g_cbias[512];
static __device__ float g_WqT[DS*DS];
static __device__ float g_WihT[DS*768];
static __device__ float g_WhhT[DS*768];
static __device__ float g_W1T[DS*DS];
static __device__ float g_W2T[DS*DS];
static __device__ float g_q[BB*KSLOT*DS];
static __device__ float g_slots[BB*KSLOT*DS];
static __device__ float g_U[BB*KSLOT*DS];
static __device__ float g_S[BB*KSLOT];
static __device__ float g_gi[BB*KSLOT*768];
static __device__ float g_gh[BB*KSLOT*768];

// ---------------- helpers ----------------
__device__ __forceinline__ uint32_t s2u(const void* p) {
    uint32_t r;
    asm("{ .reg .u64 t; cvta.to.shared.u64 t, %1; cvt.u32.u64 %0, t; }" : "=r"(r) : "l"(p));
    return r;
}
__device__ __forceinline__ void cpa16(uint32_t dst, const void* src) {
    asm volatile("cp.async.cg.shared.global [%0], [%1], 16;" :: "r"(dst), "l"(src));
}
#define CP_COMMIT() asm volatile("cp.async.commit_group;" ::: "memory")
#define CP_WAIT2()  asm volatile("cp.async.wait_group 2;" ::: "memory")

#define MMA16816(C, A, B) \
    asm volatile("mma.sync.aligned.m16n8k16.row.col.f32.f16.f16.f32 " \
        "{%0,%1,%2,%3}, {%4,%5,%6,%7}, {%8,%9}, {%0,%1,%2,%3};" \
        : "+f"((C)[0]), "+f"((C)[1]), "+f"((C)[2]), "+f"((C)[3]) \
        : "r"((A)[0]), "r"((A)[1]), "r"((A)[2]), "r"((A)[3]), "r"((B)[0]), "r"((B)[1]))

// ---------------- prep: combined weights (fp32 colsums + direct fp16 cast) ----------------
__global__ void __launch_bounds__(256) prep_wc(const float* __restrict__ Wk,
                                               const float* __restrict__ Wv,
                                               const float* __restrict__ gin,
                                               const float* __restrict__ bin) {
    int j = blockIdx.x;             // 0..511  (0..255 -> k, 256..511 -> v)
    const float* W = (j < 256) ? (Wk + (size_t)j*DF) : (Wv + (size_t)(j-256)*DF);
    int t = threadIdx.x;
    float s = 0.f, bsum = 0.f;
    for (int f = t; f < DF; f += 256) {
        float w  = W[f];
        float wc = w * gin[f];
        g_WcH[(size_t)j*DF + f] = __float2half_rn(wc);
        s += wc; bsum += w * bin[f];
    }
    __shared__ float r1[8], r2[8];
    for (int o = 16; o; o >>= 1) { s += __shfl_down_sync(0xffffffffu, s, o); bsum += __shfl_down_sync(0xffffffffu, bsum, o); }
    if ((t & 31) == 0) { r1[t>>5] = s; r2[t>>5] = bsum; }
    __syncthreads();
    if (t == 0) {
        float ts = 0.f, tb = 0.f;
        #pragma unroll
        for (int w = 0; w < 8; w++) { ts += r1[w]; tb += r2[w]; }
        g_csum[j] = ts; g_cbias[j] = tb;
    }
}

// ---------------- prep: transposed small weights + copy slots ----------------
__global__ void prep_transpose(const float* __restrict__ Wq,
                               const float* __restrict__ Wih,
                               const float* __restrict__ Whh,
                               const float* __restrict__ W1,
                               const float* __restrict__ W2,
                               const float* __restrict__ prev) {
    int i = blockIdx.x * blockDim.x + threadIdx.x;
    if (i < 768*256) {
        int g = i / 256, d = i % 256;
        g_WihT[d*768 + g] = Wih[i];
        g_WhhT[d*768 + g] = Whh[i];
    }
    if (i < 256*256) {
        int r = i / 256, c = i % 256;
        g_WqT[c*256 + r] = Wq[i];
        g_W1T[c*256 + r] = W1[i];
        g_W2T[c*256 + r] = W2[i];
    }
    if (i < BB*KSLOT*DS) g_slots[i] = prev[i];
}

// ---------------- LN stats + fp16 cast of F (one streaming pass) ----------------
__global__ void __launch_bounds__(256) row_stats_split(const float* __restrict__ F) {
    int w = threadIdx.x >> 5, l = threadIdx.x & 31;
    int row = blockIdx.x * 8 + w;
    const float4* x = (const float4*)(F + (size_t)row * DF);
    float4 a[6];
    float s = 0.f, s2 = 0.f;
    #pragma unroll
    for (int j = 0; j < 6; j++) {
        a[j] = x[l + 32*j];
        s  += a[j].x + a[j].y + a[j].z + a[j].w;
        s2 += a[j].x*a[j].x + a[j].y*a[j].y + a[j].z*a[j].z + a[j].w*a[j].w;
    }
    uint2* hdst = (uint2*)(g_Fh + (size_t)row * DF);
    #pragma unroll
    for (int j = 0; j < 6; j++) {
        float4 v = a[j];
        __half2 h0 = __floats2half2_rn(v.x, v.y);
        __half2 h1 = __floats2half2_rn(v.z, v.w);
        hdst[l + 32*j] = make_uint2(*(uint32_t*)&h0, *(uint32_t*)&h1);
    }
    for (int o = 16; o; o >>= 1) {
        s  += __shfl_down_sync(0xffffffffu, s, o);
        s2 += __shfl_down_sync(0xffffffffu, s2, o);
    }
    if (l == 0) {
        float m   = s * (1.f/768.f);
        float var = s2 * (1.f/768.f) - m*m;
        g_mean[row] = m;
        g_rstd[row] = rsqrtf(var + 1e-5f);
    }
}

// ---------------- tensor-core GEMM (fp16 single-pass, 3-stage cp.async) ----------------
// C[131072 x 512] = F @ Wc^T, fp32 accum. A = fp16(F), B = fp16(Wc).
// CTA 128x256, BK=32, 8 warps (2x4 grid, warp tile 64x64), 3-stage cp.async pipeline.
#define PADB 80                      // bytes per smem row (32 halfs data + pad); odd 16B mult
#define TILE_A (128*PADB)            // 10240
#define TILE_Bb (256*PADB)           // 20480
#define STAGE_BYTES (TILE_A + TILE_Bb)      // 30720: A, B
#define NSTAGE 3
#define GEMM_SMEM (NSTAGE*STAGE_BYTES)      // 92160
#define NCHUNK (DF/32)               // 24

__global__ void __launch_bounds__(256) gemm_mma(void) {
    extern __shared__ __align__(16) char smd[];
    __shared__ float s_cs[256], s_cb[256];

    const int tid = threadIdx.x;
    const int wid = tid >> 5, lane = tid & 31;
    const int wm = wid & 1, wn = wid >> 1;      // warp grid 2 x 4, tile 64x64
    const int bn = blockIdx.x * 256;
    const int bm = blockIdx.y * 128;

    s_cs[tid] = g_csum[bn + tid];
    s_cb[tid] = g_cbias[bn + tid];

    const uint32_t smem_u = s2u(smd);
    const int arow = tid >> 2;           // 0..63
    const int aq   = tid & 3;            // 16B quarter within 64B row-chunk

    auto stage = [&](int buf, int c) {
        const int kb = c * 32;
        uint32_t sb = smem_u + buf * STAGE_BYTES;
        const __half* fa = g_Fh + (size_t)(bm + arow) * DF + kb + aq * 8;
        uint32_t da = sb + arow * PADB + aq * 16;
        cpa16(da,            fa);
        cpa16(da + 64*PADB,  fa + (size_t)64*DF);
        const __half* bh = g_WcH + (size_t)(bn + arow) * DF + kb + aq * 8;
        uint32_t db = sb + TILE_A + arow * PADB + aq * 16;
        #pragma unroll
        for (int j = 0; j < 4; j++)
            cpa16(db + j*64*PADB, bh + (size_t)j*64*DF);
    };

    float acc[4][8][4];
    #pragma unroll
    for (int mi = 0; mi < 4; mi++)
        #pragma unroll
        for (int ni = 0; ni < 8; ni++)
            #pragma unroll
            for (int e = 0; e < 4; e++) acc[mi][ni][e] = 0.f;

    stage(0, 0); CP_COMMIT();
    stage(1, 1); CP_COMMIT();
    stage(2, 2); CP_COMMIT();

    const int fr = lane >> 2;            // 0..7
    const int fk = (lane & 3) * 4;       // byte offset of k-pair

    int buf = 0;
    #pragma unroll 1
    for (int c = 0; c < NCHUNK; c++) {
        CP_WAIT2();
        __syncthreads();

        const char* Aa = smd + buf * STAGE_BYTES;
        const char* Bh = Aa + TILE_A;

        #pragma unroll
        for (int ks = 0; ks < 2; ks++) {
            uint32_t af[4][4], bfr[8][2];
            #pragma unroll
            for (int mi = 0; mi < 4; mi++) {
                uint32_t o = (wm*64 + mi*16 + fr) * PADB + ks*32 + fk;
                af[mi][0] = *(const uint32_t*)(Aa + o);
                af[mi][1] = *(const uint32_t*)(Aa + o + 8*PADB);
                af[mi][2] = *(const uint32_t*)(Aa + o + 16);
                af[mi][3] = *(const uint32_t*)(Aa + o + 8*PADB + 16);
            }
            #pragma unroll
            for (int ni = 0; ni < 8; ni++) {
                uint32_t o = (wn*64 + ni*8 + fr) * PADB + ks*32 + fk;
                bfr[ni][0] = *(const uint32_t*)(Bh + o);
                bfr[ni][1] = *(const uint32_t*)(Bh + o + 16);
            }
            #pragma unroll
            for (int mi = 0; mi < 4; mi++)
                #pragma unroll
                for (int ni = 0; ni < 8; ni++)
                    MMA16816(acc[mi][ni], af[mi], bfr[ni]);
        }

        __syncthreads();
        if (c + NSTAGE < NCHUNK) stage(buf, c + NSTAGE);
        CP_COMMIT();
        buf = (buf == NSTAGE-1) ? 0 : buf + 1;
    }

    // ---- epilogue: LN fold + fp16 store to k/v ----
    __half* base = (blockIdx.x == 0) ? g_k : g_v;
    #pragma unroll
    for (int mi = 0; mi < 4; mi++) {
        int r1 = bm + wm*64 + mi*16 + fr;
        int r2 = r1 + 8;
        float rm1 = g_mean[r1], rs1 = g_rstd[r1];
        float rm2 = g_mean[r2], rs2 = g_rstd[r2];
        #pragma unroll
        for (int ni = 0; ni < 8; ni++) {
            int cl = wn*64 + ni*8 + (lane & 3)*2;   // local col in [0,256)
            float cs0 = s_cs[cl], cs1 = s_cs[cl+1];
            float cb0 = s_cb[cl], cb1 = s_cb[cl+1];
            __half2* d1 = (__half2*)(base + (size_t)r1*DS + cl);
            __half2* d2 = (__half2*)(base + (size_t)r2*DS + cl);
            *d1 = __floats2half2_rn(
                rs1*(acc[mi][ni][0] - rm1*cs0) + cb0,
                rs1*(acc[mi][ni][1] - rm1*cs1) + cb1);
            *d2 = __floats2half2_rn(
                rs2*(acc[mi][ni][2] - rm2*cs0) + cb0,
                rs2*(acc[mi][ni][3] - rm2*cs1) + cb1);
        }
    }
}

// ---------------- per-slot q = LN(slots) @ Wq^T (also zeroes U/S accumulators) ----------------
__global__ void __launch_bounds__(256) slot_q(const float* __restrict__ gs, const float* __restrict__ bs) {
    int row = blockIdx.x;
    int t = threadIdx.x;
    __shared__ float sn[256];
    __shared__ float r1[8], r2[8];
    __shared__ float smv[2];
    g_U[row*256 + t] = 0.f;
    if (t == 0) g_S[row] = 0.f;
    float x = g_slots[row*256 + t];
    float s = x, s2 = x*x;
    for (int o = 16; o; o >>= 1) { s += __shfl_down_sync(0xffffffffu, s, o); s2 += __shfl_down_sync(0xffffffffu, s2, o); }
    if ((t & 31) == 0) { r1[t>>5] = s; r2[t>>5] = s2; }
    __syncthreads();
    if (t == 0) {
        float ts = 0.f, ts2 = 0.f;
        #pragma unroll
        for (int w = 0; w < 8; w++) { ts += r1[w]; ts2 += r2[w]; }
        float m = ts * (1.f/256.f);
        float var = ts2 * (1.f/256.f) - m*m;
        smv[0] = m; smv[1] = rsqrtf(var + 1e-5f);
    }
    __syncthreads();
    sn[t] = (x - smv[0]) * smv[1] * gs[t] + bs[t];
    __syncthreads();
    float acc = 0.f;
    #pragma unroll 4
    for (int d = 0; d < 256; d++) acc += sn[d] * g_WqT[d*256 + t];
    g_q[row*256 + t] = acc;
}

// ---------------- fused attention sweep (k/v fp16 in GMEM, fp32 in smem) ----------------
#define ATILE 32
#define KPAD 260
#define CHUNKS 32
#define ATTN_SMEM_FLOATS (8*256 + 2*ATILE*KPAD + 2*8*36)

template <bool FINAL>
__global__ void __launch_bounds__(256) attn_pass(float* __restrict__ out_attn) {
    extern __shared__ float sm[];
    float* qs = sm;
    float* kt = qs + 8*256;
    float* vt = kt + ATILE*KPAD;
    float* Ls = vt + ATILE*KPAD;
    float* ps = Ls + 8*36;

    int b  = blockIdx.x;
    int ch = blockIdx.y;
    int t  = threadIdx.x;

    for (int i = t; i < 8*256; i += 256) qs[i] = g_q[b*2048 + i] * SCALE_F;

    const int n0 = ch * (NN / CHUNKS);
    float regU[8], regS[8];
    #pragma unroll
    for (int h = 0; h < 8; h++) { regU[h] = 0.f; regS[h] = 0.f; }

    const int hq = t >> 5;
    const int nl = t & 31;

    #pragma unroll 1
    for (int tile = 0; tile < (NN/CHUNKS)/ATILE; tile++) {
        int nbase = n0 + tile * ATILE;
        __syncthreads();
        const __half* kg = g_k + ((size_t)b*NN + nbase) * DS;
        const __half* vg = g_v + ((size_t)b*NN + nbase) * DS;
        for (int i = t; i < ATILE*32; i += 256) {
            int n = i >> 5; int d8 = (i & 31) << 3;
            uint4 raw = *(const uint4*)(kg + n*DS + d8);
            __half2* hp = (__half2*)&raw;
            float2 f0 = __half22float2(hp[0]), f1 = __half22float2(hp[1]);
            float2 f2 = __half22float2(hp[2]), f3 = __half22float2(hp[3]);
            *(float4*)(kt + n*KPAD + d8)     = make_float4(f0.x, f0.y, f1.x, f1.y);
            *(float4*)(kt + n*KPAD + d8 + 4) = make_float4(f2.x, f2.y, f3.x, f3.y);
            if (!FINAL) {
                uint4 rv = *(const uint4*)(vg + n*DS + d8);
                __half2* vp = (__half2*)&rv;
                float2 g0 = __half22float2(vp[0]), g1 = __half22float2(vp[1]);
                float2 g2 = __half22float2(vp[2]), g3 = __half22float2(vp[3]);
                *(float4*)(vt + n*KPAD + d8)     = make_float4(g0.x, g0.y, g1.x, g1.y);
                *(float4*)(vt + n*KPAD + d8 + 4) = make_float4(g2.x, g2.y, g3.x, g3.y);
            }
        }
        __syncthreads();

        {
            float acc = 0.f;
            const float* qrow = qs + hq*256;
            const float* krow = kt + nl*KPAD;
            #pragma unroll 8
            for (int d = 0; d < 256; d += 4) {
                float4 qv = *(const float4*)(qrow + d);
                float4 kv = *(const float4*)(krow + d);
                acc += qv.x*kv.x + qv.y*kv.y + qv.z*kv.z + qv.w*kv.w;
            }
            Ls[hq*36 + nl] = acc;
        }
        __syncthreads();

        if (t < 32) {
            float l[8], m = -1e30f;
            #pragma unroll
            for (int h = 0; h < 8; h++) { l[h] = Ls[h*36 + t]; m = fmaxf(m, l[h]); }
            float ssum = 0.f;
            #pragma unroll
            for (int h = 0; h < 8; h++) { l[h] = expf(l[h] - m); ssum += l[h]; }
            float inv = 1.f / ssum;
            #pragma unroll
            for (int h = 0; h < 8; h++) {
                float p = l[h] * inv;
                ps[h*36 + t] = p;
                regS[h] += p;
                if (FINAL)
                    out_attn[((size_t)b*KSLOT + h)*NN + nbase + t] = p;
            }
        }
        __syncthreads();

        if (!FINAL) {
            #pragma unroll 4
            for (int n = 0; n < ATILE; n++) {
                float vv = vt[n*KPAD + t];
                #pragma unroll
                for (int h = 0; h < 8; h++) regU[h] += ps[h*36 + n] * vv;
            }
        }
    }

    if (!FINAL) {
        #pragma unroll
        for (int h = 0; h < 8; h++)
            atomicAdd(&g_U[((size_t)b*KSLOT + h)*DS + t], regU[h]);
    }
    if (t < 32) {
        #pragma unroll
        for (int h = 0; h < 8; h++) {
            float v = regS[h];
            for (int o = 16; o; o >>= 1) v += __shfl_down_sync(0xffffffffu, v, o);
            if (t == 0) atomicAdd(&g_S[b*KSLOT + h], v);
        }
    }
}

// ---------------- GRU gate GEMMs ----------------
__global__ void __launch_bounds__(256) gru_gemm(const float* __restrict__ bih, const float* __restrict__ bhh) {
    int blk = blockIdx.x;
    int b = blk / 24, gc = blk % 24;
    __shared__ float su[8*256], ss[8*256];
    int t = threadIdx.x;
    for (int i = t; i < 2048; i += 256) {
        int k = i >> 8;
        su[i] = g_U[b*2048 + i] / (g_S[b*8 + k] + EPS_ATTN);
        ss[i] = g_slots[b*2048 + i];
    }
    __syncthreads();
    int g = gc*32 + (t & 31);
    int k = t >> 5;
    float gi = bih[g], gh = bhh[g];
    const float* su_k = su + k*256;
    const float* ss_k = ss + k*256;
    #pragma unroll 4
    for (int d = 0; d < 256; d++) {
        gi += su_k[d] * g_WihT[d*768 + g];
        gh += ss_k[d] * g_WhhT[d*768 + g];
    }
    g_gi[((size_t)b*8 + k)*768 + g] = gi;
    g_gh[((size_t)b*8 + k)*768 + g] = gh;
}

// ---------------- GRU combine + LN + MLP + next-iteration q (fused slot_q tail) ----------------
__global__ void __launch_bounds__(256) gru_mlp(const float* __restrict__ gm, const float* __restrict__ bm,
                                               const float* __restrict__ b1, const float* __restrict__ b2,
                                               const float* __restrict__ gs, const float* __restrict__ bs) {
    int bk = blockIdx.x;
    int t = threadIdx.x;
    const float* gi = g_gi + (size_t)bk*768;
    const float* gh = g_gh + (size_t)bk*768;
    float sl = g_slots[bk*256 + t];
    float r  = 1.f / (1.f + expf(-(gi[t]       + gh[t])));
    float z  = 1.f / (1.f + expf(-(gi[256 + t] + gh[256 + t])));
    float nn = tanhf(gi[512 + t] + r * gh[512 + t]);
    float h  = (1.f - z) * nn + z * sl;

    __shared__ float hn[256], ms[256];
    __shared__ float r1[8], r2[8];
    __shared__ float smv[2];
    float s = h, s2 = h*h;
    for (int o = 16; o; o >>= 1) { s += __shfl_down_sync(0xffffffffu, s, o); s2 += __shfl_down_sync(0xffffffffu, s2, o); }
    if ((t & 31) == 0) { r1[t>>5] = s; r2[t>>5] = s2; }
    __syncthreads();
    if (t == 0) {
        float ts = 0.f, ts2 = 0.f;
        #pragma unroll
        for (int w = 0; w < 8; w++) { ts += r1[w]; ts2 += r2[w]; }
        float m = ts * (1.f/256.f);
        float var = ts2 * (1.f/256.f) - m*m;
        smv[0] = m; smv[1] = rsqrtf(var + 1e-5f);
    }
    __syncthreads();
    hn[t] = (h - smv[0]) * smv[1] * gm[t] + bm[t];
    __syncthreads();
    float acc = b1[t];
    #pragma unroll 4
    for (int d = 0; d < 256; d++) acc += hn[d] * g_W1T[d*256 + t];
    ms[t] = fmaxf(acc, 0.f);
    __syncthreads();
    float o = h + b2[t];
    #pragma unroll 4
    for (int j = 0; j < 256; j++) o += ms[j] * g_W2T[j*256 + t];
    g_slots[bk*256 + t] = o;

    // ---- fused slot_q tail: zero U/S, q = LN(new slots) @ Wq^T ----
    g_U[bk*256 + t] = 0.f;
    if (t == 0) g_S[bk] = 0.f;
    __syncthreads();
    s = o; s2 = o*o;
    for (int off = 16; off; off >>= 1) { s += __shfl_down_sync(0xffffffffu, s, off); s2 += __shfl_down_sync(0xffffffffu, s2, off); }
    if ((t & 31) == 0) { r1[t>>5] = s; r2[t>>5] = s2; }
    __syncthreads();
    if (t == 0) {
        float ts = 0.f, ts2 = 0.f;
        #pragma unroll
        for (int w = 0; w < 8; w++) { ts += r1[w]; ts2 += r2[w]; }
        float m = ts * (1.f/256.f);
        float var = ts2 * (1.f/256.f) - m*m;
        smv[0] = m; smv[1] = rsqrtf(var + 1e-5f);
    }
    __syncthreads();
    hn[t] = (o - smv[0]) * smv[1] * gs[t] + bs[t];
    __syncthreads();
    float qa = 0.f;
    #pragma unroll 4
    for (int d = 0; d < 256; d++) qa += hn[d] * g_WqT[d*256 + t];
    g_q[bk*256 + t] = qa;
}

// ---------------- final confidence blend ----------------
__global__ void __launch_bounds__(256) finalize(const float* __restrict__ prev, float* __restrict__ out_slots) {
    int bk = blockIdx.x;
    int t = threadIdx.x;
    float mean = g_S[bk] * (1.f / 4096.f);
    float mask = 1.f / (1.f + expf(-mean));
    out_slots[bk*256 + t] = g_slots[bk*256 + t] * mask + prev[bk*256 + t] * (1.f - mask);
}

// ---------------- launch ----------------
extern "C" void kernel_launch(void* const* d_in, const int* in_sizes, int n_in,
                              void* d_out, int out_size) {
    const float* features = (const float*)d_in[0];
    const float* prev     = (const float*)d_in[1];
    const float* gin      = (const float*)d_in[2];
    const float* bin      = (const float*)d_in[3];
    const float* gs       = (const float*)d_in[4];
    const float* bs       = (const float*)d_in[5];
    const float* gm       = (const float*)d_in[6];
    const float* bm       = (const float*)d_in[7];
    const float* Wq       = (const float*)d_in[8];
    const float* Wk       = (const float*)d_in[9];
    const float* Wv       = (const float*)d_in[10];
    const float* Wih      = (const float*)d_in[11];
    const float* Whh      = (const float*)d_in[12];
    const float* bih      = (const float*)d_in[13];
    const float* bhh      = (const float*)d_in[14];
    const float* W1       = (const float*)d_in[15];
    const float* b1       = (const float*)d_in[16];
    const float* W2       = (const float*)d_in[17];
    const float* b2       = (const float*)d_in[18];

    float* out_slots = (float*)d_out;
    float* out_attn  = out_slots + BB*KSLOT*DS;

    const size_t attn_smem = (size_t)ATTN_SMEM_FLOATS * sizeof(float);
    cudaFuncSetAttribute((const void*)attn_pass<false>, cudaFuncAttributeMaxDynamicSharedMemorySize, (int)attn_smem);
    cudaFuncSetAttribute((const void*)attn_pass<true>,  cudaFuncAttributeMaxDynamicSharedMemorySize, (int)attn_smem);
    cudaFuncSetAttribute((const void*)gemm_mma, cudaFuncAttributeMaxDynamicSharedMemorySize, GEMM_SMEM);

    // prep (2 launches)
    prep_wc<<<512, 256>>>(Wk, Wv, gin, bin);
    prep_transpose<<<(768*256 + 255)/256, 256>>>(Wq, Wih, Whh, W1, W2, prev);

    // phase A: fused LN stats + fp16 cast (launch 3), fp16 tensor GEMM (launch 4 -> profiled)
    row_stats_split<<<NROWS/8, 256>>>(features);
    gemm_mma<<<dim3(2, NROWS/128), 256, GEMM_SMEM>>>();

    // initial q from prev slots (+ zero U/S)
    slot_q<<<BB*KSLOT, 256>>>(gs, bs);

    // phase B: 3 slot-attention iterations (gru_mlp computes next q + zeroes U/S)
    for (int it = 0; it < 3; it++) {
        attn_pass<false><<<dim3(BB, CHUNKS), 256, attn_smem>>>(nullptr);
        gru_gemm<<<BB*24, 256>>>(bih, bhh);
        gru_mlp<<<BB*KSLOT, 256>>>(gm, bm, b1, b2, gs, bs);
    }

    // final attention + blend
    attn_pass<true><<<dim3(BB, CHUNKS), 256, attn_smem>>>(out_attn);
    finalize<<<BB*KSLOT, 256>>>(prev, out_slots);

    (void)in_sizes; (void)n_in; (void)out_size;
}

// round 10
// speedup vs baseline: 2.6401x; 1.1735x over previous
#include <cuda_runtime.h>
#include <cuda_fp16.h>
#include <cstdint>
#include <math.h>

// ---------------- problem constants ----------------
#define BB 32
#define NN 4096
#define DF 768
#define DS 256
#define KSLOT 8
#define NROWS (BB*NN)        // 131072
#define SCALE_F 0.0625f      // 256^-0.5
#define EPS_ATTN 1e-8f

// ---------------- scratch (device globals; no allocations allowed) ----------------
static __device__ float g_mean[NROWS];
static __device__ float g_rstd[NROWS];
static __device__ __align__(16) __half g_Fh[(size_t)NROWS*DF];          // 201 MB
static __device__ __align__(16) __half g_k[(size_t)NROWS*DS];           // 67 MB
static __device__ __align__(16) __half g_v[(size_t)NROWS*DS];           // 67 MB
static __device__ __align__(16) __half g_WcH[512*DF];                   // fp16(Wc)
static __device__ float g_csum[512];
static __device__ float g_cbias[512];
static __device__ float g_WqT[DS*DS];
static __device__ float g_WihT[DS*768];
static __device__ float g_WhhT[DS*768];
static __device__ float g_W1T[DS*DS];
static __device__ float g_W2T[DS*DS];
static __device__ float g_q[BB*KSLOT*DS];
static __device__ float g_slots[BB*KSLOT*DS];
static __device__ float g_U[BB*KSLOT*DS];
static __device__ float g_S[BB*KSLOT];
static __device__ float g_gi[BB*KSLOT*768];
static __device__ float g_gh[BB*KSLOT*768];

// ---------------- helpers ----------------
__device__ __forceinline__ uint32_t s2u(const void* p) {
    uint32_t r;
    asm("{ .reg .u64 t; cvta.to.shared.u64 t, %1; cvt.u32.u64 %0, t; }" : "=r"(r) : "l"(p));
    return r;
}
__device__ __forceinline__ void cpa16(uint32_t dst, const void* src) {
    asm volatile("cp.async.cg.shared.global [%0], [%1], 16;" :: "r"(dst), "l"(src));
}
#define CP_COMMIT() asm volatile("cp.async.commit_group;" ::: "memory")
#define CP_WAIT3()  asm volatile("cp.async.wait_group 3;" ::: "memory")
#define CP_WAIT1()  asm volatile("cp.async.wait_group 1;" ::: "memory")

#define MMA16816(C, A, B) \
    asm volatile("mma.sync.aligned.m16n8k16.row.col.f32.f16.f16.f32 " \
        "{%0,%1,%2,%3}, {%4,%5,%6,%7}, {%8,%9}, {%0,%1,%2,%3};" \
        : "+f"((C)[0]), "+f"((C)[1]), "+f"((C)[2]), "+f"((C)[3]) \
        : "r"((A)[0]), "r"((A)[1]), "r"((A)[2]), "r"((A)[3]), "r"((B)[0]), "r"((B)[1]))

// ---------------- prep: combined weights (fp32 colsums + direct fp16 cast) ----------------
__global__ void __launch_bounds__(256) prep_wc(const float* __restrict__ Wk,
                                               const float* __restrict__ Wv,
                                               const float* __restrict__ gin,
                                               const float* __restrict__ bin) {
    int j = blockIdx.x;
    const float* W = (j < 256) ? (Wk + (size_t)j*DF) : (Wv + (size_t)(j-256)*DF);
    int t = threadIdx.x;
    float s = 0.f, bsum = 0.f;
    for (int f = t; f < DF; f += 256) {
        float w  = W[f];
        float wc = w * gin[f];
        g_WcH[(size_t)j*DF + f] = __float2half_rn(wc);
        s += wc; bsum += w * bin[f];
    }
    __shared__ float r1[8], r2[8];
    for (int o = 16; o; o >>= 1) { s += __shfl_down_sync(0xffffffffu, s, o); bsum += __shfl_down_sync(0xffffffffu, bsum, o); }
    if ((t & 31) == 0) { r1[t>>5] = s; r2[t>>5] = bsum; }
    __syncthreads();
    if (t == 0) {
        float ts = 0.f, tb = 0.f;
        #pragma unroll
        for (int w = 0; w < 8; w++) { ts += r1[w]; tb += r2[w]; }
        g_csum[j] = ts; g_cbias[j] = tb;
    }
}

// ---------------- prep: transposed small weights + copy slots ----------------
__global__ void prep_transpose(const float* __restrict__ Wq,
                               const float* __restrict__ Wih,
                               const float* __restrict__ Whh,
                               const float* __restrict__ W1,
                               const float* __restrict__ W2,
                               const float* __restrict__ prev) {
    int i = blockIdx.x * blockDim.x + threadIdx.x;
    if (i < 768*256) {
        int g = i / 256, d = i % 256;
        g_WihT[d*768 + g] = Wih[i];
        g_WhhT[d*768 + g] = Whh[i];
    }
    if (i < 256*256) {
        int r = i / 256, c = i % 256;
        g_WqT[c*256 + r] = Wq[i];
        g_W1T[c*256 + r] = W1[i];
        g_W2T[c*256 + r] = W2[i];
    }
    if (i < BB*KSLOT*DS) g_slots[i] = prev[i];
}

// ---------------- LN stats + fp16 cast of F (one streaming pass) ----------------
__global__ void __launch_bounds__(256) row_stats_split(const float* __restrict__ F) {
    int w = threadIdx.x >> 5, l = threadIdx.x & 31;
    int row = blockIdx.x * 8 + w;
    const float4* x = (const float4*)(F + (size_t)row * DF);
    float4 a[6];
    float s = 0.f, s2 = 0.f;
    #pragma unroll
    for (int j = 0; j < 6; j++) {
        a[j] = x[l + 32*j];
        s  += a[j].x + a[j].y + a[j].z + a[j].w;
        s2 += a[j].x*a[j].x + a[j].y*a[j].y + a[j].z*a[j].z + a[j].w*a[j].w;
    }
    uint2* hdst = (uint2*)(g_Fh + (size_t)row * DF);
    #pragma unroll
    for (int j = 0; j < 6; j++) {
        float4 v = a[j];
        __half2 h0 = __floats2half2_rn(v.x, v.y);
        __half2 h1 = __floats2half2_rn(v.z, v.w);
        hdst[l + 32*j] = make_uint2(*(uint32_t*)&h0, *(uint32_t*)&h1);
    }
    for (int o = 16; o; o >>= 1) {
        s  += __shfl_down_sync(0xffffffffu, s, o);
        s2 += __shfl_down_sync(0xffffffffu, s2, o);
    }
    if (l == 0) {
        float m   = s * (1.f/768.f);
        float var = s2 * (1.f/768.f) - m*m;
        g_mean[row] = m;
        g_rstd[row] = rsqrtf(var + 1e-5f);
    }
}

// ---------------- tensor-core GEMM (fp16 single-pass, 4-stage cp.async, 2 CTA/SM) ----------------
// CTA 128x128, 8 warps (2x4 grid, warp tile 64x32), grid (4, 1024).
#define GPADB 80                     // bytes per smem row
#define GTILE (128*GPADB)            // 10240
#define GSTAGE (2*GTILE)             // 20480: A, B
#define GNSTAGE 4
#define GEMM_SMEM (GNSTAGE*GSTAGE)   // 81920
#define NCHUNK (DF/32)               // 24

__global__ void __launch_bounds__(256, 2) gemm_mma(void) {
    extern __shared__ __align__(16) char smd[];
    __shared__ float s_cs[128], s_cb[128];

    const int tid = threadIdx.x;
    const int wid = tid >> 5, lane = tid & 31;
    const int wm = wid & 1, wn = wid >> 1;      // warp grid 2 x 4, tile 64x32
    const int bnG = blockIdx.x * 128;
    const int bm = blockIdx.y * 128;

    if (tid < 128) { s_cs[tid] = g_csum[bnG + tid]; s_cb[tid] = g_cbias[bnG + tid]; }

    const uint32_t smem_u = s2u(smd);
    const int arow = tid >> 2;           // 0..63
    const int aq   = tid & 3;

    auto stage = [&](int buf, int c) {
        const int kb = c * 32;
        uint32_t sb = smem_u + buf * GSTAGE;
        const __half* fa = g_Fh + (size_t)(bm + arow) * DF + kb + aq * 8;
        uint32_t da = sb + arow * GPADB + aq * 16;
        cpa16(da,            fa);
        cpa16(da + 64*GPADB, fa + (size_t)64*DF);
        const __half* bh = g_WcH + (size_t)(bnG + arow) * DF + kb + aq * 8;
        uint32_t db = sb + GTILE + arow * GPADB + aq * 16;
        cpa16(db,            bh);
        cpa16(db + 64*GPADB, bh + (size_t)64*DF);
    };

    float acc[4][4][4];
    #pragma unroll
    for (int mi = 0; mi < 4; mi++)
        #pragma unroll
        for (int ni = 0; ni < 4; ni++)
            #pragma unroll
            for (int e = 0; e < 4; e++) acc[mi][ni][e] = 0.f;

    stage(0, 0); CP_COMMIT();
    stage(1, 1); CP_COMMIT();
    stage(2, 2); CP_COMMIT();
    stage(3, 3); CP_COMMIT();

    const int fr = lane >> 2;
    const int fk = (lane & 3) * 4;

    #pragma unroll 1
    for (int c = 0; c < NCHUNK; c++) {
        const int buf = c & 3;
        CP_WAIT3();
        __syncthreads();

        const char* Aa = smd + buf * GSTAGE;
        const char* Bb = Aa + GTILE;

        #pragma unroll
        for (int ks = 0; ks < 2; ks++) {
            uint32_t af[4][4], bfr[4][2];
            #pragma unroll
            for (int mi = 0; mi < 4; mi++) {
                uint32_t o = (wm*64 + mi*16 + fr) * GPADB + ks*32 + fk;
                af[mi][0] = *(const uint32_t*)(Aa + o);
                af[mi][1] = *(const uint32_t*)(Aa + o + 8*GPADB);
                af[mi][2] = *(const uint32_t*)(Aa + o + 16);
                af[mi][3] = *(const uint32_t*)(Aa + o + 8*GPADB + 16);
            }
            #pragma unroll
            for (int ni = 0; ni < 4; ni++) {
                uint32_t o = (wn*32 + ni*8 + fr) * GPADB + ks*32 + fk;
                bfr[ni][0] = *(const uint32_t*)(Bb + o);
                bfr[ni][1] = *(const uint32_t*)(Bb + o + 16);
            }
            #pragma unroll
            for (int mi = 0; mi < 4; mi++)
                #pragma unroll
                for (int ni = 0; ni < 4; ni++)
                    MMA16816(acc[mi][ni], af[mi], bfr[ni]);
        }

        __syncthreads();
        if (c + GNSTAGE < NCHUNK) stage(buf, c + GNSTAGE);
        CP_COMMIT();
    }

    // ---- epilogue: LN fold + fp16 store to k/v ----
    #pragma unroll
    for (int mi = 0; mi < 4; mi++) {
        int r1 = bm + wm*64 + mi*16 + fr;
        int r2 = r1 + 8;
        float rm1 = g_mean[r1], rs1 = g_rstd[r1];
        float rm2 = g_mean[r2], rs2 = g_rstd[r2];
        #pragma unroll
        for (int ni = 0; ni < 4; ni++) {
            int cl = wn*32 + ni*8 + (lane & 3)*2;   // local col [0,128)
            int colg = bnG + cl;
            float cs0 = s_cs[cl], cs1 = s_cs[cl+1];
            float cb0 = s_cb[cl], cb1 = s_cb[cl+1];
            __half* base;
            int coff;
            if (colg < 256) { base = g_k; coff = colg; }
            else            { base = g_v; coff = colg - 256; }
            __half2* d1 = (__half2*)(base + (size_t)r1*DS + coff);
            __half2* d2 = (__half2*)(base + (size_t)r2*DS + coff);
            *d1 = __floats2half2_rn(
                rs1*(acc[mi][ni][0] - rm1*cs0) + cb0,
                rs1*(acc[mi][ni][1] - rm1*cs1) + cb1);
            *d2 = __floats2half2_rn(
                rs2*(acc[mi][ni][2] - rm2*cs0) + cb0,
                rs2*(acc[mi][ni][3] - rm2*cs1) + cb1);
        }
    }
}

// ---------------- per-slot q = LN(slots) @ Wq^T (also zeroes U/S accumulators) ----------------
__global__ void __launch_bounds__(256) slot_q(const float* __restrict__ gs, const float* __restrict__ bs) {
    int row = blockIdx.x;
    int t = threadIdx.x;
    __shared__ float sn[256];
    __shared__ float r1[8], r2[8];
    __shared__ float smv[2];
    g_U[row*256 + t] = 0.f;
    if (t == 0) g_S[row] = 0.f;
    float x = g_slots[row*256 + t];
    float s = x, s2 = x*x;
    for (int o = 16; o; o >>= 1) { s += __shfl_down_sync(0xffffffffu, s, o); s2 += __shfl_down_sync(0xffffffffu, s2, o); }
    if ((t & 31) == 0) { r1[t>>5] = s; r2[t>>5] = s2; }
    __syncthreads();
    if (t == 0) {
        float ts = 0.f, ts2 = 0.f;
        #pragma unroll
        for (int w = 0; w < 8; w++) { ts += r1[w]; ts2 += r2[w]; }
        float m = ts * (1.f/256.f);
        float var = ts2 * (1.f/256.f) - m*m;
        smv[0] = m; smv[1] = rsqrtf(var + 1e-5f);
    }
    __syncthreads();
    sn[t] = (x - smv[0]) * smv[1] * gs[t] + bs[t];
    __syncthreads();
    float acc = 0.f;
    #pragma unroll 4
    for (int d = 0; d < 256; d++) acc += sn[d] * g_WqT[d*256 + t];
    g_q[row*256 + t] = acc;
}

// ---------------- fused attention sweep (k/v fp16 in smem via cp.async, double-buffered) ----------------
#define ATILE 32
#define KHPB 528                      // bytes per smem k/v row (264 halfs; 33x16B)
#define KT_B (ATILE*KHPB)             // 16896
#define KVBUF (2*KT_B)                // kt+vt per buffer
#define CHUNKS 32
#define ATTN_SMEM_B (8192 + 2*KVBUF + 2*8*36*4)   // 78080

template <bool FINAL>
__global__ void __launch_bounds__(256) attn_pass(float* __restrict__ out_attn) {
    extern __shared__ __align__(16) char asm_[];
    float* qs = (float*)asm_;                         // 8*256 fp32
    char*  kv = asm_ + 8192;                          // 2 buffers of (kt, vt) fp16
    float* Ls = (float*)(asm_ + 8192 + 2*KVBUF);
    float* ps = Ls + 8*36;

    int b  = blockIdx.x;
    int ch = blockIdx.y;
    int t  = threadIdx.x;

    const uint32_t kv_u = s2u(kv);
    const int lrow = t >> 3;          // 0..31
    const int lq   = t & 7;           // 16B unit

    const int n0 = ch * (NN / CHUNKS);
    const char* kgb = (const char*)(g_k + ((size_t)b*NN + n0) * DS);
    const char* vgb = (const char*)(g_v + ((size_t)b*NN + n0) * DS);

    auto issue_tile = [&](int buf, int tile) {
        uint32_t kb = kv_u + buf * KVBUF;
        const char* ks = kgb + (size_t)tile * ATILE * 512 + lrow * 512 + lq * 16;
        uint32_t kd = kb + lrow * KHPB + lq * 16;
        #pragma unroll
        for (int r = 0; r < 4; r++) cpa16(kd + r*128, ks + r*128);
        if (!FINAL) {
            const char* vs = vgb + (size_t)tile * ATILE * 512 + lrow * 512 + lq * 16;
            uint32_t vd = kb + KT_B + lrow * KHPB + lq * 16;
            #pragma unroll
            for (int r = 0; r < 4; r++) cpa16(vd + r*128, vs + r*128);
        }
    };

    for (int i = t; i < 8*256; i += 256) qs[i] = g_q[b*2048 + i] * SCALE_F;

    issue_tile(0, 0); CP_COMMIT();
    issue_tile(1, 1); CP_COMMIT();

    float regU[8], regS[8];
    #pragma unroll
    for (int h = 0; h < 8; h++) { regU[h] = 0.f; regS[h] = 0.f; }

    const int hq = t >> 5;
    const int nl = t & 31;

    #pragma unroll 1
    for (int tile = 0; tile < (NN/CHUNKS)/ATILE; tile++) {
        const int buf = tile & 1;
        CP_WAIT1();
        __syncthreads();
        const char* ktb = kv + buf * KVBUF;
        const char* vtb = ktb + KT_B;

        // logits: thread (slot hq, position nl); k fp16, q fp32 (broadcast reads)
        {
            float acc = 0.f;
            const float* qrow = qs + hq*256;
            const char* krow = ktb + nl * KHPB;
            #pragma unroll 4
            for (int d8 = 0; d8 < 32; d8++) {
                uint4 raw = *(const uint4*)(krow + d8*16);
                __half2* hp = (__half2*)&raw;
                float2 k0 = __half22float2(hp[0]), k1 = __half22float2(hp[1]);
                float2 k2 = __half22float2(hp[2]), k3 = __half22float2(hp[3]);
                float4 q0 = *(const float4*)(qrow + d8*8);
                float4 q1 = *(const float4*)(qrow + d8*8 + 4);
                acc += q0.x*k0.x + q0.y*k0.y + q0.z*k1.x + q0.w*k1.y
                     + q1.x*k2.x + q1.y*k2.y + q1.z*k3.x + q1.w*k3.y;
            }
            Ls[hq*36 + nl] = acc;
        }
        __syncthreads();

        if (t < 32) {
            float l[8], m = -1e30f;
            #pragma unroll
            for (int h = 0; h < 8; h++) { l[h] = Ls[h*36 + t]; m = fmaxf(m, l[h]); }
            float ssum = 0.f;
            #pragma unroll
            for (int h = 0; h < 8; h++) { l[h] = expf(l[h] - m); ssum += l[h]; }
            float inv = 1.f / ssum;
            #pragma unroll
            for (int h = 0; h < 8; h++) {
                float p = l[h] * inv;
                ps[h*36 + t] = p;
                regS[h] += p;
                if (FINAL)
                    out_attn[((size_t)b*KSLOT + h)*NN + n0 + tile*ATILE + t] = p;
            }
        }
        __syncthreads();

        if (!FINAL) {
            // U[slot][d=t] += p[slot][n] * v[n][t]; v fp16, converted once per (n,t)
            #pragma unroll 4
            for (int n = 0; n < ATILE; n++) {
                float vv = __half2float(*(const __half*)(vtb + n*KHPB + t*2));
                #pragma unroll
                for (int h = 0; h < 8; h++) regU[h] += ps[h*36 + n] * vv;
            }
        }
        __syncthreads();
        if (tile + 2 < (NN/CHUNKS)/ATILE) issue_tile(buf, tile + 2);
        CP_COMMIT();
    }

    if (!FINAL) {
        #pragma unroll
        for (int h = 0; h < 8; h++)
            atomicAdd(&g_U[((size_t)b*KSLOT + h)*DS + t], regU[h]);
    }
    if (t < 32) {
        #pragma unroll
        for (int h = 0; h < 8; h++) {
            float v = regS[h];
            for (int o = 16; o; o >>= 1) v += __shfl_down_sync(0xffffffffu, v, o);
            if (t == 0) atomicAdd(&g_S[b*KSLOT + h], v);
        }
    }
}

// ---------------- GRU gate GEMMs ----------------
__global__ void __launch_bounds__(256) gru_gemm(const float* __restrict__ bih, const float* __restrict__ bhh) {
    int blk = blockIdx.x;
    int b = blk / 24, gc = blk % 24;
    __shared__ float su[8*256], ss[8*256];
    int t = threadIdx.x;
    for (int i = t; i < 2048; i += 256) {
        int k = i >> 8;
        su[i] = g_U[b*2048 + i] / (g_S[b*8 + k] + EPS_ATTN);
        ss[i] = g_slots[b*2048 + i];
    }
    __syncthreads();
    int g = gc*32 + (t & 31);
    int k = t >> 5;
    float gi = bih[g], gh = bhh[g];
    const float* su_k = su + k*256;
    const float* ss_k = ss + k*256;
    #pragma unroll 4
    for (int d = 0; d < 256; d++) {
        gi += su_k[d] * g_WihT[d*768 + g];
        gh += ss_k[d] * g_WhhT[d*768 + g];
    }
    g_gi[((size_t)b*8 + k)*768 + g] = gi;
    g_gh[((size_t)b*8 + k)*768 + g] = gh;
}

// ---------------- GRU combine + LN + MLP + next-iteration q (fused slot_q tail) ----------------
__global__ void __launch_bounds__(256) gru_mlp(const float* __restrict__ gm, const float* __restrict__ bm,
                                               const float* __restrict__ b1, const float* __restrict__ b2,
                                               const float* __restrict__ gs, const float* __restrict__ bs) {
    int bk = blockIdx.x;
    int t = threadIdx.x;
    const float* gi = g_gi + (size_t)bk*768;
    const float* gh = g_gh + (size_t)bk*768;
    float sl = g_slots[bk*256 + t];
    float r  = 1.f / (1.f + expf(-(gi[t]       + gh[t])));
    float z  = 1.f / (1.f + expf(-(gi[256 + t] + gh[256 + t])));
    float nn = tanhf(gi[512 + t] + r * gh[512 + t]);
    float h  = (1.f - z) * nn + z * sl;

    __shared__ float hn[256], ms[256];
    __shared__ float r1[8], r2[8];
    __shared__ float smv[2];
    float s = h, s2 = h*h;
    for (int o = 16; o; o >>= 1) { s += __shfl_down_sync(0xffffffffu, s, o); s2 += __shfl_down_sync(0xffffffffu, s2, o); }
    if ((t & 31) == 0) { r1[t>>5] = s; r2[t>>5] = s2; }
    __syncthreads();
    if (t == 0) {
        float ts = 0.f, ts2 = 0.f;
        #pragma unroll
        for (int w = 0; w < 8; w++) { ts += r1[w]; ts2 += r2[w]; }
        float m = ts * (1.f/256.f);
        float var = ts2 * (1.f/256.f) - m*m;
        smv[0] = m; smv[1] = rsqrtf(var + 1e-5f);
    }
    __syncthreads();
    hn[t] = (h - smv[0]) * smv[1] * gm[t] + bm[t];
    __syncthreads();
    float acc = b1[t];
    #pragma unroll 4
    for (int d = 0; d < 256; d++) acc += hn[d] * g_W1T[d*256 + t];
    ms[t] = fmaxf(acc, 0.f);
    __syncthreads();
    float o = h + b2[t];
    #pragma unroll 4
    for (int j = 0; j < 256; j++) o += ms[j] * g_W2T[j*256 + t];
    g_slots[bk*256 + t] = o;

    // ---- fused slot_q tail: zero U/S, q = LN(new slots) @ Wq^T ----
    g_U[bk*256 + t] = 0.f;
    if (t == 0) g_S[bk] = 0.f;
    __syncthreads();
    s = o; s2 = o*o;
    for (int off = 16; off; off >>= 1) { s += __shfl_down_sync(0xffffffffu, s, off); s2 += __shfl_down_sync(0xffffffffu, s2, off); }
    if ((t & 31) == 0) { r1[t>>5] = s; r2[t>>5] = s2; }
    __syncthreads();
    if (t == 0) {
        float ts = 0.f, ts2 = 0.f;
        #pragma unroll
        for (int w = 0; w < 8; w++) { ts += r1[w]; ts2 += r2[w]; }
        float m = ts * (1.f/256.f);
        float var = ts2 * (1.f/256.f) - m*m;
        smv[0] = m; smv[1] = rsqrtf(var + 1e-5f);
    }
    __syncthreads();
    hn[t] = (o - smv[0]) * smv[1] * gs[t] + bs[t];
    __syncthreads();
    float qa = 0.f;
    #pragma unroll 4
    for (int d = 0; d < 256; d++) qa += hn[d] * g_WqT[d*256 + t];
    g_q[bk*256 + t] = qa;
}

// ---------------- final confidence blend ----------------
__global__ void __launch_bounds__(256) finalize(const float* __restrict__ prev, float* __restrict__ out_slots) {
    int bk = blockIdx.x;
    int t = threadIdx.x;
    float mean = g_S[bk] * (1.f / 4096.f);
    float mask = 1.f / (1.f + expf(-mean));
    out_slots[bk*256 + t] = g_slots[bk*256 + t] * mask + prev[bk*256 + t] * (1.f - mask);
}

// ---------------- launch ----------------
extern "C" void kernel_launch(void* const* d_in, const int* in_sizes, int n_in,
                              void* d_out, int out_size) {
    const float* features = (const float*)d_in[0];
    const float* prev     = (const float*)d_in[1];
    const float* gin      = (const float*)d_in[2];
    const float* bin      = (const float*)d_in[3];
    const float* gs       = (const float*)d_in[4];
    const float* bs       = (const float*)d_in[5];
    const float* gm       = (const float*)d_in[6];
    const float* bm       = (const float*)d_in[7];
    const float* Wq       = (const float*)d_in[8];
    const float* Wk       = (const float*)d_in[9];
    const float* Wv       = (const float*)d_in[10];
    const float* Wih      = (const float*)d_in[11];
    const float* Whh      = (const float*)d_in[12];
    const float* bih      = (const float*)d_in[13];
    const float* bhh      = (const float*)d_in[14];
    const float* W1       = (const float*)d_in[15];
    const float* b1       = (const float*)d_in[16];
    const float* W2       = (const float*)d_in[17];
    const float* b2       = (const float*)d_in[18];

    float* out_slots = (float*)d_out;
    float* out_attn  = out_slots + BB*KSLOT*DS;

    cudaFuncSetAttribute((const void*)attn_pass<false>, cudaFuncAttributeMaxDynamicSharedMemorySize, ATTN_SMEM_B);
    cudaFuncSetAttribute((const void*)attn_pass<true>,  cudaFuncAttributeMaxDynamicSharedMemorySize, ATTN_SMEM_B);
    cudaFuncSetAttribute((const void*)gemm_mma, cudaFuncAttributeMaxDynamicSharedMemorySize, GEMM_SMEM);

    // prep (2 launches)
    prep_wc<<<512, 256>>>(Wk, Wv, gin, bin);
    prep_transpose<<<(768*256 + 255)/256, 256>>>(Wq, Wih, Whh, W1, W2, prev);

    // phase A
    row_stats_split<<<NROWS/8, 256>>>(features);
    gemm_mma<<<dim3(4, NROWS/128), 256, GEMM_SMEM>>>();

    // initial q from prev slots (+ zero U/S)
    slot_q<<<BB*KSLOT, 256>>>(gs, bs);

    // phase B: 3 slot-attention iterations (gru_mlp computes next q + zeroes U/S)
    for (int it = 0; it < 3; it++) {
        attn_pass<false><<<dim3(BB, CHUNKS), 256, ATTN_SMEM_B>>>(nullptr);
        gru_gemm<<<BB*24, 256>>>(bih, bhh);
        gru_mlp<<<BB*KSLOT, 256>>>(gm, bm, b1, b2, gs, bs);
    }

    // final attention + blend
    attn_pass<true><<<dim3(BB, CHUNKS), 256, ATTN_SMEM_B>>>(out_attn);
    finalize<<<BB*KSLOT, 256>>>(prev, out_slots);

    (void)in_sizes; (void)n_in; (void)out_size;
}

// round 11
// speedup vs baseline: 2.7834x; 1.0543x over previous
#include <cuda_runtime.h>
#include <cuda_fp16.h>
#include <cstdint>
#include <math.h>

// ---------------- problem constants ----------------
#define BB 32
#define NN 4096
#define DF 768
#define DS 256
#define KSLOT 8
#define NROWS (BB*NN)        // 131072
#define SCALE_F 0.0625f      // 256^-0.5
#define EPS_ATTN 1e-8f

// ---------------- scratch (device globals; no allocations allowed) ----------------
static __device__ float g_mean[NROWS];
static __device__ float g_rstd[NROWS];
static __device__ __align__(16) __half g_Fh[(size_t)NROWS*DF];          // 201 MB
static __device__ __align__(16) __half g_k[(size_t)NROWS*DS];           // 67 MB
static __device__ __align__(16) __half g_v[(size_t)NROWS*DS];           // 67 MB
static __device__ __align__(16) __half g_WcH[512*DF];                   // fp16(Wc)
static __device__ float g_csum[512];
static __device__ float g_cbias[512];
static __device__ float g_WqT[DS*DS];
static __device__ float g_WihT[DS*768];
static __device__ float g_WhhT[DS*768];
static __device__ float g_W1T[DS*DS];
static __device__ float g_W2T[DS*DS];
static __device__ float g_q[BB*KSLOT*DS];
static __device__ float g_slots[BB*KSLOT*DS];
static __device__ float g_U[BB*KSLOT*DS];
static __device__ float g_S[BB*KSLOT];
static __device__ float g_gi[BB*KSLOT*768];
static __device__ float g_gh[BB*KSLOT*768];

// ---------------- helpers ----------------
__device__ __forceinline__ uint32_t s2u(const void* p) {
    uint32_t r;
    asm("{ .reg .u64 t; cvta.to.shared.u64 t, %1; cvt.u32.u64 %0, t; }" : "=r"(r) : "l"(p));
    return r;
}
__device__ __forceinline__ void cpa16(uint32_t dst, const void* src) {
    asm volatile("cp.async.cg.shared.global [%0], [%1], 16;" :: "r"(dst), "l"(src));
}
#define CP_COMMIT() asm volatile("cp.async.commit_group;" ::: "memory")
#define CP_WAIT3()  asm volatile("cp.async.wait_group 3;" ::: "memory")
#define CP_WAIT1()  asm volatile("cp.async.wait_group 1;" ::: "memory")

#define MMA16816(C, A, B) \
    asm volatile("mma.sync.aligned.m16n8k16.row.col.f32.f16.f16.f32 " \
        "{%0,%1,%2,%3}, {%4,%5,%6,%7}, {%8,%9}, {%0,%1,%2,%3};" \
        : "+f"((C)[0]), "+f"((C)[1]), "+f"((C)[2]), "+f"((C)[3]) \
        : "r"((A)[0]), "r"((A)[1]), "r"((A)[2]), "r"((A)[3]), "r"((B)[0]), "r"((B)[1]))

// ---------------- prep: combined weights (fp32 colsums + direct fp16 cast) ----------------
__global__ void __launch_bounds__(256) prep_wc(const float* __restrict__ Wk,
                                               const float* __restrict__ Wv,
                                               const float* __restrict__ gin,
                                               const float* __restrict__ bin) {
    int j = blockIdx.x;
    const float* W = (j < 256) ? (Wk + (size_t)j*DF) : (Wv + (size_t)(j-256)*DF);
    int t = threadIdx.x;
    float s = 0.f, bsum = 0.f;
    for (int f = t; f < DF; f += 256) {
        float w  = W[f];
        float wc = w * gin[f];
        g_WcH[(size_t)j*DF + f] = __float2half_rn(wc);
        s += wc; bsum += w * bin[f];
    }
    __shared__ float r1[8], r2[8];
    for (int o = 16; o; o >>= 1) { s += __shfl_down_sync(0xffffffffu, s, o); bsum += __shfl_down_sync(0xffffffffu, bsum, o); }
    if ((t & 31) == 0) { r1[t>>5] = s; r2[t>>5] = bsum; }
    __syncthreads();
    if (t == 0) {
        float ts = 0.f, tb = 0.f;
        #pragma unroll
        for (int w = 0; w < 8; w++) { ts += r1[w]; tb += r2[w]; }
        g_csum[j] = ts; g_cbias[j] = tb;
    }
}

// ---------------- prep: transposed small weights + copy slots ----------------
__global__ void prep_transpose(const float* __restrict__ Wq,
                               const float* __restrict__ Wih,
                               const float* __restrict__ Whh,
                               const float* __restrict__ W1,
                               const float* __restrict__ W2,
                               const float* __restrict__ prev) {
    int i = blockIdx.x * blockDim.x + threadIdx.x;
    if (i < 768*256) {
        int g = i / 256, d = i % 256;
        g_WihT[d*768 + g] = Wih[i];
        g_WhhT[d*768 + g] = Whh[i];
    }
    if (i < 256*256) {
        int r = i / 256, c = i % 256;
        g_WqT[c*256 + r] = Wq[i];
        g_W1T[c*256 + r] = W1[i];
        g_W2T[c*256 + r] = W2[i];
    }
    if (i < BB*KSLOT*DS) g_slots[i] = prev[i];
}

// ---------------- LN stats + fp16 cast of F (one streaming pass) ----------------
__global__ void __launch_bounds__(256) row_stats_split(const float* __restrict__ F) {
    int w = threadIdx.x >> 5, l = threadIdx.x & 31;
    int row = blockIdx.x * 8 + w;
    const float4* x = (const float4*)(F + (size_t)row * DF);
    float4 a[6];
    float s = 0.f, s2 = 0.f;
    #pragma unroll
    for (int j = 0; j < 6; j++) {
        a[j] = x[l + 32*j];
        s  += a[j].x + a[j].y + a[j].z + a[j].w;
        s2 += a[j].x*a[j].x + a[j].y*a[j].y + a[j].z*a[j].z + a[j].w*a[j].w;
    }
    uint2* hdst = (uint2*)(g_Fh + (size_t)row * DF);
    #pragma unroll
    for (int j = 0; j < 6; j++) {
        float4 v = a[j];
        __half2 h0 = __floats2half2_rn(v.x, v.y);
        __half2 h1 = __floats2half2_rn(v.z, v.w);
        hdst[l + 32*j] = make_uint2(*(uint32_t*)&h0, *(uint32_t*)&h1);
    }
    for (int o = 16; o; o >>= 1) {
        s  += __shfl_down_sync(0xffffffffu, s, o);
        s2 += __shfl_down_sync(0xffffffffu, s2, o);
    }
    if (l == 0) {
        float m   = s * (1.f/768.f);
        float var = s2 * (1.f/768.f) - m*m;
        g_mean[row] = m;
        g_rstd[row] = rsqrtf(var + 1e-5f);
    }
}

// ---------------- tensor-core GEMM (fp16 single-pass, 4-stage cp.async, 2 CTA/SM) ----------------
#define GPADB 80
#define GTILE (128*GPADB)
#define GSTAGE (2*GTILE)
#define GNSTAGE 4
#define GEMM_SMEM (GNSTAGE*GSTAGE)   // 81920
#define NCHUNK (DF/32)               // 24

__global__ void __launch_bounds__(256, 2) gemm_mma(void) {
    extern __shared__ __align__(16) char smd[];
    __shared__ float s_cs[128], s_cb[128];

    const int tid = threadIdx.x;
    const int wid = tid >> 5, lane = tid & 31;
    const int wm = wid & 1, wn = wid >> 1;
    const int bnG = blockIdx.x * 128;
    const int bm = blockIdx.y * 128;

    if (tid < 128) { s_cs[tid] = g_csum[bnG + tid]; s_cb[tid] = g_cbias[bnG + tid]; }

    const uint32_t smem_u = s2u(smd);
    const int arow = tid >> 2;
    const int aq   = tid & 3;

    auto stage = [&](int buf, int c) {
        const int kb = c * 32;
        uint32_t sb = smem_u + buf * GSTAGE;
        const __half* fa = g_Fh + (size_t)(bm + arow) * DF + kb + aq * 8;
        uint32_t da = sb + arow * GPADB + aq * 16;
        cpa16(da,            fa);
        cpa16(da + 64*GPADB, fa + (size_t)64*DF);
        const __half* bh = g_WcH + (size_t)(bnG + arow) * DF + kb + aq * 8;
        uint32_t db = sb + GTILE + arow * GPADB + aq * 16;
        cpa16(db,            bh);
        cpa16(db + 64*GPADB, bh + (size_t)64*DF);
    };

    float acc[4][4][4];
    #pragma unroll
    for (int mi = 0; mi < 4; mi++)
        #pragma unroll
        for (int ni = 0; ni < 4; ni++)
            #pragma unroll
            for (int e = 0; e < 4; e++) acc[mi][ni][e] = 0.f;

    stage(0, 0); CP_COMMIT();
    stage(1, 1); CP_COMMIT();
    stage(2, 2); CP_COMMIT();
    stage(3, 3); CP_COMMIT();

    const int fr = lane >> 2;
    const int fk = (lane & 3) * 4;

    #pragma unroll 1
    for (int c = 0; c < NCHUNK; c++) {
        const int buf = c & 3;
        CP_WAIT3();
        __syncthreads();

        const char* Aa = smd + buf * GSTAGE;
        const char* Bb = Aa + GTILE;

        #pragma unroll
        for (int ks = 0; ks < 2; ks++) {
            uint32_t af[4][4], bfr[4][2];
            #pragma unroll
            for (int mi = 0; mi < 4; mi++) {
                uint32_t o = (wm*64 + mi*16 + fr) * GPADB + ks*32 + fk;
                af[mi][0] = *(const uint32_t*)(Aa + o);
                af[mi][1] = *(const uint32_t*)(Aa + o + 8*GPADB);
                af[mi][2] = *(const uint32_t*)(Aa + o + 16);
                af[mi][3] = *(const uint32_t*)(Aa + o + 8*GPADB + 16);
            }
            #pragma unroll
            for (int ni = 0; ni < 4; ni++) {
                uint32_t o = (wn*32 + ni*8 + fr) * GPADB + ks*32 + fk;
                bfr[ni][0] = *(const uint32_t*)(Bb + o);
                bfr[ni][1] = *(const uint32_t*)(Bb + o + 16);
            }
            #pragma unroll
            for (int mi = 0; mi < 4; mi++)
                #pragma unroll
                for (int ni = 0; ni < 4; ni++)
                    MMA16816(acc[mi][ni], af[mi], bfr[ni]);
        }

        __syncthreads();
        if (c + GNSTAGE < NCHUNK) stage(buf, c + GNSTAGE);
        CP_COMMIT();
    }

    // ---- epilogue: LN fold + fp16 store to k/v ----
    #pragma unroll
    for (int mi = 0; mi < 4; mi++) {
        int r1 = bm + wm*64 + mi*16 + fr;
        int r2 = r1 + 8;
        float rm1 = g_mean[r1], rs1 = g_rstd[r1];
        float rm2 = g_mean[r2], rs2 = g_rstd[r2];
        #pragma unroll
        for (int ni = 0; ni < 4; ni++) {
            int cl = wn*32 + ni*8 + (lane & 3)*2;
            int colg = bnG + cl;
            float cs0 = s_cs[cl], cs1 = s_cs[cl+1];
            float cb0 = s_cb[cl], cb1 = s_cb[cl+1];
            __half* base;
            int coff;
            if (colg < 256) { base = g_k; coff = colg; }
            else            { base = g_v; coff = colg - 256; }
            __half2* d1 = (__half2*)(base + (size_t)r1*DS + coff);
            __half2* d2 = (__half2*)(base + (size_t)r2*DS + coff);
            *d1 = __floats2half2_rn(
                rs1*(acc[mi][ni][0] - rm1*cs0) + cb0,
                rs1*(acc[mi][ni][1] - rm1*cs1) + cb1);
            *d2 = __floats2half2_rn(
                rs2*(acc[mi][ni][2] - rm2*cs0) + cb0,
                rs2*(acc[mi][ni][3] - rm2*cs1) + cb1);
        }
    }
}

// ---------------- per-slot q = LN(slots) @ Wq^T (also zeroes U/S accumulators) ----------------
__global__ void __launch_bounds__(256) slot_q(const float* __restrict__ gs, const float* __restrict__ bs) {
    int row = blockIdx.x;
    int t = threadIdx.x;
    __shared__ float sn[256];
    __shared__ float r1[8], r2[8];
    __shared__ float smv[2];
    g_U[row*256 + t] = 0.f;
    if (t == 0) g_S[row] = 0.f;
    float x = g_slots[row*256 + t];
    float s = x, s2 = x*x;
    for (int o = 16; o; o >>= 1) { s += __shfl_down_sync(0xffffffffu, s, o); s2 += __shfl_down_sync(0xffffffffu, s2, o); }
    if ((t & 31) == 0) { r1[t>>5] = s; r2[t>>5] = s2; }
    __syncthreads();
    if (t == 0) {
        float ts = 0.f, ts2 = 0.f;
        #pragma unroll
        for (int w = 0; w < 8; w++) { ts += r1[w]; ts2 += r2[w]; }
        float m = ts * (1.f/256.f);
        float var = ts2 * (1.f/256.f) - m*m;
        smv[0] = m; smv[1] = rsqrtf(var + 1e-5f);
    }
    __syncthreads();
    sn[t] = (x - smv[0]) * smv[1] * gs[t] + bs[t];
    __syncthreads();
    float acc = 0.f;
    #pragma unroll 4
    for (int d = 0; d < 256; d++) acc += sn[d] * g_WqT[d*256 + t];
    g_q[row*256 + t] = acc;
}

// ---------------- fused attention sweep (k/v fp16 in smem via cp.async, double-buffered) ----------------
#define ATILE 32
#define KHPB 528                      // bytes per smem k/v row (264 halfs; 33x16B)
#define KT_B (ATILE*KHPB)             // 16896
#define KVBUF (2*KT_B)
#define CHUNKS 32
#define ATTN_SMEM_B (8192 + 2*KVBUF + 2*8*36*4 + 64)

template <bool FINAL>
__global__ void __launch_bounds__(256) attn_pass(float* __restrict__ out_attn) {
    extern __shared__ __align__(16) char asm_[];
    float* qs = (float*)asm_;                         // 8*256 fp32
    char*  kv = asm_ + 8192;                          // 2 buffers of (kt, vt) fp16
    float* Ls = (float*)(asm_ + 8192 + 2*KVBUF);      // 8*36
    float* ps = Ls + 8*36;                            // 8*36
    float* sS = ps + 8*36;                            // 8 slot sums

    int b  = blockIdx.x;
    int ch = blockIdx.y;
    int t  = threadIdx.x;

    const uint32_t kv_u = s2u(kv);
    const int lrow = t >> 3;
    const int lq   = t & 7;

    const int n0 = ch * (NN / CHUNKS);
    const char* kgb = (const char*)(g_k + ((size_t)b*NN + n0) * DS);
    const char* vgb = (const char*)(g_v + ((size_t)b*NN + n0) * DS);

    auto issue_tile = [&](int buf, int tile) {
        uint32_t kb = kv_u + buf * KVBUF;
        const char* ks = kgb + (size_t)tile * ATILE * 512 + lrow * 512 + lq * 16;
        uint32_t kd = kb + lrow * KHPB + lq * 16;
        #pragma unroll
        for (int r = 0; r < 4; r++) cpa16(kd + r*128, ks + r*128);
        if (!FINAL) {
            const char* vs = vgb + (size_t)tile * ATILE * 512 + lrow * 512 + lq * 16;
            uint32_t vd = kb + KT_B + lrow * KHPB + lq * 16;
            #pragma unroll
            for (int r = 0; r < 4; r++) cpa16(vd + r*128, vs + r*128);
        }
    };

    for (int i = t; i < 8*256; i += 256) qs[i] = g_q[b*2048 + i] * SCALE_F;
    if (t < 8) sS[t] = 0.f;

    issue_tile(0, 0); CP_COMMIT();
    issue_tile(1, 1); CP_COMMIT();

    float regU[8];
    #pragma unroll
    for (int h = 0; h < 8; h++) regU[h] = 0.f;
    float regS = 0.f;                 // per-thread partial for slot (t&7)

    const int hq = t >> 5;            // logits: slot = warp id
    const int nl = t & 31;            // logits: position = lane
    const int spos = t >> 3;          // softmax: position 0..31
    const int sslot = t & 7;          // softmax: slot 0..7

    #pragma unroll 1
    for (int tile = 0; tile < (NN/CHUNKS)/ATILE; tile++) {
        const int buf = tile & 1;
        CP_WAIT1();
        __syncthreads();
        const char* ktb = kv + buf * KVBUF;
        const char* vtb = ktb + KT_B;

        // logits: thread (slot hq, position nl); 4 independent accumulators
        {
            float a4[4] = {0.f, 0.f, 0.f, 0.f};
            const float* qrow = qs + hq*256;
            const char* krow = ktb + nl * KHPB;
            #pragma unroll
            for (int d8 = 0; d8 < 32; d8++) {
                uint4 raw = *(const uint4*)(krow + d8*16);
                __half2* hp = (__half2*)&raw;
                float2 k0 = __half22float2(hp[0]), k1 = __half22float2(hp[1]);
                float2 k2 = __half22float2(hp[2]), k3 = __half22float2(hp[3]);
                float4 q0 = *(const float4*)(qrow + d8*8);
                float4 q1 = *(const float4*)(qrow + d8*8 + 4);
                a4[d8 & 3] += q0.x*k0.x + q0.y*k0.y + q0.z*k1.x + q0.w*k1.y
                            + q1.x*k2.x + q1.y*k2.y + q1.z*k3.x + q1.w*k3.y;
            }
            Ls[hq*36 + nl] = (a4[0] + a4[1]) + (a4[2] + a4[3]);
        }
        __syncthreads();

        // softmax over 8 slots, all 256 threads: (pos=t>>3, slot=t&7), width-8 shfl
        {
            float val = Ls[sslot*36 + spos];
            float m = val;
            #pragma unroll
            for (int off = 4; off; off >>= 1)
                m = fmaxf(m, __shfl_xor_sync(0xffffffffu, m, off, 8));
            float e = __expf(val - m);
            float ssum = e;
            #pragma unroll
            for (int off = 4; off; off >>= 1)
                ssum += __shfl_xor_sync(0xffffffffu, ssum, off, 8);
            float p = e / ssum;
            ps[sslot*36 + spos] = p;
            regS += p;
            if (FINAL)
                out_attn[((size_t)b*KSLOT + sslot)*NN + n0 + tile*ATILE + spos] = p;
        }
        __syncthreads();

        if (!FINAL) {
            // U[slot][d=t] += p[slot][n] * v[n][t]; float4 ps loads (broadcast)
            #pragma unroll
            for (int n4 = 0; n4 < 8; n4++) {
                float4 pv[8];
                #pragma unroll
                for (int h = 0; h < 8; h++)
                    pv[h] = *(const float4*)(ps + h*36 + n4*4);
                float vv[4];
                #pragma unroll
                for (int j = 0; j < 4; j++)
                    vv[j] = __half2float(*(const __half*)(vtb + (n4*4+j)*KHPB + t*2));
                #pragma unroll
                for (int j = 0; j < 4; j++)
                    #pragma unroll
                    for (int h = 0; h < 8; h++)
                        regU[h] += ((const float*)&pv[h])[j] * vv[j];
            }
        }
        __syncthreads();
        if (tile + 2 < (NN/CHUNKS)/ATILE) issue_tile(buf, tile + 2);
        CP_COMMIT();
    }

    if (!FINAL) {
        #pragma unroll
        for (int h = 0; h < 8; h++)
            atomicAdd(&g_U[((size_t)b*KSLOT + h)*DS + t], regU[h]);
    }
    // per-slot S reduction: 32 threads share slot (t&7) -> smem atomics, then global
    atomicAdd(&sS[sslot], regS);
    __syncthreads();
    if (t < 8) atomicAdd(&g_S[b*KSLOT + t], sS[t]);
}

// ---------------- GRU gate GEMMs ----------------
__global__ void __launch_bounds__(256) gru_gemm(const float* __restrict__ bih, const float* __restrict__ bhh) {
    int blk = blockIdx.x;
    int b = blk / 24, gc = blk % 24;
    __shared__ float su[8*256], ss[8*256];
    int t = threadIdx.x;
    for (int i = t; i < 2048; i += 256) {
        int k = i >> 8;
        su[i] = g_U[b*2048 + i] / (g_S[b*8 + k] + EPS_ATTN);
        ss[i] = g_slots[b*2048 + i];
    }
    __syncthreads();
    int g = gc*32 + (t & 31);
    int k = t >> 5;
    float gia = bih[g], gha = bhh[g];
    float gib = 0.f, ghb = 0.f;
    const float* su_k = su + k*256;
    const float* ss_k = ss + k*256;
    #pragma unroll 8
    for (int d = 0; d < 256; d += 2) {
        gia += su_k[d]   * g_WihT[d*768 + g];
        gib += su_k[d+1] * g_WihT[(d+1)*768 + g];
        gha += ss_k[d]   * g_WhhT[d*768 + g];
        ghb += ss_k[d+1] * g_WhhT[(d+1)*768 + g];
    }
    g_gi[((size_t)b*8 + k)*768 + g] = gia + gib;
    g_gh[((size_t)b*8 + k)*768 + g] = gha + ghb;
}

// ---------------- GRU combine + LN + MLP + next-iteration q (fused slot_q tail) ----------------
__global__ void __launch_bounds__(256) gru_mlp(const float* __restrict__ gm, const float* __restrict__ bm,
                                               const float* __restrict__ b1, const float* __restrict__ b2,
                                               const float* __restrict__ gs, const float* __restrict__ bs) {
    int bk = blockIdx.x;
    int t = threadIdx.x;
    const float* gi = g_gi + (size_t)bk*768;
    const float* gh = g_gh + (size_t)bk*768;
    float sl = g_slots[bk*256 + t];
    float r  = 1.f / (1.f + __expf(-(gi[t]       + gh[t])));
    float z  = 1.f / (1.f + __expf(-(gi[256 + t] + gh[256 + t])));
    float nn = tanhf(gi[512 + t] + r * gh[512 + t]);
    float h  = (1.f - z) * nn + z * sl;

    __shared__ float hn[256], ms[256];
    __shared__ float r1[8], r2[8];
    __shared__ float smv[2];
    float s = h, s2 = h*h;
    for (int o = 16; o; o >>= 1) { s += __shfl_down_sync(0xffffffffu, s, o); s2 += __shfl_down_sync(0xffffffffu, s2, o); }
    if ((t & 31) == 0) { r1[t>>5] = s; r2[t>>5] = s2; }
    __syncthreads();
    if (t == 0) {
        float ts = 0.f, ts2 = 0.f;
        #pragma unroll
        for (int w = 0; w < 8; w++) { ts += r1[w]; ts2 += r2[w]; }
        float m = ts * (1.f/256.f);
        float var = ts2 * (1.f/256.f) - m*m;
        smv[0] = m; smv[1] = rsqrtf(var + 1e-5f);
    }
    __syncthreads();
    hn[t] = (h - smv[0]) * smv[1] * gm[t] + bm[t];
    __syncthreads();
    float acc = b1[t];
    #pragma unroll 4
    for (int d = 0; d < 256; d++) acc += hn[d] * g_W1T[d*256 + t];
    ms[t] = fmaxf(acc, 0.f);
    __syncthreads();
    float o = h + b2[t];
    #pragma unroll 4
    for (int j = 0; j < 256; j++) o += ms[j] * g_W2T[j*256 + t];
    g_slots[bk*256 + t] = o;

    // ---- fused slot_q tail: zero U/S, q = LN(new slots) @ Wq^T ----
    g_U[bk*256 + t] = 0.f;
    if (t == 0) g_S[bk] = 0.f;
    __syncthreads();
    s = o; s2 = o*o;
    for (int off = 16; off; off >>= 1) { s += __shfl_down_sync(0xffffffffu, s, off); s2 += __shfl_down_sync(0xffffffffu, s2, off); }
    if ((t & 31) == 0) { r1[t>>5] = s; r2[t>>5] = s2; }
    __syncthreads();
    if (t == 0) {
        float ts = 0.f, ts2 = 0.f;
        #pragma unroll
        for (int w = 0; w < 8; w++) { ts += r1[w]; ts2 += r2[w]; }
        float m = ts * (1.f/256.f);
        float var = ts2 * (1.f/256.f) - m*m;
        smv[0] = m; smv[1] = rsqrtf(var + 1e-5f);
    }
    __syncthreads();
    hn[t] = (o - smv[0]) * smv[1] * gs[t] + bs[t];
    __syncthreads();
    float qa = 0.f;
    #pragma unroll 4
    for (int d = 0; d < 256; d++) qa += hn[d] * g_WqT[d*256 + t];
    g_q[bk*256 + t] = qa;
}

// ---------------- final confidence blend ----------------
__global__ void __launch_bounds__(256) finalize(const float* __restrict__ prev, float* __restrict__ out_slots) {
    int bk = blockIdx.x;
    int t = threadIdx.x;
    float mean = g_S[bk] * (1.f / 4096.f);
    float mask = 1.f / (1.f + __expf(-mean));
    out_slots[bk*256 + t] = g_slots[bk*256 + t] * mask + prev[bk*256 + t] * (1.f - mask);
}

// ---------------- launch ----------------
extern "C" void kernel_launch(void* const* d_in, const int* in_sizes, int n_in,
                              void* d_out, int out_size) {
    const float* features = (const float*)d_in[0];
    const float* prev     = (const float*)d_in[1];
    const float* gin      = (const float*)d_in[2];
    const float* bin      = (const float*)d_in[3];
    const float* gs       = (const float*)d_in[4];
    const float* bs       = (const float*)d_in[5];
    const float* gm       = (const float*)d_in[6];
    const float* bm       = (const float*)d_in[7];
    const float* Wq       = (const float*)d_in[8];
    const float* Wk       = (const float*)d_in[9];
    const float* Wv       = (const float*)d_in[10];
    const float* Wih      = (const float*)d_in[11];
    const float* Whh      = (const float*)d_in[12];
    const float* bih      = (const float*)d_in[13];
    const float* bhh      = (const float*)d_in[14];
    const float* W1       = (const float*)d_in[15];
    const float* b1       = (const float*)d_in[16];
    const float* W2       = (const float*)d_in[17];
    const float* b2       = (const float*)d_in[18];

    float* out_slots = (float*)d_out;
    float* out_attn  = out_slots + BB*KSLOT*DS;

    cudaFuncSetAttribute((const void*)attn_pass<false>, cudaFuncAttributeMaxDynamicSharedMemorySize, ATTN_SMEM_B);
    cudaFuncSetAttribute((const void*)attn_pass<true>,  cudaFuncAttributeMaxDynamicSharedMemorySize, ATTN_SMEM_B);
    cudaFuncSetAttribute((const void*)gemm_mma, cudaFuncAttributeMaxDynamicSharedMemorySize, GEMM_SMEM);

    // prep (2 launches)
    prep_wc<<<512, 256>>>(Wk, Wv, gin, bin);
    prep_transpose<<<(768*256 + 255)/256, 256>>>(Wq, Wih, Whh, W1, W2, prev);

    // phase A
    row_stats_split<<<NROWS/8, 256>>>(features);
    gemm_mma<<<dim3(4, NROWS/128), 256, GEMM_SMEM>>>();

    // initial q from prev slots (+ zero U/S)
    slot_q<<<BB*KSLOT, 256>>>(gs, bs);

    // phase B: 3 slot-attention iterations (gru_mlp computes next q + zeroes U/S)
    for (int it = 0; it < 3; it++) {
        attn_pass<false><<<dim3(BB, CHUNKS), 256, ATTN_SMEM_B>>>(nullptr);
        gru_gemm<<<BB*24, 256>>>(bih, bhh);
        gru_mlp<<<BB*KSLOT, 256>>>(gm, bm, b1, b2, gs, bs);
    }

    // final attention + blend
    attn_pass<true><<<dim3(BB, CHUNKS), 256, ATTN_SMEM_B>>>(out_attn);
    finalize<<<BB*KSLOT, 256>>>(prev, out_slots);

    (void)in_sizes; (void)n_in; (void)out_size;
}